// round 9
// baseline (speedup 1.0000x reference)
#include <cuda_runtime.h>
#include <cuda_bf16.h>
#include <math.h>
#include <stdint.h>

// Problem constants
#define S_ 2048
#define D_ 1280
#define H_ 16
#define HD_ 80
#define HDP_ 96           // padded head dim for score-MMA K (3 chunks of 32)
#define I_ 5120
#define NQKV_ 3840
#define EPS_ 1e-6f
#define SCALE_ 0.11180339887498949f  // 80^-0.5

typedef __nv_bfloat16 bf16;

// ===================== device scratch (no allocation allowed) =====================
__device__ float g_qkv[S_ * NQKV_];                  // qkv proj fp32
__device__ bf16  g_hh[S_ * D_],  g_hl[S_ * D_];      // LN out split
__device__ bf16  g_qh[H_ * S_ * HDP_], g_ql[H_ * S_ * HDP_];
__device__ bf16  g_kh[H_ * S_ * HDP_], g_kl[H_ * S_ * HDP_];
__device__ bf16  g_vth[H_ * HD_ * S_], g_vtl[H_ * HD_ * S_];   // V^T per head
__device__ float g_scores[(size_t)H_ * S_ * S_];     // 268 MB
__device__ bf16  g_ph[(size_t)H_ * S_ * S_], g_pl[(size_t)H_ * S_ * S_];
__device__ bf16  g_ah[S_ * D_],  g_al[S_ * D_];      // attn out split
__device__ bf16  g_mh[S_ * I_],  g_ml[S_ * I_];      // mlp hidden split
__device__ bf16  g_wqh[NQKV_ * D_], g_wql[NQKV_ * D_];
__device__ bf16  g_wph[D_ * D_],    g_wpl[D_ * D_];
__device__ bf16  g_w1h[I_ * D_],    g_w1l[I_ * D_];
__device__ bf16  g_w2h[D_ * I_],    g_w2l[D_ * I_];

__device__ __forceinline__ void bsplit(float v, bf16& h, bf16& l) {
    h = __float2bfloat16(v);
    l = __float2bfloat16(v - __bfloat162float(h));
}

__device__ __forceinline__ uint32_t smem_to_u32(const void* smem_ptr) {
    uint32_t addr;
    asm("{ .reg .u64 tmp; cvta.to.shared.u64 tmp, %1; cvt.u32.u64 %0, tmp; }"
        : "=r"(addr) : "l"(smem_ptr));
    return addr;
}

__device__ __forceinline__ void ldsm4(uint32_t (&r)[4], uint32_t addr) {
    asm volatile("ldmatrix.sync.aligned.m8n8.x4.shared.b16 {%0,%1,%2,%3}, [%4];"
                 : "=r"(r[0]), "=r"(r[1]), "=r"(r[2]), "=r"(r[3]) : "r"(addr));
}

__device__ __forceinline__ void mma16816(float (&d)[4], const uint32_t (&a)[4],
                                         const uint32_t* b) {
    asm volatile(
        "mma.sync.aligned.m16n8k16.row.col.f32.bf16.bf16.f32 "
        "{%0,%1,%2,%3}, {%4,%5,%6,%7}, {%8,%9}, {%0,%1,%2,%3};"
        : "+f"(d[0]), "+f"(d[1]), "+f"(d[2]), "+f"(d[3])
        : "r"(a[0]), "r"(a[1]), "r"(a[2]), "r"(a[3]), "r"(b[0]), "r"(b[1]));
}

__device__ __forceinline__ void cp16(uint32_t dst, const void* src) {
    asm volatile("cp.async.cg.shared.global [%0], [%1], 16;"
                 :: "r"(dst), "l"(src));
}

// ===================== LayerNorm -> bf16 split =====================
__global__ void ln_split_kernel(const float* __restrict__ x,
                                const float* __restrict__ g,
                                const float* __restrict__ b,
                                bf16* __restrict__ oh, bf16* __restrict__ ol) {
    const int row = blockIdx.x;
    const int t = threadIdx.x;
    __shared__ float srow[D_];
    __shared__ float red[256];

    float local = 0.f;
    for (int i = t; i < D_; i += 256) {
        float v = x[(size_t)row * D_ + i];
        srow[i] = v;
        local += v;
    }
    red[t] = local;
    __syncthreads();
    for (int s = 128; s > 0; s >>= 1) { if (t < s) red[t] += red[t + s]; __syncthreads(); }
    const float mean = red[0] * (1.0f / D_);
    __syncthreads();

    local = 0.f;
    for (int i = t; i < D_; i += 256) { float dv = srow[i] - mean; local += dv * dv; }
    red[t] = local;
    __syncthreads();
    for (int s = 128; s > 0; s >>= 1) { if (t < s) red[t] += red[t + s]; __syncthreads(); }
    const float inv = rsqrtf(red[0] * (1.0f / D_) + EPS_);

    for (int i = t; i < D_; i += 256) {
        float v = (srow[i] - mean) * inv * g[i] + b[i];
        bf16 h, l; bsplit(v, h, l);
        oh[(size_t)row * D_ + i] = h;
        ol[(size_t)row * D_ + i] = l;
    }
}

// ===================== weight transpose + split: w[K][N] -> Wt[N][K] =====================
__global__ void wsplit_T_kernel(const float* __restrict__ w,
                                bf16* __restrict__ oh, bf16* __restrict__ ol,
                                int K, int N) {
    __shared__ float tile[32][33];
    int k0 = blockIdx.y * 32, n0 = blockIdx.x * 32;
    int tx = threadIdx.x, ty = threadIdx.y;
#pragma unroll
    for (int j = 0; j < 4; j++)
        tile[ty + j * 8][tx] = w[(size_t)(k0 + ty + j * 8) * N + n0 + tx];
    __syncthreads();
#pragma unroll
    for (int j = 0; j < 4; j++) {
        int n = ty + j * 8;
        float v = tile[tx][n];
        bf16 h, l; bsplit(v, h, l);
        size_t o = (size_t)(n0 + n) * K + k0 + tx;
        oh[o] = h; ol[o] = l;
    }
}

// ===================== RoPE + head split + V transpose (incl. zero pad) =====================
__global__ void rope_split_kernel(const float* __restrict__ qkv,
                                  const float* __restrict__ cosp,
                                  const float* __restrict__ sinp,
                                  bf16* __restrict__ Qh, bf16* __restrict__ Ql,
                                  bf16* __restrict__ Kh, bf16* __restrict__ Kl,
                                  bf16* __restrict__ Vth, bf16* __restrict__ Vtl) {
    int i = blockIdx.x * blockDim.x + threadIdx.x;
    if (i >= S_ * H_ * HDP_) return;
    const int s = i / (H_ * HDP_);
    const int r = i % (H_ * HDP_);
    const int h = r / HDP_;
    const int d = r % HDP_;

    const size_t oq = ((size_t)h * S_ + s) * HDP_ + d;
    if (d >= HD_) {
        const bf16 z = __float2bfloat16(0.f);
        Qh[oq] = z; Ql[oq] = z; Kh[oq] = z; Kl[oq] = z;
        return;
    }

    const float c = cosp[s * HD_ + d];
    const float sn = sinp[s * HD_ + d];
    const size_t base = (size_t)s * NQKV_;

    const int d2 = (d < HD_ / 2) ? d + HD_ / 2 : d - HD_ / 2;
    const float sign = (d < HD_ / 2) ? -1.f : 1.f;

    const float q  = qkv[base + h * HD_ + d];
    const float qp = qkv[base + h * HD_ + d2];
    const float k  = qkv[base + D_ + h * HD_ + d];
    const float kp = qkv[base + D_ + h * HD_ + d2];
    const float v  = qkv[base + 2 * D_ + h * HD_ + d];

    const float rq = q * c + sign * qp * sn;
    const float rk = k * c + sign * kp * sn;

    bf16 hh, ll;
    bsplit(rq, hh, ll); Qh[oq] = hh; Ql[oq] = ll;
    bsplit(rk, hh, ll); Kh[oq] = hh; Kl[oq] = ll;
    const size_t ov = ((size_t)h * HD_ + d) * S_ + s;
    bsplit(v, hh, ll);  Vth[ov] = hh; Vtl[ov] = ll;
}

// ===================== row softmax -> bf16 split probs =====================
__global__ void softmax_kernel(const float* __restrict__ Sc,
                               bf16* __restrict__ Ph, bf16* __restrict__ Pl) {
    const size_t row = blockIdx.x;
    const float* p = Sc + row * S_;
    const int t = threadIdx.x;
    __shared__ float red[256];

    float v[8];
    float m = -1e30f;
#pragma unroll
    for (int i = 0; i < 8; i++) { v[i] = p[t + i * 256]; m = fmaxf(m, v[i]); }
    red[t] = m;
    __syncthreads();
    for (int s = 128; s > 0; s >>= 1) { if (t < s) red[t] = fmaxf(red[t], red[t + s]); __syncthreads(); }
    m = red[0];
    __syncthreads();

    float sum = 0.f;
#pragma unroll
    for (int i = 0; i < 8; i++) { v[i] = expf(v[i] - m); sum += v[i]; }
    red[t] = sum;
    __syncthreads();
    for (int s = 128; s > 0; s >>= 1) { if (t < s) red[t] += red[t + s]; __syncthreads(); }
    const float inv = 1.0f / red[0];
#pragma unroll
    for (int i = 0; i < 8; i++) {
        float pv = v[i] * inv;
        bf16 h, l; bsplit(pv, h, l);
        size_t o = row * S_ + t + i * 256;
        Ph[o] = h; Pl[o] = l;
    }
}

// ===================== 128x256 bf16x3 GEMM, 512 threads, 3-stage =====================
// C[M, N] = alpha * A[M,K] @ B[N,K]^T
// EPI: 0 = C=v+bias  1 = C=v  2 = C+=v+bias  4 = gelu(v+bias) split-store
#define A_T 10240             // 128 rows * 80B pitch
#define B_T 20480             // 256 rows * 80B pitch
#define STAGE_B (2 * A_T + 2 * B_T)   // 61440
#define GEMM2_SMEM (3 * STAGE_B)      // 184320

template <int EPI>
__global__ void __launch_bounds__(512, 1)
gemm_mma2(const bf16* __restrict__ Agh, const bf16* __restrict__ Agl,
          const bf16* __restrict__ Bgh, const bf16* __restrict__ Bgl,
          const float* __restrict__ bias,
          float* __restrict__ C, bf16* __restrict__ Ch, bf16* __restrict__ Cl,
          int K, int lda, int ldb, int ldc,
          long long sA, long long sB, long long sC, float alpha) {
    extern __shared__ __align__(16) char smem[];
    const uint32_t sbase = smem_to_u32(smem);
    const int tid = threadIdx.x;
    const int wid = tid >> 5;
    const int lane = tid & 31;
    const int warp_m = wid & 3;   // 4 x 32 rows
    const int warp_n = wid >> 2;  // 4 x 64 cols
    const int bz = blockIdx.z;

    Agh += (size_t)bz * sA; Agl += (size_t)bz * sA;
    Bgh += (size_t)bz * sB; Bgl += (size_t)bz * sB;
    const size_t coff = (size_t)bz * sC;
    const int row0 = blockIdx.y * 128;
    const int col0 = blockIdx.x * 256;

    const uint32_t a_off = (uint32_t)(((lane & 15) * 40 + (lane >> 4) * 8) * 2);
    const uint32_t b_off = (uint32_t)(((((lane & 7) | ((lane >> 4) << 3)) * 40) +
                                      (((lane >> 3) & 1) * 8)) * 2);

    auto load_chunk = [&](int kc, int stg) {
        const int k0 = kc << 5;
        const uint32_t dbase = sbase + (uint32_t)stg * STAGE_B;
#pragma unroll
        for (int it = 0; it < 2; it++) {
            int e = it * 512 + tid;
            int t = e >> 9;
            int idx = e & 511;
            int row = idx >> 2, c8 = idx & 3;
            const bf16* src = (t ? Agl : Agh) + (size_t)(row0 + row) * lda + k0 + c8 * 8;
            uint32_t dst = dbase + (uint32_t)t * A_T + (uint32_t)(row * 80 + c8 * 16);
            cp16(dst, src);
        }
#pragma unroll
        for (int it = 0; it < 4; it++) {
            int e = it * 512 + tid;
            int t = e >> 10;
            int idx = e & 1023;
            int row = idx >> 2, c8 = idx & 3;
            const bf16* src = (t ? Bgl : Bgh) + (size_t)(col0 + row) * ldb + k0 + c8 * 8;
            uint32_t dst = dbase + 2 * A_T + (uint32_t)t * B_T + (uint32_t)(row * 80 + c8 * 16);
            cp16(dst, src);
        }
    };

    float acc[2][8][4];
#pragma unroll
    for (int mi = 0; mi < 2; mi++)
#pragma unroll
        for (int nj = 0; nj < 8; nj++)
#pragma unroll
            for (int c = 0; c < 4; c++) acc[mi][nj][c] = 0.f;

    const int NC = K >> 5;
    load_chunk(0, 0);
    asm volatile("cp.async.commit_group;" ::: "memory");
    if (1 < NC) load_chunk(1, 1);
    asm volatile("cp.async.commit_group;" ::: "memory");

    int stg = 0;
    for (int kc = 0; kc < NC; kc++) {
        asm volatile("cp.async.wait_group 1;" ::: "memory");
        __syncthreads();
        // prefetch kc+2 into the stage freed by kc-1
        if (kc + 2 < NC) load_chunk(kc + 2, (stg + 2 >= 3) ? stg - 1 : stg + 2);
        asm volatile("cp.async.commit_group;" ::: "memory");

        const uint32_t cbase = sbase + (uint32_t)stg * STAGE_B;
#pragma unroll
        for (int ks = 0; ks < 2; ks++) {
            uint32_t ah[2][4], al[2][4];
#pragma unroll
            for (int mi = 0; mi < 2; mi++) {
                uint32_t ad = cbase + (uint32_t)((warp_m * 32 + mi * 16) * 80 + ks * 32) + a_off;
                ldsm4(ah[mi], ad);
                ldsm4(al[mi], ad + A_T);
            }
#pragma unroll
            for (int ni = 0; ni < 4; ni++) {
                uint32_t bh[4], bl[4];
                uint32_t bd = cbase + 2 * A_T +
                              (uint32_t)((warp_n * 64 + ni * 16) * 80 + ks * 32) + b_off;
                ldsm4(bh, bd);
                ldsm4(bl, bd + B_T);
#pragma unroll
                for (int mi = 0; mi < 2; mi++)
#pragma unroll
                    for (int j = 0; j < 2; j++) {
                        const int nj = ni * 2 + j;
                        mma16816(acc[mi][nj], ah[mi], &bh[j * 2]);
                        mma16816(acc[mi][nj], ah[mi], &bl[j * 2]);
                        mma16816(acc[mi][nj], al[mi], &bh[j * 2]);
                    }
            }
        }
        __syncthreads();
        stg = (stg + 1 >= 3) ? 0 : stg + 1;
    }

    // ---- epilogue ----
    const int gid = lane >> 2, tig = lane & 3;
#pragma unroll
    for (int mi = 0; mi < 2; mi++) {
#pragma unroll
        for (int hh = 0; hh < 2; hh++) {
            const int r = row0 + warp_m * 32 + mi * 16 + gid + hh * 8;
#pragma unroll
            for (int nj = 0; nj < 8; nj++) {
                const int c = col0 + warp_n * 64 + nj * 8 + tig * 2;
                float v0 = acc[mi][nj][hh * 2 + 0] * alpha;
                float v1 = acc[mi][nj][hh * 2 + 1] * alpha;
                const size_t o = coff + (size_t)r * ldc + c;
                if (EPI == 0) {
                    C[o] = v0 + bias[c];
                    C[o + 1] = v1 + bias[c + 1];
                } else if (EPI == 1) {
                    C[o] = v0;
                    C[o + 1] = v1;
                } else if (EPI == 2) {
                    C[o] = C[o] + v0 + bias[c];
                    C[o + 1] = C[o + 1] + v1 + bias[c + 1];
                } else {
                    float g0 = v0 + bias[c], g1 = v1 + bias[c + 1];
                    g0 = 0.5f * g0 * (1.0f + erff(g0 * 0.70710678118654752f));
                    g1 = 0.5f * g1 * (1.0f + erff(g1 * 0.70710678118654752f));
                    bf16 h0, l0, h1, l1;
                    bsplit(g0, h0, l0); bsplit(g1, h1, l1);
                    Ch[o] = h0; Ch[o + 1] = h1;
                    Cl[o] = l0; Cl[o + 1] = l1;
                }
            }
        }
    }
}

// ===================== 128x128 bf16x3 GEMM (PV path, N=80 masked) =====================
#define TILE_B 10240
#define BUF_B (4 * TILE_B)
#define GEMM_SMEM (2 * BUF_B)

template <int EPI>
__global__ void __launch_bounds__(256, 1)
gemm_mma(const bf16* __restrict__ Agh, const bf16* __restrict__ Agl,
         const bf16* __restrict__ Bgh, const bf16* __restrict__ Bgl,
         const float* __restrict__ bias,
         float* __restrict__ C, bf16* __restrict__ Ch, bf16* __restrict__ Cl,
         int Ntot, int K, int lda, int ldb, int ldc,
         long long sA, long long sB, long long sC, float alpha) {
    extern __shared__ __align__(16) char smem[];
    const uint32_t sbase = smem_to_u32(smem);
    const int tid = threadIdx.x;
    const int wid = tid >> 5;
    const int lane = tid & 31;
    const int warp_m = wid & 3;
    const int warp_n = wid >> 2;
    const int bz = blockIdx.z;

    Agh += (size_t)bz * sA; Agl += (size_t)bz * sA;
    Bgh += (size_t)bz * sB; Bgl += (size_t)bz * sB;
    const size_t coff = (size_t)bz * sC;
    const int row0 = blockIdx.y * 128;
    const int col0 = blockIdx.x * 128;

    const uint32_t a_off = (uint32_t)(((lane & 15) * 40 + (lane >> 4) * 8) * 2);
    const uint32_t b_off = (uint32_t)(((((lane & 7) | ((lane >> 4) << 3)) * 40) +
                                      (((lane >> 3) & 1) * 8)) * 2);

    auto load_chunk = [&](int kc, int buf) {
        const int k0 = kc << 5;
        const uint32_t dbase = sbase + (uint32_t)buf * BUF_B;
#pragma unroll
        for (int it = 0; it < 8; it++) {
            int e = it * 256 + tid;
            int t = e >> 9;
            int idx = e & 511;
            int row = idx >> 2;
            int c8 = idx & 3;
            const bf16* src;
            int sz = 16;
            if (t == 0)      src = Agh + (size_t)(row0 + row) * lda + k0 + c8 * 8;
            else if (t == 1) src = Agl + (size_t)(row0 + row) * lda + k0 + c8 * 8;
            else {
                int br = col0 + row;
                if (br >= Ntot) { br = col0; sz = 0; }
                src = (t == 2 ? Bgh : Bgl) + (size_t)br * ldb + k0 + c8 * 8;
            }
            uint32_t dst = dbase + (uint32_t)t * TILE_B + (uint32_t)(row * 80 + c8 * 16);
            asm volatile("cp.async.cg.shared.global [%0], [%1], 16, %2;"
                         :: "r"(dst), "l"(src), "r"(sz));
        }
    };

    float acc[2][8][4];
#pragma unroll
    for (int mi = 0; mi < 2; mi++)
#pragma unroll
        for (int nj = 0; nj < 8; nj++)
#pragma unroll
            for (int c = 0; c < 4; c++) acc[mi][nj][c] = 0.f;

    const int NC = K >> 5;
    load_chunk(0, 0);
    asm volatile("cp.async.commit_group;" ::: "memory");

    for (int kc = 0; kc < NC; kc++) {
        const int buf = kc & 1;
        if (kc + 1 < NC) {
            load_chunk(kc + 1, buf ^ 1);
            asm volatile("cp.async.commit_group;" ::: "memory");
            asm volatile("cp.async.wait_group 1;" ::: "memory");
        } else {
            asm volatile("cp.async.wait_group 0;" ::: "memory");
        }
        __syncthreads();

        const uint32_t bofs = sbase + (uint32_t)buf * BUF_B;
#pragma unroll
        for (int ks = 0; ks < 2; ks++) {
            uint32_t ah[2][4], al[2][4], bh[4][4], bl[4][4];
#pragma unroll
            for (int mi = 0; mi < 2; mi++) {
                uint32_t ad = bofs + (uint32_t)((warp_m * 32 + mi * 16) * 80 + ks * 32) + a_off;
                ldsm4(ah[mi], ad);
                ldsm4(al[mi], ad + TILE_B);
            }
#pragma unroll
            for (int ni = 0; ni < 4; ni++) {
                uint32_t bd = bofs + 2 * TILE_B +
                              (uint32_t)((warp_n * 64 + ni * 16) * 80 + ks * 32) + b_off;
                ldsm4(bh[ni], bd);
                ldsm4(bl[ni], bd + TILE_B);
            }
#pragma unroll
            for (int mi = 0; mi < 2; mi++)
#pragma unroll
                for (int nj = 0; nj < 8; nj++) {
                    const uint32_t* bhp = &bh[nj >> 1][(nj & 1) * 2];
                    const uint32_t* blp = &bl[nj >> 1][(nj & 1) * 2];
                    mma16816(acc[mi][nj], ah[mi], bhp);
                    mma16816(acc[mi][nj], ah[mi], blp);
                    mma16816(acc[mi][nj], al[mi], bhp);
                }
        }
        __syncthreads();
    }

    const int gid = lane >> 2, tig = lane & 3;
#pragma unroll
    for (int mi = 0; mi < 2; mi++) {
#pragma unroll
        for (int hh = 0; hh < 2; hh++) {
            const int r = row0 + warp_m * 32 + mi * 16 + gid + hh * 8;
#pragma unroll
            for (int nj = 0; nj < 8; nj++) {
                const int c = col0 + warp_n * 64 + nj * 8 + tig * 2;
                if (c >= Ntot) continue;
                float v0 = acc[mi][nj][hh * 2 + 0] * alpha;
                float v1 = acc[mi][nj][hh * 2 + 1] * alpha;
                const size_t o = coff + (size_t)r * ldc + c;
                if (EPI == 3) {
                    bf16 h0, l0, h1, l1;
                    bsplit(v0, h0, l0); bsplit(v1, h1, l1);
                    Ch[o] = h0; Ch[o + 1] = h1;
                    Cl[o] = l0; Cl[o + 1] = l1;
                }
            }
        }
    }
}

// ===================== host-side launch =====================
extern "C" void kernel_launch(void* const* d_in, const int* in_sizes, int n_in,
                              void* d_out, int out_size) {
    const float* hidden = (const float*)d_in[0];
    const float* cosp   = (const float*)d_in[1];
    const float* sinp   = (const float*)d_in[2];
    const float* qkv_w  = (const float*)d_in[3];
    const float* qkv_b  = (const float*)d_in[4];
    const float* proj_w = (const float*)d_in[5];
    const float* proj_b = (const float*)d_in[6];
    const float* ln1_g  = (const float*)d_in[7];
    const float* ln1_b  = (const float*)d_in[8];
    const float* ln2_g  = (const float*)d_in[9];
    const float* ln2_b  = (const float*)d_in[10];
    const float* fc1_w  = (const float*)d_in[11];
    const float* fc1_b  = (const float*)d_in[12];
    const float* fc2_w  = (const float*)d_in[13];
    const float* fc2_b  = (const float*)d_in[14];

    float* x = (float*)d_out;

    float *p_qkv, *p_sc;
    bf16 *p_hh, *p_hl, *p_qh, *p_ql, *p_kh, *p_kl, *p_vth, *p_vtl;
    bf16 *p_ph, *p_pl, *p_ah, *p_al, *p_mh, *p_ml;
    bf16 *wqh, *wql, *wph, *wpl, *w1h, *w1l, *w2h, *w2l;
    cudaGetSymbolAddress((void**)&p_qkv, g_qkv);
    cudaGetSymbolAddress((void**)&p_sc,  g_scores);
    cudaGetSymbolAddress((void**)&p_hh,  g_hh);   cudaGetSymbolAddress((void**)&p_hl, g_hl);
    cudaGetSymbolAddress((void**)&p_qh,  g_qh);   cudaGetSymbolAddress((void**)&p_ql, g_ql);
    cudaGetSymbolAddress((void**)&p_kh,  g_kh);   cudaGetSymbolAddress((void**)&p_kl, g_kl);
    cudaGetSymbolAddress((void**)&p_vth, g_vth);  cudaGetSymbolAddress((void**)&p_vtl, g_vtl);
    cudaGetSymbolAddress((void**)&p_ph,  g_ph);   cudaGetSymbolAddress((void**)&p_pl, g_pl);
    cudaGetSymbolAddress((void**)&p_ah,  g_ah);   cudaGetSymbolAddress((void**)&p_al, g_al);
    cudaGetSymbolAddress((void**)&p_mh,  g_mh);   cudaGetSymbolAddress((void**)&p_ml, g_ml);
    cudaGetSymbolAddress((void**)&wqh, g_wqh);    cudaGetSymbolAddress((void**)&wql, g_wql);
    cudaGetSymbolAddress((void**)&wph, g_wph);    cudaGetSymbolAddress((void**)&wpl, g_wpl);
    cudaGetSymbolAddress((void**)&w1h, g_w1h);    cudaGetSymbolAddress((void**)&w1l, g_w1l);
    cudaGetSymbolAddress((void**)&w2h, g_w2h);    cudaGetSymbolAddress((void**)&w2l, g_w2l);

    cudaFuncSetAttribute((const void*)gemm_mma2<0>, cudaFuncAttributeMaxDynamicSharedMemorySize, GEMM2_SMEM);
    cudaFuncSetAttribute((const void*)gemm_mma2<1>, cudaFuncAttributeMaxDynamicSharedMemorySize, GEMM2_SMEM);
    cudaFuncSetAttribute((const void*)gemm_mma2<2>, cudaFuncAttributeMaxDynamicSharedMemorySize, GEMM2_SMEM);
    cudaFuncSetAttribute((const void*)gemm_mma2<4>, cudaFuncAttributeMaxDynamicSharedMemorySize, GEMM2_SMEM);
    cudaFuncSetAttribute((const void*)gemm_mma<3>,  cudaFuncAttributeMaxDynamicSharedMemorySize, GEMM_SMEM);

    cudaMemcpyAsync(x, hidden, (size_t)S_ * D_ * sizeof(float), cudaMemcpyDeviceToDevice);

    for (int l = 0; l < 2; l++) {
        const float* qw = qkv_w + (size_t)l * D_ * NQKV_;
        const float* qb = qkv_b + (size_t)l * NQKV_;
        const float* pw = proj_w + (size_t)l * D_ * D_;
        const float* pb = proj_b + (size_t)l * D_;
        const float* g1 = ln1_g + (size_t)l * D_;
        const float* b1 = ln1_b + (size_t)l * D_;
        const float* g2 = ln2_g + (size_t)l * D_;
        const float* b2 = ln2_b + (size_t)l * D_;
        const float* f1w = fc1_w + (size_t)l * D_ * I_;
        const float* f1b = fc1_b + (size_t)l * I_;
        const float* f2w = fc2_w + (size_t)l * I_ * D_;
        const float* f2b = fc2_b + (size_t)l * D_;

        // weight transpose+split
        wsplit_T_kernel<<<dim3(NQKV_ / 32, D_ / 32), dim3(32, 8)>>>(qw, wqh, wql, D_, NQKV_);
        wsplit_T_kernel<<<dim3(D_ / 32, D_ / 32), dim3(32, 8)>>>(pw, wph, wpl, D_, D_);
        wsplit_T_kernel<<<dim3(I_ / 32, D_ / 32), dim3(32, 8)>>>(f1w, w1h, w1l, D_, I_);
        wsplit_T_kernel<<<dim3(D_ / 32, I_ / 32), dim3(32, 8)>>>(f2w, w2h, w2l, I_, D_);

        // LN1 -> split
        ln_split_kernel<<<S_, 256>>>(x, g1, b1, p_hh, p_hl);

        // qkv = h @ W_qkv + b   (fp32 out)
        gemm_mma2<0><<<dim3(NQKV_ / 256, S_ / 128, 1), 512, GEMM2_SMEM>>>(
            p_hh, p_hl, wqh, wql, qb, p_qkv, nullptr, nullptr,
            D_, D_, D_, NQKV_, 0, 0, 0, 1.f);

        // RoPE + split + V^T (+zero pad)
        rope_split_kernel<<<(S_ * H_ * HDP_ + 255) / 256, 256>>>(
            p_qkv, cosp, sinp, p_qh, p_ql, p_kh, p_kl, p_vth, p_vtl);

        // scores = (Q @ K^T) * SCALE  per head (fp32), K padded to 96
        gemm_mma2<1><<<dim3(S_ / 256, S_ / 128, H_), 512, GEMM2_SMEM>>>(
            p_qh, p_ql, p_kh, p_kl, nullptr, p_sc, nullptr, nullptr,
            HDP_, HDP_, HDP_, S_,
            (long long)S_ * HDP_, (long long)S_ * HDP_, (long long)S_ * S_, SCALE_);

        // softmax -> split probs
        softmax_kernel<<<H_ * S_, 256>>>(p_sc, p_ph, p_pl);

        // O = P @ V  (bf16 split out into [S,D] with per-head col offset)
        gemm_mma<3><<<dim3(1, S_ / 128, H_), 256, GEMM_SMEM>>>(
            p_ph, p_pl, p_vth, p_vtl, nullptr, nullptr, p_ah, p_al,
            HD_, S_, S_, S_, D_,
            (long long)S_ * S_, (long long)HD_ * S_, (long long)HD_, 1.f);

        // x += O @ W_proj + b
        gemm_mma2<2><<<dim3(D_ / 256, S_ / 128, 1), 512, GEMM2_SMEM>>>(
            p_ah, p_al, wph, wpl, pb, x, nullptr, nullptr,
            D_, D_, D_, D_, 0, 0, 0, 1.f);

        // LN2 -> split
        ln_split_kernel<<<S_, 256>>>(x, g2, b2, p_hh, p_hl);

        // mlp = gelu(h @ W1 + b)  (bf16 split out)
        gemm_mma2<4><<<dim3(I_ / 256, S_ / 128, 1), 512, GEMM2_SMEM>>>(
            p_hh, p_hl, w1h, w1l, f1b, nullptr, p_mh, p_ml,
            D_, D_, D_, I_, 0, 0, 0, 1.f);

        // x += mlp @ W2 + b
        gemm_mma2<2><<<dim3(D_ / 256, S_ / 128, 1), 512, GEMM2_SMEM>>>(
            p_mh, p_ml, w2h, w2l, f2b, x, nullptr, nullptr,
            I_, I_, I_, D_, 0, 0, 0, 1.f);
    }
}

// round 10
// speedup vs baseline: 1.0020x; 1.0020x over previous
#include <cuda_runtime.h>
#include <cuda_bf16.h>
#include <math.h>
#include <stdint.h>

// Problem constants
#define S_ 2048
#define D_ 1280
#define H_ 16
#define HD_ 80
#define HDP_ 96           // padded head dim for score-MMA K (3 chunks of 32)
#define I_ 5120
#define NQKV_ 3840
#define EPS_ 1e-6f
#define SCALE_ 0.11180339887498949f  // 80^-0.5

typedef __nv_bfloat16 bf16;

// ===================== device scratch (no allocation allowed) =====================
__device__ float g_qkv[S_ * NQKV_];                  // qkv proj fp32
__device__ bf16  g_hh[S_ * D_],  g_hl[S_ * D_];      // LN out split
__device__ bf16  g_qh[H_ * S_ * HDP_], g_ql[H_ * S_ * HDP_];
__device__ bf16  g_kh[H_ * S_ * HDP_], g_kl[H_ * S_ * HDP_];
__device__ bf16  g_vth[H_ * HD_ * S_], g_vtl[H_ * HD_ * S_];   // V^T per head
__device__ float g_scores[(size_t)H_ * S_ * S_];     // 268 MB
__device__ bf16  g_ph[(size_t)H_ * S_ * S_], g_pl[(size_t)H_ * S_ * S_];
__device__ bf16  g_ah[S_ * D_],  g_al[S_ * D_];      // attn out split
__device__ bf16  g_mh[S_ * I_],  g_ml[S_ * I_];      // mlp hidden split
__device__ bf16  g_wqh[NQKV_ * D_], g_wql[NQKV_ * D_];
__device__ bf16  g_wph[D_ * D_],    g_wpl[D_ * D_];
__device__ bf16  g_w1h[I_ * D_],    g_w1l[I_ * D_];
__device__ bf16  g_w2h[D_ * I_],    g_w2l[D_ * I_];

__device__ __forceinline__ void bsplit(float v, bf16& h, bf16& l) {
    h = __float2bfloat16(v);
    l = __float2bfloat16(v - __bfloat162float(h));
}

__device__ __forceinline__ uint32_t smem_to_u32(const void* smem_ptr) {
    uint32_t addr;
    asm("{ .reg .u64 tmp; cvta.to.shared.u64 tmp, %1; cvt.u32.u64 %0, tmp; }"
        : "=r"(addr) : "l"(smem_ptr));
    return addr;
}

__device__ __forceinline__ void ldsm4(uint32_t (&r)[4], uint32_t addr) {
    asm volatile("ldmatrix.sync.aligned.m8n8.x4.shared.b16 {%0,%1,%2,%3}, [%4];"
                 : "=r"(r[0]), "=r"(r[1]), "=r"(r[2]), "=r"(r[3]) : "r"(addr));
}

__device__ __forceinline__ void mma16816(float (&d)[4], const uint32_t (&a)[4],
                                         const uint32_t* b) {
    asm volatile(
        "mma.sync.aligned.m16n8k16.row.col.f32.bf16.bf16.f32 "
        "{%0,%1,%2,%3}, {%4,%5,%6,%7}, {%8,%9}, {%0,%1,%2,%3};"
        : "+f"(d[0]), "+f"(d[1]), "+f"(d[2]), "+f"(d[3])
        : "r"(a[0]), "r"(a[1]), "r"(a[2]), "r"(a[3]), "r"(b[0]), "r"(b[1]));
}

__device__ __forceinline__ void cp16(uint32_t dst, const void* src) {
    asm volatile("cp.async.cg.shared.global [%0], [%1], 16;"
                 :: "r"(dst), "l"(src));
}

// ===================== LayerNorm -> bf16 split =====================
__global__ void ln_split_kernel(const float* __restrict__ x,
                                const float* __restrict__ g,
                                const float* __restrict__ b,
                                bf16* __restrict__ oh, bf16* __restrict__ ol) {
    const int row = blockIdx.x;
    const int t = threadIdx.x;
    __shared__ float srow[D_];
    __shared__ float red[256];

    float local = 0.f;
    for (int i = t; i < D_; i += 256) {
        float v = x[(size_t)row * D_ + i];
        srow[i] = v;
        local += v;
    }
    red[t] = local;
    __syncthreads();
    for (int s = 128; s > 0; s >>= 1) { if (t < s) red[t] += red[t + s]; __syncthreads(); }
    const float mean = red[0] * (1.0f / D_);
    __syncthreads();

    local = 0.f;
    for (int i = t; i < D_; i += 256) { float dv = srow[i] - mean; local += dv * dv; }
    red[t] = local;
    __syncthreads();
    for (int s = 128; s > 0; s >>= 1) { if (t < s) red[t] += red[t + s]; __syncthreads(); }
    const float inv = rsqrtf(red[0] * (1.0f / D_) + EPS_);

    for (int i = t; i < D_; i += 256) {
        float v = (srow[i] - mean) * inv * g[i] + b[i];
        bf16 h, l; bsplit(v, h, l);
        oh[(size_t)row * D_ + i] = h;
        ol[(size_t)row * D_ + i] = l;
    }
}

// ===================== weight transpose + split: w[K][N] -> Wt[N][K] =====================
__global__ void wsplit_T_kernel(const float* __restrict__ w,
                                bf16* __restrict__ oh, bf16* __restrict__ ol,
                                int K, int N) {
    __shared__ float tile[32][33];
    int k0 = blockIdx.y * 32, n0 = blockIdx.x * 32;
    int tx = threadIdx.x, ty = threadIdx.y;
#pragma unroll
    for (int j = 0; j < 4; j++)
        tile[ty + j * 8][tx] = w[(size_t)(k0 + ty + j * 8) * N + n0 + tx];
    __syncthreads();
#pragma unroll
    for (int j = 0; j < 4; j++) {
        int n = ty + j * 8;
        float v = tile[tx][n];
        bf16 h, l; bsplit(v, h, l);
        size_t o = (size_t)(n0 + n) * K + k0 + tx;
        oh[o] = h; ol[o] = l;
    }
}

// ===================== RoPE + head split + V transpose (incl. zero pad) =====================
__global__ void rope_split_kernel(const float* __restrict__ qkv,
                                  const float* __restrict__ cosp,
                                  const float* __restrict__ sinp,
                                  bf16* __restrict__ Qh, bf16* __restrict__ Ql,
                                  bf16* __restrict__ Kh, bf16* __restrict__ Kl,
                                  bf16* __restrict__ Vth, bf16* __restrict__ Vtl) {
    int i = blockIdx.x * blockDim.x + threadIdx.x;
    if (i >= S_ * H_ * HDP_) return;
    const int s = i / (H_ * HDP_);
    const int r = i % (H_ * HDP_);
    const int h = r / HDP_;
    const int d = r % HDP_;

    const size_t oq = ((size_t)h * S_ + s) * HDP_ + d;
    if (d >= HD_) {
        const bf16 z = __float2bfloat16(0.f);
        Qh[oq] = z; Ql[oq] = z; Kh[oq] = z; Kl[oq] = z;
        return;
    }

    const float c = cosp[s * HD_ + d];
    const float sn = sinp[s * HD_ + d];
    const size_t base = (size_t)s * NQKV_;

    const int d2 = (d < HD_ / 2) ? d + HD_ / 2 : d - HD_ / 2;
    const float sign = (d < HD_ / 2) ? -1.f : 1.f;

    const float q  = qkv[base + h * HD_ + d];
    const float qp = qkv[base + h * HD_ + d2];
    const float k  = qkv[base + D_ + h * HD_ + d];
    const float kp = qkv[base + D_ + h * HD_ + d2];
    const float v  = qkv[base + 2 * D_ + h * HD_ + d];

    const float rq = q * c + sign * qp * sn;
    const float rk = k * c + sign * kp * sn;

    bf16 hh, ll;
    bsplit(rq, hh, ll); Qh[oq] = hh; Ql[oq] = ll;
    bsplit(rk, hh, ll); Kh[oq] = hh; Kl[oq] = ll;
    const size_t ov = ((size_t)h * HD_ + d) * S_ + s;
    bsplit(v, hh, ll);  Vth[ov] = hh; Vtl[ov] = ll;
}

// ===================== row softmax -> bf16 split probs =====================
__global__ void softmax_kernel(const float* __restrict__ Sc,
                               bf16* __restrict__ Ph, bf16* __restrict__ Pl) {
    const size_t row = blockIdx.x;
    const float* p = Sc + row * S_;
    const int t = threadIdx.x;
    __shared__ float red[256];

    float v[8];
    float m = -1e30f;
#pragma unroll
    for (int i = 0; i < 8; i++) { v[i] = p[t + i * 256]; m = fmaxf(m, v[i]); }
    red[t] = m;
    __syncthreads();
    for (int s = 128; s > 0; s >>= 1) { if (t < s) red[t] = fmaxf(red[t], red[t + s]); __syncthreads(); }
    m = red[0];
    __syncthreads();

    float sum = 0.f;
#pragma unroll
    for (int i = 0; i < 8; i++) { v[i] = expf(v[i] - m); sum += v[i]; }
    red[t] = sum;
    __syncthreads();
    for (int s = 128; s > 0; s >>= 1) { if (t < s) red[t] += red[t + s]; __syncthreads(); }
    const float inv = 1.0f / red[0];
#pragma unroll
    for (int i = 0; i < 8; i++) {
        float pv = v[i] * inv;
        bf16 h, l; bsplit(pv, h, l);
        size_t o = row * S_ + t + i * 256;
        Ph[o] = h; Pl[o] = l;
    }
}

// ===================== 128x256 bf16x3 GEMM, 512 threads, 3-stage =====================
// C[M, N] = alpha * A[M,K] @ B[N,K]^T
// EPI: 0 = C=v+bias  1 = C=v  2 = C+=v+bias  4 = gelu(v+bias) split-store
#define A_T 10240             // 128 rows * 80B pitch
#define B_T 20480             // 256 rows * 80B pitch
#define STAGE_B (2 * A_T + 2 * B_T)   // 61440
#define GEMM2_SMEM (3 * STAGE_B)      // 184320

template <int EPI>
__global__ void __launch_bounds__(512, 1)
gemm_mma2(const bf16* __restrict__ Agh, const bf16* __restrict__ Agl,
          const bf16* __restrict__ Bgh, const bf16* __restrict__ Bgl,
          const float* __restrict__ bias,
          float* __restrict__ C, bf16* __restrict__ Ch, bf16* __restrict__ Cl,
          int K, int lda, int ldb, int ldc,
          long long sA, long long sB, long long sC, float alpha) {
    extern __shared__ __align__(16) char smem[];
    const uint32_t sbase = smem_to_u32(smem);
    const int tid = threadIdx.x;
    const int wid = tid >> 5;
    const int lane = tid & 31;
    const int warp_m = wid & 3;   // 4 x 32 rows
    const int warp_n = wid >> 2;  // 4 x 64 cols
    const int bz = blockIdx.z;

    Agh += (size_t)bz * sA; Agl += (size_t)bz * sA;
    Bgh += (size_t)bz * sB; Bgl += (size_t)bz * sB;
    const size_t coff = (size_t)bz * sC;
    const int row0 = blockIdx.y * 128;
    const int col0 = blockIdx.x * 256;

    const uint32_t a_off = (uint32_t)(((lane & 15) * 40 + (lane >> 4) * 8) * 2);
    const uint32_t b_off = (uint32_t)(((((lane & 7) | ((lane >> 4) << 3)) * 40) +
                                      (((lane >> 3) & 1) * 8)) * 2);

    auto load_chunk = [&](int kc, int stg) {
        const int k0 = kc << 5;
        const uint32_t dbase = sbase + (uint32_t)stg * STAGE_B;
#pragma unroll
        for (int it = 0; it < 2; it++) {
            int e = it * 512 + tid;
            int t = e >> 9;
            int idx = e & 511;
            int row = idx >> 2, c8 = idx & 3;
            const bf16* src = (t ? Agl : Agh) + (size_t)(row0 + row) * lda + k0 + c8 * 8;
            uint32_t dst = dbase + (uint32_t)t * A_T + (uint32_t)(row * 80 + c8 * 16);
            cp16(dst, src);
        }
#pragma unroll
        for (int it = 0; it < 4; it++) {
            int e = it * 512 + tid;
            int t = e >> 10;
            int idx = e & 1023;
            int row = idx >> 2, c8 = idx & 3;
            const bf16* src = (t ? Bgl : Bgh) + (size_t)(col0 + row) * ldb + k0 + c8 * 8;
            uint32_t dst = dbase + 2 * A_T + (uint32_t)t * B_T + (uint32_t)(row * 80 + c8 * 16);
            cp16(dst, src);
        }
    };

    float acc[2][8][4];
#pragma unroll
    for (int mi = 0; mi < 2; mi++)
#pragma unroll
        for (int nj = 0; nj < 8; nj++)
#pragma unroll
            for (int c = 0; c < 4; c++) acc[mi][nj][c] = 0.f;

    const int NC = K >> 5;
    load_chunk(0, 0);
    asm volatile("cp.async.commit_group;" ::: "memory");
    if (1 < NC) load_chunk(1, 1);
    asm volatile("cp.async.commit_group;" ::: "memory");

    int stg = 0;
    for (int kc = 0; kc < NC; kc++) {
        asm volatile("cp.async.wait_group 1;" ::: "memory");
        __syncthreads();
        // prefetch kc+2 into the stage freed by kc-1
        if (kc + 2 < NC) load_chunk(kc + 2, (stg + 2 >= 3) ? stg - 1 : stg + 2);
        asm volatile("cp.async.commit_group;" ::: "memory");

        const uint32_t cbase = sbase + (uint32_t)stg * STAGE_B;
#pragma unroll
        for (int ks = 0; ks < 2; ks++) {
            uint32_t ah[2][4], al[2][4];
#pragma unroll
            for (int mi = 0; mi < 2; mi++) {
                uint32_t ad = cbase + (uint32_t)((warp_m * 32 + mi * 16) * 80 + ks * 32) + a_off;
                ldsm4(ah[mi], ad);
                ldsm4(al[mi], ad + A_T);
            }
#pragma unroll
            for (int ni = 0; ni < 4; ni++) {
                uint32_t bh[4], bl[4];
                uint32_t bd = cbase + 2 * A_T +
                              (uint32_t)((warp_n * 64 + ni * 16) * 80 + ks * 32) + b_off;
                ldsm4(bh, bd);
                ldsm4(bl, bd + B_T);
#pragma unroll
                for (int mi = 0; mi < 2; mi++)
#pragma unroll
                    for (int j = 0; j < 2; j++) {
                        const int nj = ni * 2 + j;
                        mma16816(acc[mi][nj], ah[mi], &bh[j * 2]);
                        mma16816(acc[mi][nj], ah[mi], &bl[j * 2]);
                        mma16816(acc[mi][nj], al[mi], &bh[j * 2]);
                    }
            }
        }
        __syncthreads();
        stg = (stg + 1 >= 3) ? 0 : stg + 1;
    }

    // ---- epilogue ----
    const int gid = lane >> 2, tig = lane & 3;
#pragma unroll
    for (int mi = 0; mi < 2; mi++) {
#pragma unroll
        for (int hh = 0; hh < 2; hh++) {
            const int r = row0 + warp_m * 32 + mi * 16 + gid + hh * 8;
#pragma unroll
            for (int nj = 0; nj < 8; nj++) {
                const int c = col0 + warp_n * 64 + nj * 8 + tig * 2;
                float v0 = acc[mi][nj][hh * 2 + 0] * alpha;
                float v1 = acc[mi][nj][hh * 2 + 1] * alpha;
                const size_t o = coff + (size_t)r * ldc + c;
                if (EPI == 0) {
                    C[o] = v0 + bias[c];
                    C[o + 1] = v1 + bias[c + 1];
                } else if (EPI == 1) {
                    C[o] = v0;
                    C[o + 1] = v1;
                } else if (EPI == 2) {
                    C[o] = C[o] + v0 + bias[c];
                    C[o + 1] = C[o + 1] + v1 + bias[c + 1];
                } else {
                    float g0 = v0 + bias[c], g1 = v1 + bias[c + 1];
                    g0 = 0.5f * g0 * (1.0f + erff(g0 * 0.70710678118654752f));
                    g1 = 0.5f * g1 * (1.0f + erff(g1 * 0.70710678118654752f));
                    bf16 h0, l0, h1, l1;
                    bsplit(g0, h0, l0); bsplit(g1, h1, l1);
                    Ch[o] = h0; Ch[o + 1] = h1;
                    Cl[o] = l0; Cl[o + 1] = l1;
                }
            }
        }
    }
}

// ===================== 128x128 bf16x3 GEMM (PV path, N=80 masked) =====================
#define TILE_B 10240
#define BUF_B (4 * TILE_B)
#define GEMM_SMEM (2 * BUF_B)

template <int EPI>
__global__ void __launch_bounds__(256, 1)
gemm_mma(const bf16* __restrict__ Agh, const bf16* __restrict__ Agl,
         const bf16* __restrict__ Bgh, const bf16* __restrict__ Bgl,
         const float* __restrict__ bias,
         float* __restrict__ C, bf16* __restrict__ Ch, bf16* __restrict__ Cl,
         int Ntot, int K, int lda, int ldb, int ldc,
         long long sA, long long sB, long long sC, float alpha) {
    extern __shared__ __align__(16) char smem[];
    const uint32_t sbase = smem_to_u32(smem);
    const int tid = threadIdx.x;
    const int wid = tid >> 5;
    const int lane = tid & 31;
    const int warp_m = wid & 3;
    const int warp_n = wid >> 2;
    const int bz = blockIdx.z;

    Agh += (size_t)bz * sA; Agl += (size_t)bz * sA;
    Bgh += (size_t)bz * sB; Bgl += (size_t)bz * sB;
    const size_t coff = (size_t)bz * sC;
    const int row0 = blockIdx.y * 128;
    const int col0 = blockIdx.x * 128;

    const uint32_t a_off = (uint32_t)(((lane & 15) * 40 + (lane >> 4) * 8) * 2);
    const uint32_t b_off = (uint32_t)(((((lane & 7) | ((lane >> 4) << 3)) * 40) +
                                      (((lane >> 3) & 1) * 8)) * 2);

    auto load_chunk = [&](int kc, int buf) {
        const int k0 = kc << 5;
        const uint32_t dbase = sbase + (uint32_t)buf * BUF_B;
#pragma unroll
        for (int it = 0; it < 8; it++) {
            int e = it * 256 + tid;
            int t = e >> 9;
            int idx = e & 511;
            int row = idx >> 2;
            int c8 = idx & 3;
            const bf16* src;
            int sz = 16;
            if (t == 0)      src = Agh + (size_t)(row0 + row) * lda + k0 + c8 * 8;
            else if (t == 1) src = Agl + (size_t)(row0 + row) * lda + k0 + c8 * 8;
            else {
                int br = col0 + row;
                if (br >= Ntot) { br = col0; sz = 0; }
                src = (t == 2 ? Bgh : Bgl) + (size_t)br * ldb + k0 + c8 * 8;
            }
            uint32_t dst = dbase + (uint32_t)t * TILE_B + (uint32_t)(row * 80 + c8 * 16);
            asm volatile("cp.async.cg.shared.global [%0], [%1], 16, %2;"
                         :: "r"(dst), "l"(src), "r"(sz));
        }
    };

    float acc[2][8][4];
#pragma unroll
    for (int mi = 0; mi < 2; mi++)
#pragma unroll
        for (int nj = 0; nj < 8; nj++)
#pragma unroll
            for (int c = 0; c < 4; c++) acc[mi][nj][c] = 0.f;

    const int NC = K >> 5;
    load_chunk(0, 0);
    asm volatile("cp.async.commit_group;" ::: "memory");

    for (int kc = 0; kc < NC; kc++) {
        const int buf = kc & 1;
        if (kc + 1 < NC) {
            load_chunk(kc + 1, buf ^ 1);
            asm volatile("cp.async.commit_group;" ::: "memory");
            asm volatile("cp.async.wait_group 1;" ::: "memory");
        } else {
            asm volatile("cp.async.wait_group 0;" ::: "memory");
        }
        __syncthreads();

        const uint32_t bofs = sbase + (uint32_t)buf * BUF_B;
#pragma unroll
        for (int ks = 0; ks < 2; ks++) {
            uint32_t ah[2][4], al[2][4], bh[4][4], bl[4][4];
#pragma unroll
            for (int mi = 0; mi < 2; mi++) {
                uint32_t ad = bofs + (uint32_t)((warp_m * 32 + mi * 16) * 80 + ks * 32) + a_off;
                ldsm4(ah[mi], ad);
                ldsm4(al[mi], ad + TILE_B);
            }
#pragma unroll
            for (int ni = 0; ni < 4; ni++) {
                uint32_t bd = bofs + 2 * TILE_B +
                              (uint32_t)((warp_n * 64 + ni * 16) * 80 + ks * 32) + b_off;
                ldsm4(bh[ni], bd);
                ldsm4(bl[ni], bd + TILE_B);
            }
#pragma unroll
            for (int mi = 0; mi < 2; mi++)
#pragma unroll
                for (int nj = 0; nj < 8; nj++) {
                    const uint32_t* bhp = &bh[nj >> 1][(nj & 1) * 2];
                    const uint32_t* blp = &bl[nj >> 1][(nj & 1) * 2];
                    mma16816(acc[mi][nj], ah[mi], bhp);
                    mma16816(acc[mi][nj], ah[mi], blp);
                    mma16816(acc[mi][nj], al[mi], bhp);
                }
        }
        __syncthreads();
    }

    const int gid = lane >> 2, tig = lane & 3;
#pragma unroll
    for (int mi = 0; mi < 2; mi++) {
#pragma unroll
        for (int hh = 0; hh < 2; hh++) {
            const int r = row0 + warp_m * 32 + mi * 16 + gid + hh * 8;
#pragma unroll
            for (int nj = 0; nj < 8; nj++) {
                const int c = col0 + warp_n * 64 + nj * 8 + tig * 2;
                if (c >= Ntot) continue;
                float v0 = acc[mi][nj][hh * 2 + 0] * alpha;
                float v1 = acc[mi][nj][hh * 2 + 1] * alpha;
                const size_t o = coff + (size_t)r * ldc + c;
                if (EPI == 3) {
                    bf16 h0, l0, h1, l1;
                    bsplit(v0, h0, l0); bsplit(v1, h1, l1);
                    Ch[o] = h0; Ch[o + 1] = h1;
                    Cl[o] = l0; Cl[o + 1] = l1;
                }
            }
        }
    }
}

// ===================== host-side launch =====================
extern "C" void kernel_launch(void* const* d_in, const int* in_sizes, int n_in,
                              void* d_out, int out_size) {
    const float* hidden = (const float*)d_in[0];
    const float* cosp   = (const float*)d_in[1];
    const float* sinp   = (const float*)d_in[2];
    const float* qkv_w  = (const float*)d_in[3];
    const float* qkv_b  = (const float*)d_in[4];
    const float* proj_w = (const float*)d_in[5];
    const float* proj_b = (const float*)d_in[6];
    const float* ln1_g  = (const float*)d_in[7];
    const float* ln1_b  = (const float*)d_in[8];
    const float* ln2_g  = (const float*)d_in[9];
    const float* ln2_b  = (const float*)d_in[10];
    const float* fc1_w  = (const float*)d_in[11];
    const float* fc1_b  = (const float*)d_in[12];
    const float* fc2_w  = (const float*)d_in[13];
    const float* fc2_b  = (const float*)d_in[14];

    float* x = (float*)d_out;

    float *p_qkv, *p_sc;
    bf16 *p_hh, *p_hl, *p_qh, *p_ql, *p_kh, *p_kl, *p_vth, *p_vtl;
    bf16 *p_ph, *p_pl, *p_ah, *p_al, *p_mh, *p_ml;
    bf16 *wqh, *wql, *wph, *wpl, *w1h, *w1l, *w2h, *w2l;
    cudaGetSymbolAddress((void**)&p_qkv, g_qkv);
    cudaGetSymbolAddress((void**)&p_sc,  g_scores);
    cudaGetSymbolAddress((void**)&p_hh,  g_hh);   cudaGetSymbolAddress((void**)&p_hl, g_hl);
    cudaGetSymbolAddress((void**)&p_qh,  g_qh);   cudaGetSymbolAddress((void**)&p_ql, g_ql);
    cudaGetSymbolAddress((void**)&p_kh,  g_kh);   cudaGetSymbolAddress((void**)&p_kl, g_kl);
    cudaGetSymbolAddress((void**)&p_vth, g_vth);  cudaGetSymbolAddress((void**)&p_vtl, g_vtl);
    cudaGetSymbolAddress((void**)&p_ph,  g_ph);   cudaGetSymbolAddress((void**)&p_pl, g_pl);
    cudaGetSymbolAddress((void**)&p_ah,  g_ah);   cudaGetSymbolAddress((void**)&p_al, g_al);
    cudaGetSymbolAddress((void**)&p_mh,  g_mh);   cudaGetSymbolAddress((void**)&p_ml, g_ml);
    cudaGetSymbolAddress((void**)&wqh, g_wqh);    cudaGetSymbolAddress((void**)&wql, g_wql);
    cudaGetSymbolAddress((void**)&wph, g_wph);    cudaGetSymbolAddress((void**)&wpl, g_wpl);
    cudaGetSymbolAddress((void**)&w1h, g_w1h);    cudaGetSymbolAddress((void**)&w1l, g_w1l);
    cudaGetSymbolAddress((void**)&w2h, g_w2h);    cudaGetSymbolAddress((void**)&w2l, g_w2l);

    cudaFuncSetAttribute((const void*)gemm_mma2<0>, cudaFuncAttributeMaxDynamicSharedMemorySize, GEMM2_SMEM);
    cudaFuncSetAttribute((const void*)gemm_mma2<1>, cudaFuncAttributeMaxDynamicSharedMemorySize, GEMM2_SMEM);
    cudaFuncSetAttribute((const void*)gemm_mma2<2>, cudaFuncAttributeMaxDynamicSharedMemorySize, GEMM2_SMEM);
    cudaFuncSetAttribute((const void*)gemm_mma2<4>, cudaFuncAttributeMaxDynamicSharedMemorySize, GEMM2_SMEM);
    cudaFuncSetAttribute((const void*)gemm_mma<3>,  cudaFuncAttributeMaxDynamicSharedMemorySize, GEMM_SMEM);

    cudaMemcpyAsync(x, hidden, (size_t)S_ * D_ * sizeof(float), cudaMemcpyDeviceToDevice);

    for (int l = 0; l < 2; l++) {
        const float* qw = qkv_w + (size_t)l * D_ * NQKV_;
        const float* qb = qkv_b + (size_t)l * NQKV_;
        const float* pw = proj_w + (size_t)l * D_ * D_;
        const float* pb = proj_b + (size_t)l * D_;
        const float* g1 = ln1_g + (size_t)l * D_;
        const float* b1 = ln1_b + (size_t)l * D_;
        const float* g2 = ln2_g + (size_t)l * D_;
        const float* b2 = ln2_b + (size_t)l * D_;
        const float* f1w = fc1_w + (size_t)l * D_ * I_;
        const float* f1b = fc1_b + (size_t)l * I_;
        const float* f2w = fc2_w + (size_t)l * I_ * D_;
        const float* f2b = fc2_b + (size_t)l * D_;

        // weight transpose+split
        wsplit_T_kernel<<<dim3(NQKV_ / 32, D_ / 32), dim3(32, 8)>>>(qw, wqh, wql, D_, NQKV_);
        wsplit_T_kernel<<<dim3(D_ / 32, D_ / 32), dim3(32, 8)>>>(pw, wph, wpl, D_, D_);
        wsplit_T_kernel<<<dim3(I_ / 32, D_ / 32), dim3(32, 8)>>>(f1w, w1h, w1l, D_, I_);
        wsplit_T_kernel<<<dim3(D_ / 32, I_ / 32), dim3(32, 8)>>>(f2w, w2h, w2l, I_, D_);

        // LN1 -> split
        ln_split_kernel<<<S_, 256>>>(x, g1, b1, p_hh, p_hl);

        // qkv = h @ W_qkv + b   (fp32 out)
        gemm_mma2<0><<<dim3(NQKV_ / 256, S_ / 128, 1), 512, GEMM2_SMEM>>>(
            p_hh, p_hl, wqh, wql, qb, p_qkv, nullptr, nullptr,
            D_, D_, D_, NQKV_, 0, 0, 0, 1.f);

        // RoPE + split + V^T (+zero pad)
        rope_split_kernel<<<(S_ * H_ * HDP_ + 255) / 256, 256>>>(
            p_qkv, cosp, sinp, p_qh, p_ql, p_kh, p_kl, p_vth, p_vtl);

        // scores = (Q @ K^T) * SCALE  per head (fp32), K padded to 96
        gemm_mma2<1><<<dim3(S_ / 256, S_ / 128, H_), 512, GEMM2_SMEM>>>(
            p_qh, p_ql, p_kh, p_kl, nullptr, p_sc, nullptr, nullptr,
            HDP_, HDP_, HDP_, S_,
            (long long)S_ * HDP_, (long long)S_ * HDP_, (long long)S_ * S_, SCALE_);

        // softmax -> split probs
        softmax_kernel<<<H_ * S_, 256>>>(p_sc, p_ph, p_pl);

        // O = P @ V  (bf16 split out into [S,D] with per-head col offset)
        gemm_mma<3><<<dim3(1, S_ / 128, H_), 256, GEMM_SMEM>>>(
            p_ph, p_pl, p_vth, p_vtl, nullptr, nullptr, p_ah, p_al,
            HD_, S_, S_, S_, D_,
            (long long)S_ * S_, (long long)HD_ * S_, (long long)HD_, 1.f);

        // x += O @ W_proj + b
        gemm_mma2<2><<<dim3(D_ / 256, S_ / 128, 1), 512, GEMM2_SMEM>>>(
            p_ah, p_al, wph, wpl, pb, x, nullptr, nullptr,
            D_, D_, D_, D_, 0, 0, 0, 1.f);

        // LN2 -> split
        ln_split_kernel<<<S_, 256>>>(x, g2, b2, p_hh, p_hl);

        // mlp = gelu(h @ W1 + b)  (bf16 split out)
        gemm_mma2<4><<<dim3(I_ / 256, S_ / 128, 1), 512, GEMM2_SMEM>>>(
            p_hh, p_hl, w1h, w1l, f1b, nullptr, p_mh, p_ml,
            D_, D_, D_, I_, 0, 0, 0, 1.f);

        // x += mlp @ W2 + b
        gemm_mma2<2><<<dim3(D_ / 256, S_ / 128, 1), 512, GEMM2_SMEM>>>(
            p_mh, p_ml, w2h, w2l, f2b, x, nullptr, nullptr,
            I_, I_, I_, D_, 0, 0, 0, 1.f);
    }
}

// round 11
// speedup vs baseline: 1.1854x; 1.1830x over previous
#include <cuda_runtime.h>
#include <cuda_bf16.h>
#include <math.h>
#include <stdint.h>

// Problem constants
#define S_ 2048
#define D_ 1280
#define H_ 16
#define HD_ 80
#define HDP_ 96           // padded head dim (3 chunks of 32)
#define I_ 5120
#define NQKV_ 3840
#define EPS_ 1e-6f
#define SCALE_ 0.11180339887498949f  // 80^-0.5

typedef __nv_bfloat16 bf16;

// ===================== device scratch (no allocation allowed) =====================
__device__ float g_qkv[S_ * NQKV_];                  // qkv proj fp32
__device__ bf16  g_hh[S_ * D_],  g_hl[S_ * D_];      // LN out split
__device__ bf16  g_qh[H_ * S_ * HDP_], g_ql[H_ * S_ * HDP_];
__device__ bf16  g_kh[H_ * S_ * HDP_], g_kl[H_ * S_ * HDP_];
__device__ bf16  g_vth[H_ * HD_ * S_], g_vtl[H_ * HD_ * S_];   // V^T per head
__device__ bf16  g_ah[S_ * D_],  g_al[S_ * D_];      // attn out split
__device__ bf16  g_mh[S_ * I_],  g_ml[S_ * I_];      // mlp hidden split
__device__ bf16  g_wqh[NQKV_ * D_], g_wql[NQKV_ * D_];
__device__ bf16  g_wph[D_ * D_],    g_wpl[D_ * D_];
__device__ bf16  g_w1h[I_ * D_],    g_w1l[I_ * D_];
__device__ bf16  g_w2h[D_ * I_],    g_w2l[D_ * I_];

__device__ __forceinline__ void bsplit(float v, bf16& h, bf16& l) {
    h = __float2bfloat16(v);
    l = __float2bfloat16(v - __bfloat162float(h));
}

__device__ __forceinline__ uint32_t packbf(float a, float b) {
    __nv_bfloat162 t = __floats2bfloat162_rn(a, b);
    return *reinterpret_cast<uint32_t*>(&t);
}

__device__ __forceinline__ uint32_t smem_to_u32(const void* smem_ptr) {
    uint32_t addr;
    asm("{ .reg .u64 tmp; cvta.to.shared.u64 tmp, %1; cvt.u32.u64 %0, tmp; }"
        : "=r"(addr) : "l"(smem_ptr));
    return addr;
}

__device__ __forceinline__ void ldsm4(uint32_t (&r)[4], uint32_t addr) {
    asm volatile("ldmatrix.sync.aligned.m8n8.x4.shared.b16 {%0,%1,%2,%3}, [%4];"
                 : "=r"(r[0]), "=r"(r[1]), "=r"(r[2]), "=r"(r[3]) : "r"(addr));
}

__device__ __forceinline__ void mma16816(float (&d)[4], const uint32_t (&a)[4],
                                         const uint32_t* b) {
    asm volatile(
        "mma.sync.aligned.m16n8k16.row.col.f32.bf16.bf16.f32 "
        "{%0,%1,%2,%3}, {%4,%5,%6,%7}, {%8,%9}, {%0,%1,%2,%3};"
        : "+f"(d[0]), "+f"(d[1]), "+f"(d[2]), "+f"(d[3])
        : "r"(a[0]), "r"(a[1]), "r"(a[2]), "r"(a[3]), "r"(b[0]), "r"(b[1]));
}

__device__ __forceinline__ void cp16(uint32_t dst, const void* src) {
    asm volatile("cp.async.cg.shared.global [%0], [%1], 16;"
                 :: "r"(dst), "l"(src));
}

// ===================== LayerNorm -> bf16 split =====================
__global__ void ln_split_kernel(const float* __restrict__ x,
                                const float* __restrict__ g,
                                const float* __restrict__ b,
                                bf16* __restrict__ oh, bf16* __restrict__ ol) {
    const int row = blockIdx.x;
    const int t = threadIdx.x;
    __shared__ float srow[D_];
    __shared__ float red[256];

    float local = 0.f;
    for (int i = t; i < D_; i += 256) {
        float v = x[(size_t)row * D_ + i];
        srow[i] = v;
        local += v;
    }
    red[t] = local;
    __syncthreads();
    for (int s = 128; s > 0; s >>= 1) { if (t < s) red[t] += red[t + s]; __syncthreads(); }
    const float mean = red[0] * (1.0f / D_);
    __syncthreads();

    local = 0.f;
    for (int i = t; i < D_; i += 256) { float dv = srow[i] - mean; local += dv * dv; }
    red[t] = local;
    __syncthreads();
    for (int s = 128; s > 0; s >>= 1) { if (t < s) red[t] += red[t + s]; __syncthreads(); }
    const float inv = rsqrtf(red[0] * (1.0f / D_) + EPS_);

    for (int i = t; i < D_; i += 256) {
        float v = (srow[i] - mean) * inv * g[i] + b[i];
        bf16 h, l; bsplit(v, h, l);
        oh[(size_t)row * D_ + i] = h;
        ol[(size_t)row * D_ + i] = l;
    }
}

// ===================== weight transpose + split: w[K][N] -> Wt[N][K] =====================
__global__ void wsplit_T_kernel(const float* __restrict__ w,
                                bf16* __restrict__ oh, bf16* __restrict__ ol,
                                int K, int N) {
    __shared__ float tile[32][33];
    int k0 = blockIdx.y * 32, n0 = blockIdx.x * 32;
    int tx = threadIdx.x, ty = threadIdx.y;
#pragma unroll
    for (int j = 0; j < 4; j++)
        tile[ty + j * 8][tx] = w[(size_t)(k0 + ty + j * 8) * N + n0 + tx];
    __syncthreads();
#pragma unroll
    for (int j = 0; j < 4; j++) {
        int n = ty + j * 8;
        float v = tile[tx][n];
        bf16 h, l; bsplit(v, h, l);
        size_t o = (size_t)(n0 + n) * K + k0 + tx;
        oh[o] = h; ol[o] = l;
    }
}

// ===================== RoPE + head split + V transpose (incl. zero pad) =====================
__global__ void rope_split_kernel(const float* __restrict__ qkv,
                                  const float* __restrict__ cosp,
                                  const float* __restrict__ sinp,
                                  bf16* __restrict__ Qh, bf16* __restrict__ Ql,
                                  bf16* __restrict__ Kh, bf16* __restrict__ Kl,
                                  bf16* __restrict__ Vth, bf16* __restrict__ Vtl) {
    int i = blockIdx.x * blockDim.x + threadIdx.x;
    if (i >= S_ * H_ * HDP_) return;
    const int s = i / (H_ * HDP_);
    const int r = i % (H_ * HDP_);
    const int h = r / HDP_;
    const int d = r % HDP_;

    const size_t oq = ((size_t)h * S_ + s) * HDP_ + d;
    if (d >= HD_) {
        const bf16 z = __float2bfloat16(0.f);
        Qh[oq] = z; Ql[oq] = z; Kh[oq] = z; Kl[oq] = z;
        return;
    }

    const float c = cosp[s * HD_ + d];
    const float sn = sinp[s * HD_ + d];
    const size_t base = (size_t)s * NQKV_;

    const int d2 = (d < HD_ / 2) ? d + HD_ / 2 : d - HD_ / 2;
    const float sign = (d < HD_ / 2) ? -1.f : 1.f;

    const float q  = qkv[base + h * HD_ + d];
    const float qp = qkv[base + h * HD_ + d2];
    const float k  = qkv[base + D_ + h * HD_ + d];
    const float kp = qkv[base + D_ + h * HD_ + d2];
    const float v  = qkv[base + 2 * D_ + h * HD_ + d];

    const float rq = q * c + sign * qp * sn;
    const float rk = k * c + sign * kp * sn;

    bf16 hh, ll;
    bsplit(rq, hh, ll); Qh[oq] = hh; Ql[oq] = ll;
    bsplit(rk, hh, ll); Kh[oq] = hh; Kl[oq] = ll;
    const size_t ov = ((size_t)h * HD_ + d) * S_ + s;
    bsplit(v, hh, ll);  Vth[ov] = hh; Vtl[ov] = ll;
}

// ===================== fused flash attention =====================
// grid (S/128, H). 256 threads, 8 warps; warp w owns 16 query rows.
// K tile: 128 keys x 96 dims bf16, pitch 208B. V^T tile: 80 dims x 128 keys, pitch 272B.
#define FL_PK 208
#define FL_PV 272
#define FL_KT (128 * FL_PK)             // 26624
#define FL_VT (80 * FL_PV)              // 21760
#define FL_STG (2 * FL_KT + 2 * FL_VT)  // 96768
#define FLASH_SMEM (2 * FL_STG)         // 193536

__global__ void __launch_bounds__(256, 1)
flash_kernel(const bf16* __restrict__ Qh_, const bf16* __restrict__ Ql_,
             const bf16* __restrict__ Kh_, const bf16* __restrict__ Kl_,
             const bf16* __restrict__ Vth_, const bf16* __restrict__ Vtl_,
             bf16* __restrict__ Oh_, bf16* __restrict__ Ol_) {
    extern __shared__ __align__(16) char smem[];
    const uint32_t sbase = smem_to_u32(smem);
    const int tid = threadIdx.x;
    const int wid = tid >> 5;
    const int lane = tid & 31;
    const int h = blockIdx.y;
    const int q0 = blockIdx.x * 128;

    const bf16* Qhh = Qh_ + ((size_t)h * S_ + q0) * HDP_;
    const bf16* Qll = Ql_ + ((size_t)h * S_ + q0) * HDP_;
    const bf16* Khh = Kh_ + (size_t)h * S_ * HDP_;
    const bf16* Kll = Kl_ + (size_t)h * S_ * HDP_;
    const bf16* Vhh = Vth_ + (size_t)h * HD_ * S_;
    const bf16* Vll = Vtl_ + (size_t)h * HD_ * S_;

    // ---- stage Q through smem (stage-0 K area), ldmatrix to regs ----
#pragma unroll
    for (int it = 0; it < 12; it++) {
        int e = it * 256 + tid;           // 3072 = 2 splits * 128 rows * 12 chunks
        int split = e >= 1536;
        int idx = split ? e - 1536 : e;
        int row = idx / 12, c = idx % 12;
        const bf16* src = (split ? Qll : Qhh) + (size_t)row * HDP_ + c * 8;
        cp16(sbase + (uint32_t)split * FL_KT + (uint32_t)(row * FL_PK + c * 16), src);
    }
    asm volatile("cp.async.commit_group;" ::: "memory");
    asm volatile("cp.async.wait_group 0;" ::: "memory");
    __syncthreads();

    const uint32_t a_off = (uint32_t)((lane & 15) * FL_PK + (lane >> 4) * 16);
    uint32_t qfh[6][4], qfl[6][4];
#pragma unroll
    for (int ks = 0; ks < 6; ks++) {
        uint32_t ad = sbase + (uint32_t)(wid * 16 * FL_PK + ks * 32) + a_off;
        ldsm4(qfh[ks], ad);
        ldsm4(qfl[ks], ad + FL_KT);
    }
    __syncthreads();

    // ---- KV tile loader ----
    auto load_kv = [&](int t, int stg) {
        const int k0 = t * 128;
        const uint32_t db = sbase + (uint32_t)stg * FL_STG;
#pragma unroll
        for (int it = 0; it < 12; it++) {   // K: 2 splits * 128 rows * 12 chunks
            int e = it * 256 + tid;
            int split = e >= 1536;
            int idx = split ? e - 1536 : e;
            int row = idx / 12, c = idx % 12;
            const bf16* src = (split ? Kll : Khh) + (size_t)(k0 + row) * HDP_ + c * 8;
            cp16(db + (uint32_t)split * FL_KT + (uint32_t)(row * FL_PK + c * 16), src);
        }
#pragma unroll
        for (int it = 0; it < 10; it++) {   // V: 2 splits * 80 rows * 16 chunks
            int e = it * 256 + tid;
            int split = e >= 1280;
            int idx = split ? e - 1280 : e;
            int row = idx / 16, c = idx % 16;
            const bf16* src = (split ? Vll : Vhh) + (size_t)row * S_ + k0 + c * 8;
            cp16(db + 2 * FL_KT + (uint32_t)split * FL_VT + (uint32_t)(row * FL_PV + c * 16), src);
        }
    };

    const uint32_t bk_off = (uint32_t)((((lane & 7) | ((lane >> 4) << 3)) * FL_PK) +
                                       (((lane >> 3) & 1) * 16));
    const uint32_t bv_off = (uint32_t)((((lane & 7) | ((lane >> 4) << 3)) * FL_PV) +
                                       (((lane >> 3) & 1) * 16));

    float acc_o[10][4];
#pragma unroll
    for (int i = 0; i < 10; i++)
#pragma unroll
        for (int c = 0; c < 4; c++) acc_o[i][c] = 0.f;
    float m0 = -1e30f, m1 = -1e30f, sum0 = 0.f, sum1 = 0.f;
    const float SC2 = SCALE_ * 1.4426950408889634f;

    const int NT = S_ / 128;
    load_kv(0, 0);
    asm volatile("cp.async.commit_group;" ::: "memory");

    for (int t = 0; t < NT; t++) {
        const int buf = t & 1;
        if (t + 1 < NT) {
            load_kv(t + 1, buf ^ 1);
            asm volatile("cp.async.commit_group;" ::: "memory");
            asm volatile("cp.async.wait_group 1;" ::: "memory");
        } else {
            asm volatile("cp.async.wait_group 0;" ::: "memory");
        }
        __syncthreads();

        const uint32_t kb = sbase + (uint32_t)buf * FL_STG;
        const uint32_t vb = kb + 2 * FL_KT;

        // ---- S = Q @ K^T (bf16x3) ----
        float accs[16][4];
#pragma unroll
        for (int i = 0; i < 16; i++)
#pragma unroll
            for (int c = 0; c < 4; c++) accs[i][c] = 0.f;

#pragma unroll
        for (int ks = 0; ks < 6; ks++) {
#pragma unroll
            for (int nb = 0; nb < 8; nb++) {
                uint32_t kh[4], kl[4];
                uint32_t kd = kb + (uint32_t)(nb * 16 * FL_PK + ks * 32) + bk_off;
                ldsm4(kh, kd);
                ldsm4(kl, kd + FL_KT);
#pragma unroll
                for (int j = 0; j < 2; j++) {
                    mma16816(accs[nb * 2 + j], qfh[ks], &kh[j * 2]);
                    mma16816(accs[nb * 2 + j], qfh[ks], &kl[j * 2]);
                    mma16816(accs[nb * 2 + j], qfl[ks], &kh[j * 2]);
                }
            }
        }

        // ---- online softmax (rows warp-local; reduce over 4-lane quad) ----
        float tm0 = -1e30f, tm1 = -1e30f;
#pragma unroll
        for (int nj = 0; nj < 16; nj++) {
            tm0 = fmaxf(tm0, fmaxf(accs[nj][0], accs[nj][1]));
            tm1 = fmaxf(tm1, fmaxf(accs[nj][2], accs[nj][3]));
        }
        tm0 = fmaxf(tm0, __shfl_xor_sync(0xffffffff, tm0, 1));
        tm0 = fmaxf(tm0, __shfl_xor_sync(0xffffffff, tm0, 2));
        tm1 = fmaxf(tm1, __shfl_xor_sync(0xffffffff, tm1, 1));
        tm1 = fmaxf(tm1, __shfl_xor_sync(0xffffffff, tm1, 2));
        tm0 *= SC2; tm1 *= SC2;

        const float nm0 = fmaxf(m0, tm0), nm1 = fmaxf(m1, tm1);
        const float f0 = exp2f(m0 - nm0), f1 = exp2f(m1 - nm1);
        m0 = nm0; m1 = nm1;

        float rs0 = 0.f, rs1 = 0.f;
#pragma unroll
        for (int nj = 0; nj < 16; nj++) {
            accs[nj][0] = exp2f(fmaf(accs[nj][0], SC2, -m0));
            accs[nj][1] = exp2f(fmaf(accs[nj][1], SC2, -m0));
            accs[nj][2] = exp2f(fmaf(accs[nj][2], SC2, -m1));
            accs[nj][3] = exp2f(fmaf(accs[nj][3], SC2, -m1));
            rs0 += accs[nj][0] + accs[nj][1];
            rs1 += accs[nj][2] + accs[nj][3];
        }
        rs0 += __shfl_xor_sync(0xffffffff, rs0, 1);
        rs0 += __shfl_xor_sync(0xffffffff, rs0, 2);
        rs1 += __shfl_xor_sync(0xffffffff, rs1, 1);
        rs1 += __shfl_xor_sync(0xffffffff, rs1, 2);
        sum0 = sum0 * f0 + rs0;
        sum1 = sum1 * f1 + rs1;

#pragma unroll
        for (int i = 0; i < 10; i++) {
            acc_o[i][0] *= f0; acc_o[i][1] *= f0;
            acc_o[i][2] *= f1; acc_o[i][3] *= f1;
        }

        // ---- O += P @ V (bf16x3, P from accumulators) ----
#pragma unroll
        for (int kbk = 0; kbk < 8; kbk++) {
            uint32_t ah[4], al[4];
            {
                const float* p0 = accs[kbk * 2];
                const float* p1 = accs[kbk * 2 + 1];
                float r00 = p0[0] - __bfloat162float(__float2bfloat16(p0[0]));
                float r01 = p0[1] - __bfloat162float(__float2bfloat16(p0[1]));
                float r02 = p0[2] - __bfloat162float(__float2bfloat16(p0[2]));
                float r03 = p0[3] - __bfloat162float(__float2bfloat16(p0[3]));
                float r10 = p1[0] - __bfloat162float(__float2bfloat16(p1[0]));
                float r11 = p1[1] - __bfloat162float(__float2bfloat16(p1[1]));
                float r12 = p1[2] - __bfloat162float(__float2bfloat16(p1[2]));
                float r13 = p1[3] - __bfloat162float(__float2bfloat16(p1[3]));
                ah[0] = packbf(p0[0], p0[1]); ah[1] = packbf(p0[2], p0[3]);
                ah[2] = packbf(p1[0], p1[1]); ah[3] = packbf(p1[2], p1[3]);
                al[0] = packbf(r00, r01);     al[1] = packbf(r02, r03);
                al[2] = packbf(r10, r11);     al[3] = packbf(r12, r13);
            }
#pragma unroll
            for (int db = 0; db < 5; db++) {
                uint32_t vh[4], vl[4];
                uint32_t vd = vb + (uint32_t)(db * 16 * FL_PV + kbk * 32) + bv_off;
                ldsm4(vh, vd);
                ldsm4(vl, vd + FL_VT);
#pragma unroll
                for (int j = 0; j < 2; j++) {
                    mma16816(acc_o[db * 2 + j], ah, &vh[j * 2]);
                    mma16816(acc_o[db * 2 + j], ah, &vl[j * 2]);
                    mma16816(acc_o[db * 2 + j], al, &vh[j * 2]);
                }
            }
        }
        __syncthreads();
    }

    // ---- epilogue: O /= sum, split-store to [S, D] ----
    const int gid = lane >> 2, tig = lane & 3;
    const float inv0 = 1.0f / sum0, inv1 = 1.0f / sum1;
    const int r0 = q0 + wid * 16 + gid;
    const int r1 = r0 + 8;
#pragma unroll
    for (int db = 0; db < 10; db++) {
        const int col = h * HD_ + db * 8 + tig * 2;
        bf16 hh, ll;
        size_t o0 = (size_t)r0 * D_ + col;
        size_t o1 = (size_t)r1 * D_ + col;
        bsplit(acc_o[db][0] * inv0, hh, ll); Oh_[o0] = hh; Ol_[o0] = ll;
        bsplit(acc_o[db][1] * inv0, hh, ll); Oh_[o0 + 1] = hh; Ol_[o0 + 1] = ll;
        bsplit(acc_o[db][2] * inv1, hh, ll); Oh_[o1] = hh; Ol_[o1] = ll;
        bsplit(acc_o[db][3] * inv1, hh, ll); Oh_[o1 + 1] = hh; Ol_[o1 + 1] = ll;
    }
}

// ===================== 128x256 bf16x3 GEMM, 512 threads, 3-stage =====================
// C[M, N] = alpha * A[M,K] @ B[N,K]^T
// EPI: 0 = C=v+bias  1 = C=v  2 = C+=v+bias  4 = gelu(v+bias) split-store
#define A_T 10240             // 128 rows * 80B pitch
#define B_T 20480             // 256 rows * 80B pitch
#define STAGE_B (2 * A_T + 2 * B_T)   // 61440
#define GEMM2_SMEM (3 * STAGE_B)      // 184320

template <int EPI>
__global__ void __launch_bounds__(512, 1)
gemm_mma2(const bf16* __restrict__ Agh, const bf16* __restrict__ Agl,
          const bf16* __restrict__ Bgh, const bf16* __restrict__ Bgl,
          const float* __restrict__ bias,
          float* __restrict__ C, bf16* __restrict__ Ch, bf16* __restrict__ Cl,
          int K, int lda, int ldb, int ldc,
          long long sA, long long sB, long long sC, float alpha) {
    extern __shared__ __align__(16) char smem[];
    const uint32_t sbase = smem_to_u32(smem);
    const int tid = threadIdx.x;
    const int wid = tid >> 5;
    const int lane = tid & 31;
    const int warp_m = wid & 3;   // 4 x 32 rows
    const int warp_n = wid >> 2;  // 4 x 64 cols
    const int bz = blockIdx.z;

    Agh += (size_t)bz * sA; Agl += (size_t)bz * sA;
    Bgh += (size_t)bz * sB; Bgl += (size_t)bz * sB;
    const size_t coff = (size_t)bz * sC;
    const int row0 = blockIdx.y * 128;
    const int col0 = blockIdx.x * 256;

    const uint32_t a_off = (uint32_t)(((lane & 15) * 40 + (lane >> 4) * 8) * 2);
    const uint32_t b_off = (uint32_t)(((((lane & 7) | ((lane >> 4) << 3)) * 40) +
                                      (((lane >> 3) & 1) * 8)) * 2);

    auto load_chunk = [&](int kc, int stg) {
        const int k0 = kc << 5;
        const uint32_t dbase = sbase + (uint32_t)stg * STAGE_B;
#pragma unroll
        for (int it = 0; it < 2; it++) {
            int e = it * 512 + tid;
            int t = e >> 9;
            int idx = e & 511;
            int row = idx >> 2, c8 = idx & 3;
            const bf16* src = (t ? Agl : Agh) + (size_t)(row0 + row) * lda + k0 + c8 * 8;
            uint32_t dst = dbase + (uint32_t)t * A_T + (uint32_t)(row * 80 + c8 * 16);
            cp16(dst, src);
        }
#pragma unroll
        for (int it = 0; it < 4; it++) {
            int e = it * 512 + tid;
            int t = e >> 10;
            int idx = e & 1023;
            int row = idx >> 2, c8 = idx & 3;
            const bf16* src = (t ? Bgl : Bgh) + (size_t)(col0 + row) * ldb + k0 + c8 * 8;
            uint32_t dst = dbase + 2 * A_T + (uint32_t)t * B_T + (uint32_t)(row * 80 + c8 * 16);
            cp16(dst, src);
        }
    };

    float acc[2][8][4];
#pragma unroll
    for (int mi = 0; mi < 2; mi++)
#pragma unroll
        for (int nj = 0; nj < 8; nj++)
#pragma unroll
            for (int c = 0; c < 4; c++) acc[mi][nj][c] = 0.f;

    const int NC = K >> 5;
    load_chunk(0, 0);
    asm volatile("cp.async.commit_group;" ::: "memory");
    if (1 < NC) load_chunk(1, 1);
    asm volatile("cp.async.commit_group;" ::: "memory");

    int stg = 0;
    for (int kc = 0; kc < NC; kc++) {
        asm volatile("cp.async.wait_group 1;" ::: "memory");
        __syncthreads();
        if (kc + 2 < NC) load_chunk(kc + 2, (stg + 2 >= 3) ? stg - 1 : stg + 2);
        asm volatile("cp.async.commit_group;" ::: "memory");

        const uint32_t cbase = sbase + (uint32_t)stg * STAGE_B;
#pragma unroll
        for (int ks = 0; ks < 2; ks++) {
            uint32_t ah[2][4], al[2][4];
#pragma unroll
            for (int mi = 0; mi < 2; mi++) {
                uint32_t ad = cbase + (uint32_t)((warp_m * 32 + mi * 16) * 80 + ks * 32) + a_off;
                ldsm4(ah[mi], ad);
                ldsm4(al[mi], ad + A_T);
            }
#pragma unroll
            for (int ni = 0; ni < 4; ni++) {
                uint32_t bh[4], bl[4];
                uint32_t bd = cbase + 2 * A_T +
                              (uint32_t)((warp_n * 64 + ni * 16) * 80 + ks * 32) + b_off;
                ldsm4(bh, bd);
                ldsm4(bl, bd + B_T);
#pragma unroll
                for (int mi = 0; mi < 2; mi++)
#pragma unroll
                    for (int j = 0; j < 2; j++) {
                        const int nj = ni * 2 + j;
                        mma16816(acc[mi][nj], ah[mi], &bh[j * 2]);
                        mma16816(acc[mi][nj], ah[mi], &bl[j * 2]);
                        mma16816(acc[mi][nj], al[mi], &bh[j * 2]);
                    }
            }
        }
        __syncthreads();
        stg = (stg + 1 >= 3) ? 0 : stg + 1;
    }

    // ---- epilogue ----
    const int gid = lane >> 2, tig = lane & 3;
#pragma unroll
    for (int mi = 0; mi < 2; mi++) {
#pragma unroll
        for (int hh = 0; hh < 2; hh++) {
            const int r = row0 + warp_m * 32 + mi * 16 + gid + hh * 8;
#pragma unroll
            for (int nj = 0; nj < 8; nj++) {
                const int c = col0 + warp_n * 64 + nj * 8 + tig * 2;
                float v0 = acc[mi][nj][hh * 2 + 0] * alpha;
                float v1 = acc[mi][nj][hh * 2 + 1] * alpha;
                const size_t o = coff + (size_t)r * ldc + c;
                if (EPI == 0) {
                    C[o] = v0 + bias[c];
                    C[o + 1] = v1 + bias[c + 1];
                } else if (EPI == 1) {
                    C[o] = v0;
                    C[o + 1] = v1;
                } else if (EPI == 2) {
                    C[o] = C[o] + v0 + bias[c];
                    C[o + 1] = C[o + 1] + v1 + bias[c + 1];
                } else {
                    float g0 = v0 + bias[c], g1 = v1 + bias[c + 1];
                    g0 = 0.5f * g0 * (1.0f + erff(g0 * 0.70710678118654752f));
                    g1 = 0.5f * g1 * (1.0f + erff(g1 * 0.70710678118654752f));
                    bf16 h0, l0, h1, l1;
                    bsplit(g0, h0, l0); bsplit(g1, h1, l1);
                    Ch[o] = h0; Ch[o + 1] = h1;
                    Cl[o] = l0; Cl[o + 1] = l1;
                }
            }
        }
    }
}

// ===================== host-side launch =====================
extern "C" void kernel_launch(void* const* d_in, const int* in_sizes, int n_in,
                              void* d_out, int out_size) {
    const float* hidden = (const float*)d_in[0];
    const float* cosp   = (const float*)d_in[1];
    const float* sinp   = (const float*)d_in[2];
    const float* qkv_w  = (const float*)d_in[3];
    const float* qkv_b  = (const float*)d_in[4];
    const float* proj_w = (const float*)d_in[5];
    const float* proj_b = (const float*)d_in[6];
    const float* ln1_g  = (const float*)d_in[7];
    const float* ln1_b  = (const float*)d_in[8];
    const float* ln2_g  = (const float*)d_in[9];
    const float* ln2_b  = (const float*)d_in[10];
    const float* fc1_w  = (const float*)d_in[11];
    const float* fc1_b  = (const float*)d_in[12];
    const float* fc2_w  = (const float*)d_in[13];
    const float* fc2_b  = (const float*)d_in[14];

    float* x = (float*)d_out;

    float* p_qkv;
    bf16 *p_hh, *p_hl, *p_qh, *p_ql, *p_kh, *p_kl, *p_vth, *p_vtl;
    bf16 *p_ah, *p_al, *p_mh, *p_ml;
    bf16 *wqh, *wql, *wph, *wpl, *w1h, *w1l, *w2h, *w2l;
    cudaGetSymbolAddress((void**)&p_qkv, g_qkv);
    cudaGetSymbolAddress((void**)&p_hh,  g_hh);   cudaGetSymbolAddress((void**)&p_hl, g_hl);
    cudaGetSymbolAddress((void**)&p_qh,  g_qh);   cudaGetSymbolAddress((void**)&p_ql, g_ql);
    cudaGetSymbolAddress((void**)&p_kh,  g_kh);   cudaGetSymbolAddress((void**)&p_kl, g_kl);
    cudaGetSymbolAddress((void**)&p_vth, g_vth);  cudaGetSymbolAddress((void**)&p_vtl, g_vtl);
    cudaGetSymbolAddress((void**)&p_ah,  g_ah);   cudaGetSymbolAddress((void**)&p_al, g_al);
    cudaGetSymbolAddress((void**)&p_mh,  g_mh);   cudaGetSymbolAddress((void**)&p_ml, g_ml);
    cudaGetSymbolAddress((void**)&wqh, g_wqh);    cudaGetSymbolAddress((void**)&wql, g_wql);
    cudaGetSymbolAddress((void**)&wph, g_wph);    cudaGetSymbolAddress((void**)&wpl, g_wpl);
    cudaGetSymbolAddress((void**)&w1h, g_w1h);    cudaGetSymbolAddress((void**)&w1l, g_w1l);
    cudaGetSymbolAddress((void**)&w2h, g_w2h);    cudaGetSymbolAddress((void**)&w2l, g_w2l);

    cudaFuncSetAttribute((const void*)gemm_mma2<0>, cudaFuncAttributeMaxDynamicSharedMemorySize, GEMM2_SMEM);
    cudaFuncSetAttribute((const void*)gemm_mma2<1>, cudaFuncAttributeMaxDynamicSharedMemorySize, GEMM2_SMEM);
    cudaFuncSetAttribute((const void*)gemm_mma2<2>, cudaFuncAttributeMaxDynamicSharedMemorySize, GEMM2_SMEM);
    cudaFuncSetAttribute((const void*)gemm_mma2<4>, cudaFuncAttributeMaxDynamicSharedMemorySize, GEMM2_SMEM);
    cudaFuncSetAttribute((const void*)flash_kernel,  cudaFuncAttributeMaxDynamicSharedMemorySize, FLASH_SMEM);

    cudaMemcpyAsync(x, hidden, (size_t)S_ * D_ * sizeof(float), cudaMemcpyDeviceToDevice);

    for (int l = 0; l < 2; l++) {
        const float* qw = qkv_w + (size_t)l * D_ * NQKV_;
        const float* qb = qkv_b + (size_t)l * NQKV_;
        const float* pw = proj_w + (size_t)l * D_ * D_;
        const float* pb = proj_b + (size_t)l * D_;
        const float* g1 = ln1_g + (size_t)l * D_;
        const float* b1 = ln1_b + (size_t)l * D_;
        const float* g2 = ln2_g + (size_t)l * D_;
        const float* b2 = ln2_b + (size_t)l * D_;
        const float* f1w = fc1_w + (size_t)l * D_ * I_;
        const float* f1b = fc1_b + (size_t)l * I_;
        const float* f2w = fc2_w + (size_t)l * I_ * D_;
        const float* f2b = fc2_b + (size_t)l * D_;

        // weight transpose+split
        wsplit_T_kernel<<<dim3(NQKV_ / 32, D_ / 32), dim3(32, 8)>>>(qw, wqh, wql, D_, NQKV_);
        wsplit_T_kernel<<<dim3(D_ / 32, D_ / 32), dim3(32, 8)>>>(pw, wph, wpl, D_, D_);
        wsplit_T_kernel<<<dim3(I_ / 32, D_ / 32), dim3(32, 8)>>>(f1w, w1h, w1l, D_, I_);
        wsplit_T_kernel<<<dim3(D_ / 32, I_ / 32), dim3(32, 8)>>>(f2w, w2h, w2l, I_, D_);

        // LN1 -> split
        ln_split_kernel<<<S_, 256>>>(x, g1, b1, p_hh, p_hl);

        // qkv = h @ W_qkv + b   (fp32 out)
        gemm_mma2<0><<<dim3(NQKV_ / 256, S_ / 128, 1), 512, GEMM2_SMEM>>>(
            p_hh, p_hl, wqh, wql, qb, p_qkv, nullptr, nullptr,
            D_, D_, D_, NQKV_, 0, 0, 0, 1.f);

        // RoPE + split + V^T (+zero pad)
        rope_split_kernel<<<(S_ * H_ * HDP_ + 255) / 256, 256>>>(
            p_qkv, cosp, sinp, p_qh, p_ql, p_kh, p_kl, p_vth, p_vtl);

        // fused flash attention -> attn out split in [S, D]
        flash_kernel<<<dim3(S_ / 128, H_), 256, FLASH_SMEM>>>(
            p_qh, p_ql, p_kh, p_kl, p_vth, p_vtl, p_ah, p_al);

        // x += O @ W_proj + b
        gemm_mma2<2><<<dim3(D_ / 256, S_ / 128, 1), 512, GEMM2_SMEM>>>(
            p_ah, p_al, wph, wpl, pb, x, nullptr, nullptr,
            D_, D_, D_, D_, 0, 0, 0, 1.f);

        // LN2 -> split
        ln_split_kernel<<<S_, 256>>>(x, g2, b2, p_hh, p_hl);

        // mlp = gelu(h @ W1 + b)  (bf16 split out)
        gemm_mma2<4><<<dim3(I_ / 256, S_ / 128, 1), 512, GEMM2_SMEM>>>(
            p_hh, p_hl, w1h, w1l, f1b, nullptr, p_mh, p_ml,
            D_, D_, D_, I_, 0, 0, 0, 1.f);

        // x += mlp @ W2 + b
        gemm_mma2<2><<<dim3(D_ / 256, S_ / 128, 1), 512, GEMM2_SMEM>>>(
            p_mh, p_ml, w2h, w2l, f2b, x, nullptr, nullptr,
            I_, I_, I_, D_, 0, 0, 0, 1.f);
    }
}

// round 12
// speedup vs baseline: 1.2617x; 1.0644x over previous
#include <cuda_runtime.h>
#include <cuda_bf16.h>
#include <math.h>
#include <stdint.h>

// Problem constants
#define S_ 2048
#define D_ 1280
#define H_ 16
#define HD_ 80
#define HDP_ 96           // padded head dim (3 chunks of 32)
#define I_ 5120
#define NQKV_ 3840
#define EPS_ 1e-6f
#define SCALE_ 0.11180339887498949f  // 80^-0.5

typedef __nv_bfloat16 bf16;

// ===================== device scratch (no allocation allowed) =====================
__device__ float g_qkv[S_ * NQKV_];                  // qkv proj fp32
__device__ float g_part[4][S_ * D_];                 // split-K partials (42 MB)
__device__ bf16  g_hh[S_ * D_],  g_hl[S_ * D_];      // LN out split
__device__ bf16  g_qh[H_ * S_ * HDP_], g_ql[H_ * S_ * HDP_];
__device__ bf16  g_kh[H_ * S_ * HDP_], g_kl[H_ * S_ * HDP_];
__device__ bf16  g_vth[H_ * HD_ * S_], g_vtl[H_ * HD_ * S_];   // V^T per head
__device__ bf16  g_ah[S_ * D_],  g_al[S_ * D_];      // attn out split
__device__ bf16  g_mh[S_ * I_],  g_ml[S_ * I_];      // mlp hidden split
__device__ bf16  g_wqh[NQKV_ * D_], g_wql[NQKV_ * D_];
__device__ bf16  g_wph[D_ * D_],    g_wpl[D_ * D_];
__device__ bf16  g_w1h[I_ * D_],    g_w1l[I_ * D_];
__device__ bf16  g_w2h[D_ * I_],    g_w2l[D_ * I_];

__device__ __forceinline__ void bsplit(float v, bf16& h, bf16& l) {
    h = __float2bfloat16(v);
    l = __float2bfloat16(v - __bfloat162float(h));
}

__device__ __forceinline__ uint32_t packbf(float a, float b) {
    __nv_bfloat162 t = __floats2bfloat162_rn(a, b);
    return *reinterpret_cast<uint32_t*>(&t);
}

__device__ __forceinline__ uint32_t smem_to_u32(const void* smem_ptr) {
    uint32_t addr;
    asm("{ .reg .u64 tmp; cvta.to.shared.u64 tmp, %1; cvt.u32.u64 %0, tmp; }"
        : "=r"(addr) : "l"(smem_ptr));
    return addr;
}

__device__ __forceinline__ void ldsm4(uint32_t (&r)[4], uint32_t addr) {
    asm volatile("ldmatrix.sync.aligned.m8n8.x4.shared.b16 {%0,%1,%2,%3}, [%4];"
                 : "=r"(r[0]), "=r"(r[1]), "=r"(r[2]), "=r"(r[3]) : "r"(addr));
}

__device__ __forceinline__ void mma16816(float (&d)[4], const uint32_t (&a)[4],
                                         const uint32_t* b) {
    asm volatile(
        "mma.sync.aligned.m16n8k16.row.col.f32.bf16.bf16.f32 "
        "{%0,%1,%2,%3}, {%4,%5,%6,%7}, {%8,%9}, {%0,%1,%2,%3};"
        : "+f"(d[0]), "+f"(d[1]), "+f"(d[2]), "+f"(d[3])
        : "r"(a[0]), "r"(a[1]), "r"(a[2]), "r"(a[3]), "r"(b[0]), "r"(b[1]));
}

__device__ __forceinline__ void cp16(uint32_t dst, const void* src) {
    asm volatile("cp.async.cg.shared.global [%0], [%1], 16;"
                 :: "r"(dst), "l"(src));
}

// ===================== LayerNorm -> bf16 split =====================
__global__ void ln_split_kernel(const float* __restrict__ x,
                                const float* __restrict__ g,
                                const float* __restrict__ b,
                                bf16* __restrict__ oh, bf16* __restrict__ ol) {
    const int row = blockIdx.x;
    const int t = threadIdx.x;
    __shared__ float srow[D_];
    __shared__ float red[256];

    float local = 0.f;
    for (int i = t; i < D_; i += 256) {
        float v = x[(size_t)row * D_ + i];
        srow[i] = v;
        local += v;
    }
    red[t] = local;
    __syncthreads();
    for (int s = 128; s > 0; s >>= 1) { if (t < s) red[t] += red[t + s]; __syncthreads(); }
    const float mean = red[0] * (1.0f / D_);
    __syncthreads();

    local = 0.f;
    for (int i = t; i < D_; i += 256) { float dv = srow[i] - mean; local += dv * dv; }
    red[t] = local;
    __syncthreads();
    for (int s = 128; s > 0; s >>= 1) { if (t < s) red[t] += red[t + s]; __syncthreads(); }
    const float inv = rsqrtf(red[0] * (1.0f / D_) + EPS_);

    for (int i = t; i < D_; i += 256) {
        float v = (srow[i] - mean) * inv * g[i] + b[i];
        bf16 h, l; bsplit(v, h, l);
        oh[(size_t)row * D_ + i] = h;
        ol[(size_t)row * D_ + i] = l;
    }
}

// ===================== weight transpose + split: w[K][N] -> Wt[N][K] =====================
__global__ void wsplit_T_kernel(const float* __restrict__ w,
                                bf16* __restrict__ oh, bf16* __restrict__ ol,
                                int K, int N) {
    __shared__ float tile[32][33];
    int k0 = blockIdx.y * 32, n0 = blockIdx.x * 32;
    int tx = threadIdx.x, ty = threadIdx.y;
#pragma unroll
    for (int j = 0; j < 4; j++)
        tile[ty + j * 8][tx] = w[(size_t)(k0 + ty + j * 8) * N + n0 + tx];
    __syncthreads();
#pragma unroll
    for (int j = 0; j < 4; j++) {
        int n = ty + j * 8;
        float v = tile[tx][n];
        bf16 h, l; bsplit(v, h, l);
        size_t o = (size_t)(n0 + n) * K + k0 + tx;
        oh[o] = h; ol[o] = l;
    }
}

// ===================== split-K reduce: x += p0+p1+p2+p3 + bias =====================
__global__ void reduce4_kernel(const float* __restrict__ p0, const float* __restrict__ p1,
                               const float* __restrict__ p2, const float* __restrict__ p3,
                               const float* __restrict__ bias, float* __restrict__ x) {
    int i = blockIdx.x * blockDim.x + threadIdx.x;
    if (i >= S_ * D_) return;
    const int c = i % D_;
    x[i] = x[i] + ((p0[i] + p1[i]) + (p2[i] + p3[i])) + bias[c];
}

// ===================== RoPE + head split + V transpose (incl. zero pad) =====================
__global__ void rope_split_kernel(const float* __restrict__ qkv,
                                  const float* __restrict__ cosp,
                                  const float* __restrict__ sinp,
                                  bf16* __restrict__ Qh, bf16* __restrict__ Ql,
                                  bf16* __restrict__ Kh, bf16* __restrict__ Kl,
                                  bf16* __restrict__ Vth, bf16* __restrict__ Vtl) {
    int i = blockIdx.x * blockDim.x + threadIdx.x;
    if (i >= S_ * H_ * HDP_) return;
    const int s = i / (H_ * HDP_);
    const int r = i % (H_ * HDP_);
    const int h = r / HDP_;
    const int d = r % HDP_;

    const size_t oq = ((size_t)h * S_ + s) * HDP_ + d;
    if (d >= HD_) {
        const bf16 z = __float2bfloat16(0.f);
        Qh[oq] = z; Ql[oq] = z; Kh[oq] = z; Kl[oq] = z;
        return;
    }

    const float c = cosp[s * HD_ + d];
    const float sn = sinp[s * HD_ + d];
    const size_t base = (size_t)s * NQKV_;

    const int d2 = (d < HD_ / 2) ? d + HD_ / 2 : d - HD_ / 2;
    const float sign = (d < HD_ / 2) ? -1.f : 1.f;

    const float q  = qkv[base + h * HD_ + d];
    const float qp = qkv[base + h * HD_ + d2];
    const float k  = qkv[base + D_ + h * HD_ + d];
    const float kp = qkv[base + D_ + h * HD_ + d2];
    const float v  = qkv[base + 2 * D_ + h * HD_ + d];

    const float rq = q * c + sign * qp * sn;
    const float rk = k * c + sign * kp * sn;

    bf16 hh, ll;
    bsplit(rq, hh, ll); Qh[oq] = hh; Ql[oq] = ll;
    bsplit(rk, hh, ll); Kh[oq] = hh; Kl[oq] = ll;
    const size_t ov = ((size_t)h * HD_ + d) * S_ + s;
    bsplit(v, hh, ll);  Vth[ov] = hh; Vtl[ov] = ll;
}

// ===================== fused flash attention =====================
#define FL_PK 208
#define FL_PV 272
#define FL_KT (128 * FL_PK)             // 26624
#define FL_VT (80 * FL_PV)              // 21760
#define FL_STG (2 * FL_KT + 2 * FL_VT)  // 96768
#define FLASH_SMEM (2 * FL_STG)         // 193536

__global__ void __launch_bounds__(256, 1)
flash_kernel(const bf16* __restrict__ Qh_, const bf16* __restrict__ Ql_,
             const bf16* __restrict__ Kh_, const bf16* __restrict__ Kl_,
             const bf16* __restrict__ Vth_, const bf16* __restrict__ Vtl_,
             bf16* __restrict__ Oh_, bf16* __restrict__ Ol_) {
    extern __shared__ __align__(16) char smem[];
    const uint32_t sbase = smem_to_u32(smem);
    const int tid = threadIdx.x;
    const int wid = tid >> 5;
    const int lane = tid & 31;
    const int h = blockIdx.y;
    const int q0 = blockIdx.x * 128;

    const bf16* Qhh = Qh_ + ((size_t)h * S_ + q0) * HDP_;
    const bf16* Qll = Ql_ + ((size_t)h * S_ + q0) * HDP_;
    const bf16* Khh = Kh_ + (size_t)h * S_ * HDP_;
    const bf16* Kll = Kl_ + (size_t)h * S_ * HDP_;
    const bf16* Vhh = Vth_ + (size_t)h * HD_ * S_;
    const bf16* Vll = Vtl_ + (size_t)h * HD_ * S_;

#pragma unroll
    for (int it = 0; it < 12; it++) {
        int e = it * 256 + tid;
        int split = e >= 1536;
        int idx = split ? e - 1536 : e;
        int row = idx / 12, c = idx % 12;
        const bf16* src = (split ? Qll : Qhh) + (size_t)row * HDP_ + c * 8;
        cp16(sbase + (uint32_t)split * FL_KT + (uint32_t)(row * FL_PK + c * 16), src);
    }
    asm volatile("cp.async.commit_group;" ::: "memory");
    asm volatile("cp.async.wait_group 0;" ::: "memory");
    __syncthreads();

    const uint32_t a_off = (uint32_t)((lane & 15) * FL_PK + (lane >> 4) * 16);
    uint32_t qfh[6][4], qfl[6][4];
#pragma unroll
    for (int ks = 0; ks < 6; ks++) {
        uint32_t ad = sbase + (uint32_t)(wid * 16 * FL_PK + ks * 32) + a_off;
        ldsm4(qfh[ks], ad);
        ldsm4(qfl[ks], ad + FL_KT);
    }
    __syncthreads();

    auto load_kv = [&](int t, int stg) {
        const int k0 = t * 128;
        const uint32_t db = sbase + (uint32_t)stg * FL_STG;
#pragma unroll
        for (int it = 0; it < 12; it++) {
            int e = it * 256 + tid;
            int split = e >= 1536;
            int idx = split ? e - 1536 : e;
            int row = idx / 12, c = idx % 12;
            const bf16* src = (split ? Kll : Khh) + (size_t)(k0 + row) * HDP_ + c * 8;
            cp16(db + (uint32_t)split * FL_KT + (uint32_t)(row * FL_PK + c * 16), src);
        }
#pragma unroll
        for (int it = 0; it < 10; it++) {
            int e = it * 256 + tid;
            int split = e >= 1280;
            int idx = split ? e - 1280 : e;
            int row = idx / 16, c = idx % 16;
            const bf16* src = (split ? Vll : Vhh) + (size_t)row * S_ + k0 + c * 8;
            cp16(db + 2 * FL_KT + (uint32_t)split * FL_VT + (uint32_t)(row * FL_PV + c * 16), src);
        }
    };

    const uint32_t bk_off = (uint32_t)((((lane & 7) | ((lane >> 4) << 3)) * FL_PK) +
                                       (((lane >> 3) & 1) * 16));
    const uint32_t bv_off = (uint32_t)((((lane & 7) | ((lane >> 4) << 3)) * FL_PV) +
                                       (((lane >> 3) & 1) * 16));

    float acc_o[10][4];
#pragma unroll
    for (int i = 0; i < 10; i++)
#pragma unroll
        for (int c = 0; c < 4; c++) acc_o[i][c] = 0.f;
    float m0 = -1e30f, m1 = -1e30f, sum0 = 0.f, sum1 = 0.f;
    const float SC2 = SCALE_ * 1.4426950408889634f;

    const int NT = S_ / 128;
    load_kv(0, 0);
    asm volatile("cp.async.commit_group;" ::: "memory");

    for (int t = 0; t < NT; t++) {
        const int buf = t & 1;
        if (t + 1 < NT) {
            load_kv(t + 1, buf ^ 1);
            asm volatile("cp.async.commit_group;" ::: "memory");
            asm volatile("cp.async.wait_group 1;" ::: "memory");
        } else {
            asm volatile("cp.async.wait_group 0;" ::: "memory");
        }
        __syncthreads();

        const uint32_t kb = sbase + (uint32_t)buf * FL_STG;
        const uint32_t vb = kb + 2 * FL_KT;

        float accs[16][4];
#pragma unroll
        for (int i = 0; i < 16; i++)
#pragma unroll
            for (int c = 0; c < 4; c++) accs[i][c] = 0.f;

#pragma unroll
        for (int ks = 0; ks < 6; ks++) {
#pragma unroll
            for (int nb = 0; nb < 8; nb++) {
                uint32_t kh[4], kl[4];
                uint32_t kd = kb + (uint32_t)(nb * 16 * FL_PK + ks * 32) + bk_off;
                ldsm4(kh, kd);
                ldsm4(kl, kd + FL_KT);
#pragma unroll
                for (int j = 0; j < 2; j++) {
                    mma16816(accs[nb * 2 + j], qfh[ks], &kh[j * 2]);
                    mma16816(accs[nb * 2 + j], qfh[ks], &kl[j * 2]);
                    mma16816(accs[nb * 2 + j], qfl[ks], &kh[j * 2]);
                }
            }
        }

        float tm0 = -1e30f, tm1 = -1e30f;
#pragma unroll
        for (int nj = 0; nj < 16; nj++) {
            tm0 = fmaxf(tm0, fmaxf(accs[nj][0], accs[nj][1]));
            tm1 = fmaxf(tm1, fmaxf(accs[nj][2], accs[nj][3]));
        }
        tm0 = fmaxf(tm0, __shfl_xor_sync(0xffffffff, tm0, 1));
        tm0 = fmaxf(tm0, __shfl_xor_sync(0xffffffff, tm0, 2));
        tm1 = fmaxf(tm1, __shfl_xor_sync(0xffffffff, tm1, 1));
        tm1 = fmaxf(tm1, __shfl_xor_sync(0xffffffff, tm1, 2));
        tm0 *= SC2; tm1 *= SC2;

        const float nm0 = fmaxf(m0, tm0), nm1 = fmaxf(m1, tm1);
        const float f0 = exp2f(m0 - nm0), f1 = exp2f(m1 - nm1);
        m0 = nm0; m1 = nm1;

        float rs0 = 0.f, rs1 = 0.f;
#pragma unroll
        for (int nj = 0; nj < 16; nj++) {
            accs[nj][0] = exp2f(fmaf(accs[nj][0], SC2, -m0));
            accs[nj][1] = exp2f(fmaf(accs[nj][1], SC2, -m0));
            accs[nj][2] = exp2f(fmaf(accs[nj][2], SC2, -m1));
            accs[nj][3] = exp2f(fmaf(accs[nj][3], SC2, -m1));
            rs0 += accs[nj][0] + accs[nj][1];
            rs1 += accs[nj][2] + accs[nj][3];
        }
        rs0 += __shfl_xor_sync(0xffffffff, rs0, 1);
        rs0 += __shfl_xor_sync(0xffffffff, rs0, 2);
        rs1 += __shfl_xor_sync(0xffffffff, rs1, 1);
        rs1 += __shfl_xor_sync(0xffffffff, rs1, 2);
        sum0 = sum0 * f0 + rs0;
        sum1 = sum1 * f1 + rs1;

#pragma unroll
        for (int i = 0; i < 10; i++) {
            acc_o[i][0] *= f0; acc_o[i][1] *= f0;
            acc_o[i][2] *= f1; acc_o[i][3] *= f1;
        }

#pragma unroll
        for (int kbk = 0; kbk < 8; kbk++) {
            uint32_t ah[4], al[4];
            {
                const float* p0 = accs[kbk * 2];
                const float* p1 = accs[kbk * 2 + 1];
                float r00 = p0[0] - __bfloat162float(__float2bfloat16(p0[0]));
                float r01 = p0[1] - __bfloat162float(__float2bfloat16(p0[1]));
                float r02 = p0[2] - __bfloat162float(__float2bfloat16(p0[2]));
                float r03 = p0[3] - __bfloat162float(__float2bfloat16(p0[3]));
                float r10 = p1[0] - __bfloat162float(__float2bfloat16(p1[0]));
                float r11 = p1[1] - __bfloat162float(__float2bfloat16(p1[1]));
                float r12 = p1[2] - __bfloat162float(__float2bfloat16(p1[2]));
                float r13 = p1[3] - __bfloat162float(__float2bfloat16(p1[3]));
                ah[0] = packbf(p0[0], p0[1]); ah[1] = packbf(p0[2], p0[3]);
                ah[2] = packbf(p1[0], p1[1]); ah[3] = packbf(p1[2], p1[3]);
                al[0] = packbf(r00, r01);     al[1] = packbf(r02, r03);
                al[2] = packbf(r10, r11);     al[3] = packbf(r12, r13);
            }
#pragma unroll
            for (int db = 0; db < 5; db++) {
                uint32_t vh[4], vl[4];
                uint32_t vd = vb + (uint32_t)(db * 16 * FL_PV + kbk * 32) + bv_off;
                ldsm4(vh, vd);
                ldsm4(vl, vd + FL_VT);
#pragma unroll
                for (int j = 0; j < 2; j++) {
                    mma16816(acc_o[db * 2 + j], ah, &vh[j * 2]);
                    mma16816(acc_o[db * 2 + j], ah, &vl[j * 2]);
                    mma16816(acc_o[db * 2 + j], al, &vh[j * 2]);
                }
            }
        }
        __syncthreads();
    }

    const int gid = lane >> 2, tig = lane & 3;
    const float inv0 = 1.0f / sum0, inv1 = 1.0f / sum1;
    const int r0 = q0 + wid * 16 + gid;
    const int r1 = r0 + 8;
#pragma unroll
    for (int db = 0; db < 10; db++) {
        const int col = h * HD_ + db * 8 + tig * 2;
        bf16 hh, ll;
        size_t o0 = (size_t)r0 * D_ + col;
        size_t o1 = (size_t)r1 * D_ + col;
        bsplit(acc_o[db][0] * inv0, hh, ll); Oh_[o0] = hh; Ol_[o0] = ll;
        bsplit(acc_o[db][1] * inv0, hh, ll); Oh_[o0 + 1] = hh; Ol_[o0 + 1] = ll;
        bsplit(acc_o[db][2] * inv1, hh, ll); Oh_[o1] = hh; Ol_[o1] = ll;
        bsplit(acc_o[db][3] * inv1, hh, ll); Oh_[o1 + 1] = hh; Ol_[o1 + 1] = ll;
    }
}

// ===================== 128x256 bf16x3 GEMM, 512 threads, 3-stage =====================
// C[M, N] = alpha * A[M,K] @ B[N,K]^T
// EPI: 0 = C=v+bias  1 = C=v  2 = C+=v+bias  4 = gelu(v+bias) split-store
//      5 = split-K partial: z selects K-slice (sA/sB = K-elem offset) and C slab (sC)
#define A_T 10240
#define B_T 20480
#define STAGE_B (2 * A_T + 2 * B_T)
#define GEMM2_SMEM (3 * STAGE_B)

template <int EPI>
__global__ void __launch_bounds__(512, 1)
gemm_mma2(const bf16* __restrict__ Agh, const bf16* __restrict__ Agl,
          const bf16* __restrict__ Bgh, const bf16* __restrict__ Bgl,
          const float* __restrict__ bias,
          float* __restrict__ C, bf16* __restrict__ Ch, bf16* __restrict__ Cl,
          int K, int lda, int ldb, int ldc,
          long long sA, long long sB, long long sC, float alpha) {
    extern __shared__ __align__(16) char smem[];
    const uint32_t sbase = smem_to_u32(smem);
    const int tid = threadIdx.x;
    const int wid = tid >> 5;
    const int lane = tid & 31;
    const int warp_m = wid & 3;
    const int warp_n = wid >> 2;
    const int bz = blockIdx.z;

    Agh += (size_t)bz * sA; Agl += (size_t)bz * sA;
    Bgh += (size_t)bz * sB; Bgl += (size_t)bz * sB;
    const size_t coff = (size_t)bz * sC;
    const int row0 = blockIdx.y * 128;
    const int col0 = blockIdx.x * 256;

    const uint32_t a_off = (uint32_t)(((lane & 15) * 40 + (lane >> 4) * 8) * 2);
    const uint32_t b_off = (uint32_t)(((((lane & 7) | ((lane >> 4) << 3)) * 40) +
                                      (((lane >> 3) & 1) * 8) ) * 2);

    auto load_chunk = [&](int kc, int stg) {
        const int k0 = kc << 5;
        const uint32_t dbase = sbase + (uint32_t)stg * STAGE_B;
#pragma unroll
        for (int it = 0; it < 2; it++) {
            int e = it * 512 + tid;
            int t = e >> 9;
            int idx = e & 511;
            int row = idx >> 2, c8 = idx & 3;
            const bf16* src = (t ? Agl : Agh) + (size_t)(row0 + row) * lda + k0 + c8 * 8;
            uint32_t dst = dbase + (uint32_t)t * A_T + (uint32_t)(row * 80 + c8 * 16);
            cp16(dst, src);
        }
#pragma unroll
        for (int it = 0; it < 4; it++) {
            int e = it * 512 + tid;
            int t = e >> 10;
            int idx = e & 1023;
            int row = idx >> 2, c8 = idx & 3;
            const bf16* src = (t ? Bgl : Bgh) + (size_t)(col0 + row) * ldb + k0 + c8 * 8;
            uint32_t dst = dbase + 2 * A_T + (uint32_t)t * B_T + (uint32_t)(row * 80 + c8 * 16);
            cp16(dst, src);
        }
    };

    float acc[2][8][4];
#pragma unroll
    for (int mi = 0; mi < 2; mi++)
#pragma unroll
        for (int nj = 0; nj < 8; nj++)
#pragma unroll
            for (int c = 0; c < 4; c++) acc[mi][nj][c] = 0.f;

    const int NC = K >> 5;
    load_chunk(0, 0);
    asm volatile("cp.async.commit_group;" ::: "memory");
    if (1 < NC) load_chunk(1, 1);
    asm volatile("cp.async.commit_group;" ::: "memory");

    int stg = 0;
    for (int kc = 0; kc < NC; kc++) {
        asm volatile("cp.async.wait_group 1;" ::: "memory");
        __syncthreads();
        if (kc + 2 < NC) load_chunk(kc + 2, (stg + 2 >= 3) ? stg - 1 : stg + 2);
        asm volatile("cp.async.commit_group;" ::: "memory");

        const uint32_t cbase = sbase + (uint32_t)stg * STAGE_B;
#pragma unroll
        for (int ks = 0; ks < 2; ks++) {
            uint32_t ah[2][4], al[2][4];
#pragma unroll
            for (int mi = 0; mi < 2; mi++) {
                uint32_t ad = cbase + (uint32_t)((warp_m * 32 + mi * 16) * 80 + ks * 32) + a_off;
                ldsm4(ah[mi], ad);
                ldsm4(al[mi], ad + A_T);
            }
#pragma unroll
            for (int ni = 0; ni < 4; ni++) {
                uint32_t bh[4], bl[4];
                uint32_t bd = cbase + 2 * A_T +
                              (uint32_t)((warp_n * 64 + ni * 16) * 80 + ks * 32) + b_off;
                ldsm4(bh, bd);
                ldsm4(bl, bd + B_T);
#pragma unroll
                for (int mi = 0; mi < 2; mi++)
#pragma unroll
                    for (int j = 0; j < 2; j++) {
                        const int nj = ni * 2 + j;
                        mma16816(acc[mi][nj], ah[mi], &bh[j * 2]);
                        mma16816(acc[mi][nj], ah[mi], &bl[j * 2]);
                        mma16816(acc[mi][nj], al[mi], &bh[j * 2]);
                    }
            }
        }
        __syncthreads();
        stg = (stg + 1 >= 3) ? 0 : stg + 1;
    }

    const int gid = lane >> 2, tig = lane & 3;
#pragma unroll
    for (int mi = 0; mi < 2; mi++) {
#pragma unroll
        for (int hh = 0; hh < 2; hh++) {
            const int r = row0 + warp_m * 32 + mi * 16 + gid + hh * 8;
#pragma unroll
            for (int nj = 0; nj < 8; nj++) {
                const int c = col0 + warp_n * 64 + nj * 8 + tig * 2;
                float v0 = acc[mi][nj][hh * 2 + 0] * alpha;
                float v1 = acc[mi][nj][hh * 2 + 1] * alpha;
                const size_t o = coff + (size_t)r * ldc + c;
                if (EPI == 0) {
                    C[o] = v0 + bias[c];
                    C[o + 1] = v1 + bias[c + 1];
                } else if (EPI == 1 || EPI == 5) {
                    C[o] = v0;
                    C[o + 1] = v1;
                } else if (EPI == 2) {
                    C[o] = C[o] + v0 + bias[c];
                    C[o + 1] = C[o + 1] + v1 + bias[c + 1];
                } else {
                    float g0 = v0 + bias[c], g1 = v1 + bias[c + 1];
                    g0 = 0.5f * g0 * (1.0f + erff(g0 * 0.70710678118654752f));
                    g1 = 0.5f * g1 * (1.0f + erff(g1 * 0.70710678118654752f));
                    bf16 h0, l0, h1, l1;
                    bsplit(g0, h0, l0); bsplit(g1, h1, l1);
                    Ch[o] = h0; Ch[o + 1] = h1;
                    Cl[o] = l0; Cl[o + 1] = l1;
                }
            }
        }
    }
}

// ===================== host-side launch =====================
extern "C" void kernel_launch(void* const* d_in, const int* in_sizes, int n_in,
                              void* d_out, int out_size) {
    const float* hidden = (const float*)d_in[0];
    const float* cosp   = (const float*)d_in[1];
    const float* sinp   = (const float*)d_in[2];
    const float* qkv_w  = (const float*)d_in[3];
    const float* qkv_b  = (const float*)d_in[4];
    const float* proj_w = (const float*)d_in[5];
    const float* proj_b = (const float*)d_in[6];
    const float* ln1_g  = (const float*)d_in[7];
    const float* ln1_b  = (const float*)d_in[8];
    const float* ln2_g  = (const float*)d_in[9];
    const float* ln2_b  = (const float*)d_in[10];
    const float* fc1_w  = (const float*)d_in[11];
    const float* fc1_b  = (const float*)d_in[12];
    const float* fc2_w  = (const float*)d_in[13];
    const float* fc2_b  = (const float*)d_in[14];

    float* x = (float*)d_out;

    float *p_qkv, *p_part;
    bf16 *p_hh, *p_hl, *p_qh, *p_ql, *p_kh, *p_kl, *p_vth, *p_vtl;
    bf16 *p_ah, *p_al, *p_mh, *p_ml;
    bf16 *wqh, *wql, *wph, *wpl, *w1h, *w1l, *w2h, *w2l;
    cudaGetSymbolAddress((void**)&p_qkv, g_qkv);
    cudaGetSymbolAddress((void**)&p_part, g_part);
    cudaGetSymbolAddress((void**)&p_hh,  g_hh);   cudaGetSymbolAddress((void**)&p_hl, g_hl);
    cudaGetSymbolAddress((void**)&p_qh,  g_qh);   cudaGetSymbolAddress((void**)&p_ql, g_ql);
    cudaGetSymbolAddress((void**)&p_kh,  g_kh);   cudaGetSymbolAddress((void**)&p_kl, g_kl);
    cudaGetSymbolAddress((void**)&p_vth, g_vth);  cudaGetSymbolAddress((void**)&p_vtl, g_vtl);
    cudaGetSymbolAddress((void**)&p_ah,  g_ah);   cudaGetSymbolAddress((void**)&p_al, g_al);
    cudaGetSymbolAddress((void**)&p_mh,  g_mh);   cudaGetSymbolAddress((void**)&p_ml, g_ml);
    cudaGetSymbolAddress((void**)&wqh, g_wqh);    cudaGetSymbolAddress((void**)&wql, g_wql);
    cudaGetSymbolAddress((void**)&wph, g_wph);    cudaGetSymbolAddress((void**)&wpl, g_wpl);
    cudaGetSymbolAddress((void**)&w1h, g_w1h);    cudaGetSymbolAddress((void**)&w1l, g_w1l);
    cudaGetSymbolAddress((void**)&w2h, g_w2h);    cudaGetSymbolAddress((void**)&w2l, g_w2l);

    float* part[4] = {p_part, p_part + S_ * D_, p_part + 2 * S_ * D_, p_part + 3 * S_ * D_};

    cudaFuncSetAttribute((const void*)gemm_mma2<0>, cudaFuncAttributeMaxDynamicSharedMemorySize, GEMM2_SMEM);
    cudaFuncSetAttribute((const void*)gemm_mma2<4>, cudaFuncAttributeMaxDynamicSharedMemorySize, GEMM2_SMEM);
    cudaFuncSetAttribute((const void*)gemm_mma2<5>, cudaFuncAttributeMaxDynamicSharedMemorySize, GEMM2_SMEM);
    cudaFuncSetAttribute((const void*)flash_kernel,  cudaFuncAttributeMaxDynamicSharedMemorySize, FLASH_SMEM);

    cudaMemcpyAsync(x, hidden, (size_t)S_ * D_ * sizeof(float), cudaMemcpyDeviceToDevice);

    for (int l = 0; l < 2; l++) {
        const float* qw = qkv_w + (size_t)l * D_ * NQKV_;
        const float* qb = qkv_b + (size_t)l * NQKV_;
        const float* pw = proj_w + (size_t)l * D_ * D_;
        const float* pb = proj_b + (size_t)l * D_;
        const float* g1 = ln1_g + (size_t)l * D_;
        const float* b1 = ln1_b + (size_t)l * D_;
        const float* g2 = ln2_g + (size_t)l * D_;
        const float* b2 = ln2_b + (size_t)l * D_;
        const float* f1w = fc1_w + (size_t)l * D_ * I_;
        const float* f1b = fc1_b + (size_t)l * I_;
        const float* f2w = fc2_w + (size_t)l * I_ * D_;
        const float* f2b = fc2_b + (size_t)l * D_;

        // LN1 first (so the profiled 6th launch is the qkv GEMM)
        ln_split_kernel<<<S_, 256>>>(x, g1, b1, p_hh, p_hl);

        // weight transpose+split (qkv/proj/fc1 now; fc2 later)
        wsplit_T_kernel<<<dim3(NQKV_ / 32, D_ / 32), dim3(32, 8)>>>(qw, wqh, wql, D_, NQKV_);
        wsplit_T_kernel<<<dim3(D_ / 32, D_ / 32), dim3(32, 8)>>>(pw, wph, wpl, D_, D_);
        wsplit_T_kernel<<<dim3(I_ / 32, D_ / 32), dim3(32, 8)>>>(f1w, w1h, w1l, D_, I_);

        // qkv = h @ W_qkv + b   (fp32 out)
        gemm_mma2<0><<<dim3(NQKV_ / 256, S_ / 128, 1), 512, GEMM2_SMEM>>>(
            p_hh, p_hl, wqh, wql, qb, p_qkv, nullptr, nullptr,
            D_, D_, D_, NQKV_, 0, 0, 0, 1.f);

        // RoPE + split + V^T (+zero pad)
        rope_split_kernel<<<(S_ * H_ * HDP_ + 255) / 256, 256>>>(
            p_qkv, cosp, sinp, p_qh, p_ql, p_kh, p_kl, p_vth, p_vtl);

        // fused flash attention -> attn out split in [S, D]
        flash_kernel<<<dim3(S_ / 128, H_), 256, FLASH_SMEM>>>(
            p_qh, p_ql, p_kh, p_kl, p_vth, p_vtl, p_ah, p_al);

        // proj: split-K=4 (K=1280 -> 320 each), partials then reduce into x
        gemm_mma2<5><<<dim3(D_ / 256, S_ / 128, 4), 512, GEMM2_SMEM>>>(
            p_ah, p_al, wph, wpl, nullptr, part[0], nullptr, nullptr,
            D_ / 4, D_, D_, D_, D_ / 4, D_ / 4, (long long)S_ * D_, 1.f);
        reduce4_kernel<<<(S_ * D_ + 255) / 256, 256>>>(
            part[0], part[1], part[2], part[3], pb, x);

        // LN2 -> split
        ln_split_kernel<<<S_, 256>>>(x, g2, b2, p_hh, p_hl);

        // mlp = gelu(h @ W1 + b)  (bf16 split out)
        gemm_mma2<4><<<dim3(I_ / 256, S_ / 128, 1), 512, GEMM2_SMEM>>>(
            p_hh, p_hl, w1h, w1l, f1b, nullptr, p_mh, p_ml,
            D_, D_, D_, I_, 0, 0, 0, 1.f);

        // fc2 weights now, then fc2: split-K=4 (K=5120 -> 1280 each)
        wsplit_T_kernel<<<dim3(D_ / 32, I_ / 32), dim3(32, 8)>>>(f2w, w2h, w2l, I_, D_);
        gemm_mma2<5><<<dim3(D_ / 256, S_ / 128, 4), 512, GEMM2_SMEM>>>(
            p_mh, p_ml, w2h, w2l, nullptr, part[0], nullptr, nullptr,
            I_ / 4, I_, I_, D_, I_ / 4, I_ / 4, (long long)S_ * D_, 1.f);
        reduce4_kernel<<<(S_ * D_ + 255) / 256, 256>>>(
            part[0], part[1], part[2], part[3], f2b, x);
    }
}

// round 13
// speedup vs baseline: 1.3973x; 1.1074x over previous
#include <cuda_runtime.h>
#include <cuda_bf16.h>
#include <math.h>
#include <stdint.h>

// Problem constants
#define S_ 2048
#define D_ 1280
#define H_ 16
#define HD_ 80
#define HDP_ 96           // padded head dim (3 chunks of 32)
#define I_ 5120
#define NQKV_ 3840
#define EPS_ 1e-6f
#define SCALE_ 0.11180339887498949f  // 80^-0.5

typedef __nv_bfloat16 bf16;

// ===================== device scratch (no allocation allowed) =====================
__device__ float g_qkv[S_ * NQKV_];                  // qkv proj fp32
__device__ float g_part[5][S_ * D_];                 // split-K partials (52 MB)
__device__ float g_part1[2][S_ * I_];                // fc1 split-K partials (84 MB)
__device__ bf16  g_hh[S_ * D_],  g_hl[S_ * D_];      // LN out split
__device__ bf16  g_qh[H_ * S_ * HDP_], g_ql[H_ * S_ * HDP_];
__device__ bf16  g_kh[H_ * S_ * HDP_], g_kl[H_ * S_ * HDP_];
__device__ bf16  g_vth[H_ * HD_ * S_], g_vtl[H_ * HD_ * S_];   // V^T per head
__device__ bf16  g_ah[S_ * D_],  g_al[S_ * D_];      // attn out split
__device__ bf16  g_mh[S_ * I_],  g_ml[S_ * I_];      // mlp hidden split
__device__ bf16  g_wqh[NQKV_ * D_], g_wql[NQKV_ * D_];
__device__ bf16  g_wph[D_ * D_],    g_wpl[D_ * D_];
__device__ bf16  g_w1h[I_ * D_],    g_w1l[I_ * D_];
__device__ bf16  g_w2h[D_ * I_],    g_w2l[D_ * I_];

__device__ __forceinline__ void bsplit(float v, bf16& h, bf16& l) {
    h = __float2bfloat16(v);
    l = __float2bfloat16(v - __bfloat162float(h));
}

__device__ __forceinline__ uint32_t packbf(float a, float b) {
    __nv_bfloat162 t = __floats2bfloat162_rn(a, b);
    return *reinterpret_cast<uint32_t*>(&t);
}

__device__ __forceinline__ uint32_t smem_to_u32(const void* smem_ptr) {
    uint32_t addr;
    asm("{ .reg .u64 tmp; cvta.to.shared.u64 tmp, %1; cvt.u32.u64 %0, tmp; }"
        : "=r"(addr) : "l"(smem_ptr));
    return addr;
}

__device__ __forceinline__ void ldsm4(uint32_t (&r)[4], uint32_t addr) {
    asm volatile("ldmatrix.sync.aligned.m8n8.x4.shared.b16 {%0,%1,%2,%3}, [%4];"
                 : "=r"(r[0]), "=r"(r[1]), "=r"(r[2]), "=r"(r[3]) : "r"(addr));
}

__device__ __forceinline__ void mma16816(float (&d)[4], const uint32_t (&a)[4],
                                         const uint32_t* b) {
    asm volatile(
        "mma.sync.aligned.m16n8k16.row.col.f32.bf16.bf16.f32 "
        "{%0,%1,%2,%3}, {%4,%5,%6,%7}, {%8,%9}, {%0,%1,%2,%3};"
        : "+f"(d[0]), "+f"(d[1]), "+f"(d[2]), "+f"(d[3])
        : "r"(a[0]), "r"(a[1]), "r"(a[2]), "r"(a[3]), "r"(b[0]), "r"(b[1]));
}

__device__ __forceinline__ void cp16(uint32_t dst, const void* src) {
    asm volatile("cp.async.cg.shared.global [%0], [%1], 16;"
                 :: "r"(dst), "l"(src));
}

// ===================== LayerNorm -> bf16 split =====================
__global__ void ln_split_kernel(const float* __restrict__ x,
                                const float* __restrict__ g,
                                const float* __restrict__ b,
                                bf16* __restrict__ oh, bf16* __restrict__ ol) {
    const int row = blockIdx.x;
    const int t = threadIdx.x;
    __shared__ float srow[D_];
    __shared__ float red[256];

    float local = 0.f;
    for (int i = t; i < D_; i += 256) {
        float v = x[(size_t)row * D_ + i];
        srow[i] = v;
        local += v;
    }
    red[t] = local;
    __syncthreads();
    for (int s = 128; s > 0; s >>= 1) { if (t < s) red[t] += red[t + s]; __syncthreads(); }
    const float mean = red[0] * (1.0f / D_);
    __syncthreads();

    local = 0.f;
    for (int i = t; i < D_; i += 256) { float dv = srow[i] - mean; local += dv * dv; }
    red[t] = local;
    __syncthreads();
    for (int s = 128; s > 0; s >>= 1) { if (t < s) red[t] += red[t + s]; __syncthreads(); }
    const float inv = rsqrtf(red[0] * (1.0f / D_) + EPS_);

    for (int i = t; i < D_; i += 256) {
        float v = (srow[i] - mean) * inv * g[i] + b[i];
        bf16 h, l; bsplit(v, h, l);
        oh[(size_t)row * D_ + i] = h;
        ol[(size_t)row * D_ + i] = l;
    }
}

// ===================== split-K(5) reduce + residual + LayerNorm + split =====================
__global__ void reduce5_ln_kernel(const float* __restrict__ p0, const float* __restrict__ p1,
                                  const float* __restrict__ p2, const float* __restrict__ p3,
                                  const float* __restrict__ p4,
                                  const float* __restrict__ bias, float* __restrict__ x,
                                  const float* __restrict__ g, const float* __restrict__ b,
                                  bf16* __restrict__ oh, bf16* __restrict__ ol) {
    const int row = blockIdx.x;
    const int t = threadIdx.x;
    __shared__ float srow[D_];
    __shared__ float red[256];

    float local = 0.f;
    for (int i = t; i < D_; i += 256) {
        const size_t o = (size_t)row * D_ + i;
        float v = x[o] + ((p0[o] + p1[o]) + (p2[o] + p3[o]) + p4[o]) + bias[i];
        x[o] = v;
        srow[i] = v;
        local += v;
    }
    red[t] = local;
    __syncthreads();
    for (int s = 128; s > 0; s >>= 1) { if (t < s) red[t] += red[t + s]; __syncthreads(); }
    const float mean = red[0] * (1.0f / D_);
    __syncthreads();

    local = 0.f;
    for (int i = t; i < D_; i += 256) { float dv = srow[i] - mean; local += dv * dv; }
    red[t] = local;
    __syncthreads();
    for (int s = 128; s > 0; s >>= 1) { if (t < s) red[t] += red[t + s]; __syncthreads(); }
    const float inv = rsqrtf(red[0] * (1.0f / D_) + EPS_);

    for (int i = t; i < D_; i += 256) {
        float v = (srow[i] - mean) * inv * g[i] + b[i];
        bf16 h, l; bsplit(v, h, l);
        oh[(size_t)row * D_ + i] = h;
        ol[(size_t)row * D_ + i] = l;
    }
}

// plain split-K(5) reduce: x += sum + bias (final output)
__global__ void reduce5_kernel(const float* __restrict__ p0, const float* __restrict__ p1,
                               const float* __restrict__ p2, const float* __restrict__ p3,
                               const float* __restrict__ p4,
                               const float* __restrict__ bias, float* __restrict__ x) {
    int i = blockIdx.x * blockDim.x + threadIdx.x;
    if (i >= S_ * D_) return;
    const int c = i % D_;
    x[i] = x[i] + ((p0[i] + p1[i]) + (p2[i] + p3[i]) + p4[i]) + bias[c];
}

// split-K(2) reduce + bias + gelu + bf16 split (fc1 epilogue)
__global__ void reduce2_gelu_kernel(const float* __restrict__ p0, const float* __restrict__ p1,
                                    const float* __restrict__ bias,
                                    bf16* __restrict__ mh, bf16* __restrict__ ml) {
    int i = blockIdx.x * blockDim.x + threadIdx.x;
    if (i >= S_ * I_) return;
    const int c = i % I_;
    float v = p0[i] + p1[i] + bias[c];
    v = 0.5f * v * (1.0f + erff(v * 0.70710678118654752f));
    bf16 h, l; bsplit(v, h, l);
    mh[i] = h; ml[i] = l;
}

// ===================== weight transpose + split: w[K][N] -> Wt[N][K] =====================
__global__ void wsplit_T_kernel(const float* __restrict__ w,
                                bf16* __restrict__ oh, bf16* __restrict__ ol,
                                int K, int N) {
    __shared__ float tile[32][33];
    int k0 = blockIdx.y * 32, n0 = blockIdx.x * 32;
    int tx = threadIdx.x, ty = threadIdx.y;
#pragma unroll
    for (int j = 0; j < 4; j++)
        tile[ty + j * 8][tx] = w[(size_t)(k0 + ty + j * 8) * N + n0 + tx];
    __syncthreads();
#pragma unroll
    for (int j = 0; j < 4; j++) {
        int n = ty + j * 8;
        float v = tile[tx][n];
        bf16 h, l; bsplit(v, h, l);
        size_t o = (size_t)(n0 + n) * K + k0 + tx;
        oh[o] = h; ol[o] = l;
    }
}

// ===================== RoPE + head split + V transpose (incl. zero pad) =====================
__global__ void rope_split_kernel(const float* __restrict__ qkv,
                                  const float* __restrict__ cosp,
                                  const float* __restrict__ sinp,
                                  bf16* __restrict__ Qh, bf16* __restrict__ Ql,
                                  bf16* __restrict__ Kh, bf16* __restrict__ Kl,
                                  bf16* __restrict__ Vth, bf16* __restrict__ Vtl) {
    int i = blockIdx.x * blockDim.x + threadIdx.x;
    if (i >= S_ * H_ * HDP_) return;
    const int s = i / (H_ * HDP_);
    const int r = i % (H_ * HDP_);
    const int h = r / HDP_;
    const int d = r % HDP_;

    const size_t oq = ((size_t)h * S_ + s) * HDP_ + d;
    if (d >= HD_) {
        const bf16 z = __float2bfloat16(0.f);
        Qh[oq] = z; Ql[oq] = z; Kh[oq] = z; Kl[oq] = z;
        return;
    }

    const float c = cosp[s * HD_ + d];
    const float sn = sinp[s * HD_ + d];
    const size_t base = (size_t)s * NQKV_;

    const int d2 = (d < HD_ / 2) ? d + HD_ / 2 : d - HD_ / 2;
    const float sign = (d < HD_ / 2) ? -1.f : 1.f;

    const float q  = qkv[base + h * HD_ + d];
    const float qp = qkv[base + h * HD_ + d2];
    const float k  = qkv[base + D_ + h * HD_ + d];
    const float kp = qkv[base + D_ + h * HD_ + d2];
    const float v  = qkv[base + 2 * D_ + h * HD_ + d];

    const float rq = q * c + sign * qp * sn;
    const float rk = k * c + sign * kp * sn;

    bf16 hh, ll;
    bsplit(rq, hh, ll); Qh[oq] = hh; Ql[oq] = ll;
    bsplit(rk, hh, ll); Kh[oq] = hh; Kl[oq] = ll;
    const size_t ov = ((size_t)h * HD_ + d) * S_ + s;
    bsplit(v, hh, ll);  Vth[ov] = hh; Vtl[ov] = ll;
}

// ===================== fused flash attention =====================
#define FL_PK 208
#define FL_PV 272
#define FL_KT (128 * FL_PK)             // 26624
#define FL_VT (80 * FL_PV)              // 21760
#define FL_STG (2 * FL_KT + 2 * FL_VT)  // 96768
#define FLASH_SMEM (2 * FL_STG)         // 193536

__global__ void __launch_bounds__(256, 1)
flash_kernel(const bf16* __restrict__ Qh_, const bf16* __restrict__ Ql_,
             const bf16* __restrict__ Kh_, const bf16* __restrict__ Kl_,
             const bf16* __restrict__ Vth_, const bf16* __restrict__ Vtl_,
             bf16* __restrict__ Oh_, bf16* __restrict__ Ol_) {
    extern __shared__ __align__(16) char smem[];
    const uint32_t sbase = smem_to_u32(smem);
    const int tid = threadIdx.x;
    const int wid = tid >> 5;
    const int lane = tid & 31;
    const int h = blockIdx.y;
    const int q0 = blockIdx.x * 128;

    const bf16* Qhh = Qh_ + ((size_t)h * S_ + q0) * HDP_;
    const bf16* Qll = Ql_ + ((size_t)h * S_ + q0) * HDP_;
    const bf16* Khh = Kh_ + (size_t)h * S_ * HDP_;
    const bf16* Kll = Kl_ + (size_t)h * S_ * HDP_;
    const bf16* Vhh = Vth_ + (size_t)h * HD_ * S_;
    const bf16* Vll = Vtl_ + (size_t)h * HD_ * S_;

#pragma unroll
    for (int it = 0; it < 12; it++) {
        int e = it * 256 + tid;
        int split = e >= 1536;
        int idx = split ? e - 1536 : e;
        int row = idx / 12, c = idx % 12;
        const bf16* src = (split ? Qll : Qhh) + (size_t)row * HDP_ + c * 8;
        cp16(sbase + (uint32_t)split * FL_KT + (uint32_t)(row * FL_PK + c * 16), src);
    }
    asm volatile("cp.async.commit_group;" ::: "memory");
    asm volatile("cp.async.wait_group 0;" ::: "memory");
    __syncthreads();

    const uint32_t a_off = (uint32_t)((lane & 15) * FL_PK + (lane >> 4) * 16);
    uint32_t qfh[6][4], qfl[6][4];
#pragma unroll
    for (int ks = 0; ks < 6; ks++) {
        uint32_t ad = sbase + (uint32_t)(wid * 16 * FL_PK + ks * 32) + a_off;
        ldsm4(qfh[ks], ad);
        ldsm4(qfl[ks], ad + FL_KT);
    }
    __syncthreads();

    auto load_kv = [&](int t, int stg) {
        const int k0 = t * 128;
        const uint32_t db = sbase + (uint32_t)stg * FL_STG;
#pragma unroll
        for (int it = 0; it < 12; it++) {
            int e = it * 256 + tid;
            int split = e >= 1536;
            int idx = split ? e - 1536 : e;
            int row = idx / 12, c = idx % 12;
            const bf16* src = (split ? Kll : Khh) + (size_t)(k0 + row) * HDP_ + c * 8;
            cp16(db + (uint32_t)split * FL_KT + (uint32_t)(row * FL_PK + c * 16), src);
        }
#pragma unroll
        for (int it = 0; it < 10; it++) {
            int e = it * 256 + tid;
            int split = e >= 1280;
            int idx = split ? e - 1280 : e;
            int row = idx / 16, c = idx % 16;
            const bf16* src = (split ? Vll : Vhh) + (size_t)row * S_ + k0 + c * 8;
            cp16(db + 2 * FL_KT + (uint32_t)split * FL_VT + (uint32_t)(row * FL_PV + c * 16), src);
        }
    };

    const uint32_t bk_off = (uint32_t)((((lane & 7) | ((lane >> 4) << 3)) * FL_PK) +
                                       (((lane >> 3) & 1) * 16));
    const uint32_t bv_off = (uint32_t)((((lane & 7) | ((lane >> 4) << 3)) * FL_PV) +
                                       (((lane >> 3) & 1) * 16));

    float acc_o[10][4];
#pragma unroll
    for (int i = 0; i < 10; i++)
#pragma unroll
        for (int c = 0; c < 4; c++) acc_o[i][c] = 0.f;
    float m0 = -1e30f, m1 = -1e30f, sum0 = 0.f, sum1 = 0.f;
    const float SC2 = SCALE_ * 1.4426950408889634f;

    const int NT = S_ / 128;
    load_kv(0, 0);
    asm volatile("cp.async.commit_group;" ::: "memory");

    for (int t = 0; t < NT; t++) {
        const int buf = t & 1;
        if (t + 1 < NT) {
            load_kv(t + 1, buf ^ 1);
            asm volatile("cp.async.commit_group;" ::: "memory");
            asm volatile("cp.async.wait_group 1;" ::: "memory");
        } else {
            asm volatile("cp.async.wait_group 0;" ::: "memory");
        }
        __syncthreads();

        const uint32_t kb = sbase + (uint32_t)buf * FL_STG;
        const uint32_t vb = kb + 2 * FL_KT;

        float accs[16][4];
#pragma unroll
        for (int i = 0; i < 16; i++)
#pragma unroll
            for (int c = 0; c < 4; c++) accs[i][c] = 0.f;

#pragma unroll
        for (int ks = 0; ks < 6; ks++) {
#pragma unroll
            for (int nb = 0; nb < 8; nb++) {
                uint32_t kh[4], kl[4];
                uint32_t kd = kb + (uint32_t)(nb * 16 * FL_PK + ks * 32) + bk_off;
                ldsm4(kh, kd);
                ldsm4(kl, kd + FL_KT);
#pragma unroll
                for (int j = 0; j < 2; j++) {
                    mma16816(accs[nb * 2 + j], qfh[ks], &kh[j * 2]);
                    mma16816(accs[nb * 2 + j], qfh[ks], &kl[j * 2]);
                    mma16816(accs[nb * 2 + j], qfl[ks], &kh[j * 2]);
                }
            }
        }

        float tm0 = -1e30f, tm1 = -1e30f;
#pragma unroll
        for (int nj = 0; nj < 16; nj++) {
            tm0 = fmaxf(tm0, fmaxf(accs[nj][0], accs[nj][1]));
            tm1 = fmaxf(tm1, fmaxf(accs[nj][2], accs[nj][3]));
        }
        tm0 = fmaxf(tm0, __shfl_xor_sync(0xffffffff, tm0, 1));
        tm0 = fmaxf(tm0, __shfl_xor_sync(0xffffffff, tm0, 2));
        tm1 = fmaxf(tm1, __shfl_xor_sync(0xffffffff, tm1, 1));
        tm1 = fmaxf(tm1, __shfl_xor_sync(0xffffffff, tm1, 2));
        tm0 *= SC2; tm1 *= SC2;

        const float nm0 = fmaxf(m0, tm0), nm1 = fmaxf(m1, tm1);
        const float f0 = exp2f(m0 - nm0), f1 = exp2f(m1 - nm1);
        m0 = nm0; m1 = nm1;

        float rs0 = 0.f, rs1 = 0.f;
#pragma unroll
        for (int nj = 0; nj < 16; nj++) {
            accs[nj][0] = exp2f(fmaf(accs[nj][0], SC2, -m0));
            accs[nj][1] = exp2f(fmaf(accs[nj][1], SC2, -m0));
            accs[nj][2] = exp2f(fmaf(accs[nj][2], SC2, -m1));
            accs[nj][3] = exp2f(fmaf(accs[nj][3], SC2, -m1));
            rs0 += accs[nj][0] + accs[nj][1];
            rs1 += accs[nj][2] + accs[nj][3];
        }
        rs0 += __shfl_xor_sync(0xffffffff, rs0, 1);
        rs0 += __shfl_xor_sync(0xffffffff, rs0, 2);
        rs1 += __shfl_xor_sync(0xffffffff, rs1, 1);
        rs1 += __shfl_xor_sync(0xffffffff, rs1, 2);
        sum0 = sum0 * f0 + rs0;
        sum1 = sum1 * f1 + rs1;

#pragma unroll
        for (int i = 0; i < 10; i++) {
            acc_o[i][0] *= f0; acc_o[i][1] *= f0;
            acc_o[i][2] *= f1; acc_o[i][3] *= f1;
        }

#pragma unroll
        for (int kbk = 0; kbk < 8; kbk++) {
            uint32_t ah[4], al[4];
            {
                const float* p0 = accs[kbk * 2];
                const float* p1 = accs[kbk * 2 + 1];
                float r00 = p0[0] - __bfloat162float(__float2bfloat16(p0[0]));
                float r01 = p0[1] - __bfloat162float(__float2bfloat16(p0[1]));
                float r02 = p0[2] - __bfloat162float(__float2bfloat16(p0[2]));
                float r03 = p0[3] - __bfloat162float(__float2bfloat16(p0[3]));
                float r10 = p1[0] - __bfloat162float(__float2bfloat16(p1[0]));
                float r11 = p1[1] - __bfloat162float(__float2bfloat16(p1[1]));
                float r12 = p1[2] - __bfloat162float(__float2bfloat16(p1[2]));
                float r13 = p1[3] - __bfloat162float(__float2bfloat16(p1[3]));
                ah[0] = packbf(p0[0], p0[1]); ah[1] = packbf(p0[2], p0[3]);
                ah[2] = packbf(p1[0], p1[1]); ah[3] = packbf(p1[2], p1[3]);
                al[0] = packbf(r00, r01);     al[1] = packbf(r02, r03);
                al[2] = packbf(r10, r11);     al[3] = packbf(r12, r13);
            }
#pragma unroll
            for (int db = 0; db < 5; db++) {
                uint32_t vh[4], vl[4];
                uint32_t vd = vb + (uint32_t)(db * 16 * FL_PV + kbk * 32) + bv_off;
                ldsm4(vh, vd);
                ldsm4(vl, vd + FL_VT);
#pragma unroll
                for (int j = 0; j < 2; j++) {
                    mma16816(acc_o[db * 2 + j], ah, &vh[j * 2]);
                    mma16816(acc_o[db * 2 + j], ah, &vl[j * 2]);
                    mma16816(acc_o[db * 2 + j], al, &vh[j * 2]);
                }
            }
        }
        __syncthreads();
    }

    const int gid = lane >> 2, tig = lane & 3;
    const float inv0 = 1.0f / sum0, inv1 = 1.0f / sum1;
    const int r0 = q0 + wid * 16 + gid;
    const int r1 = r0 + 8;
#pragma unroll
    for (int db = 0; db < 10; db++) {
        const int col = h * HD_ + db * 8 + tig * 2;
        bf16 hh, ll;
        size_t o0 = (size_t)r0 * D_ + col;
        size_t o1 = (size_t)r1 * D_ + col;
        bsplit(acc_o[db][0] * inv0, hh, ll); Oh_[o0] = hh; Ol_[o0] = ll;
        bsplit(acc_o[db][1] * inv0, hh, ll); Oh_[o0 + 1] = hh; Ol_[o0 + 1] = ll;
        bsplit(acc_o[db][2] * inv1, hh, ll); Oh_[o1] = hh; Ol_[o1] = ll;
        bsplit(acc_o[db][3] * inv1, hh, ll); Oh_[o1 + 1] = hh; Ol_[o1 + 1] = ll;
    }
}

// ===================== 128x256 bf16x3 GEMM, 512 threads, 3-stage =====================
// C[M, N] = alpha * A[M,K] @ B[N,K]^T
// EPI: 0 = C=v+bias   5 = split-K partial store (z = K-slice via sA/sB elems, C slab via sC)
#define A_T 10240
#define B_T 20480
#define STAGE_B (2 * A_T + 2 * B_T)
#define GEMM2_SMEM (3 * STAGE_B)

template <int EPI>
__global__ void __launch_bounds__(512, 1)
gemm_mma2(const bf16* __restrict__ Agh, const bf16* __restrict__ Agl,
          const bf16* __restrict__ Bgh, const bf16* __restrict__ Bgl,
          const float* __restrict__ bias,
          float* __restrict__ C,
          int K, int lda, int ldb, int ldc,
          long long sA, long long sB, long long sC, float alpha) {
    extern __shared__ __align__(16) char smem[];
    const uint32_t sbase = smem_to_u32(smem);
    const int tid = threadIdx.x;
    const int wid = tid >> 5;
    const int lane = tid & 31;
    const int warp_m = wid & 3;
    const int warp_n = wid >> 2;
    const int bz = blockIdx.z;

    Agh += (size_t)bz * sA; Agl += (size_t)bz * sA;
    Bgh += (size_t)bz * sB; Bgl += (size_t)bz * sB;
    const size_t coff = (size_t)bz * sC;
    const int row0 = blockIdx.y * 128;
    const int col0 = blockIdx.x * 256;

    const uint32_t a_off = (uint32_t)(((lane & 15) * 40 + (lane >> 4) * 8) * 2);
    const uint32_t b_off = (uint32_t)(((((lane & 7) | ((lane >> 4) << 3)) * 40) +
                                      (((lane >> 3) & 1) * 8) ) * 2);

    auto load_chunk = [&](int kc, int stg) {
        const int k0 = kc << 5;
        const uint32_t dbase = sbase + (uint32_t)stg * STAGE_B;
#pragma unroll
        for (int it = 0; it < 2; it++) {
            int e = it * 512 + tid;
            int t = e >> 9;
            int idx = e & 511;
            int row = idx >> 2, c8 = idx & 3;
            const bf16* src = (t ? Agl : Agh) + (size_t)(row0 + row) * lda + k0 + c8 * 8;
            uint32_t dst = dbase + (uint32_t)t * A_T + (uint32_t)(row * 80 + c8 * 16);
            cp16(dst, src);
        }
#pragma unroll
        for (int it = 0; it < 4; it++) {
            int e = it * 512 + tid;
            int t = e >> 10;
            int idx = e & 1023;
            int row = idx >> 2, c8 = idx & 3;
            const bf16* src = (t ? Bgl : Bgh) + (size_t)(col0 + row) * ldb + k0 + c8 * 8;
            uint32_t dst = dbase + 2 * A_T + (uint32_t)t * B_T + (uint32_t)(row * 80 + c8 * 16);
            cp16(dst, src);
        }
    };

    float acc[2][8][4];
#pragma unroll
    for (int mi = 0; mi < 2; mi++)
#pragma unroll
        for (int nj = 0; nj < 8; nj++)
#pragma unroll
            for (int c = 0; c < 4; c++) acc[mi][nj][c] = 0.f;

    const int NC = K >> 5;
    load_chunk(0, 0);
    asm volatile("cp.async.commit_group;" ::: "memory");
    if (1 < NC) load_chunk(1, 1);
    asm volatile("cp.async.commit_group;" ::: "memory");

    int stg = 0;
    for (int kc = 0; kc < NC; kc++) {
        asm volatile("cp.async.wait_group 1;" ::: "memory");
        __syncthreads();
        if (kc + 2 < NC) load_chunk(kc + 2, (stg + 2 >= 3) ? stg - 1 : stg + 2);
        asm volatile("cp.async.commit_group;" ::: "memory");

        const uint32_t cbase = sbase + (uint32_t)stg * STAGE_B;
#pragma unroll
        for (int ks = 0; ks < 2; ks++) {
            uint32_t ah[2][4], al[2][4];
#pragma unroll
            for (int mi = 0; mi < 2; mi++) {
                uint32_t ad = cbase + (uint32_t)((warp_m * 32 + mi * 16) * 80 + ks * 32) + a_off;
                ldsm4(ah[mi], ad);
                ldsm4(al[mi], ad + A_T);
            }
#pragma unroll
            for (int ni = 0; ni < 4; ni++) {
                uint32_t bh[4], bl[4];
                uint32_t bd = cbase + 2 * A_T +
                              (uint32_t)((warp_n * 64 + ni * 16) * 80 + ks * 32) + b_off;
                ldsm4(bh, bd);
                ldsm4(bl, bd + B_T);
#pragma unroll
                for (int mi = 0; mi < 2; mi++)
#pragma unroll
                    for (int j = 0; j < 2; j++) {
                        const int nj = ni * 2 + j;
                        mma16816(acc[mi][nj], ah[mi], &bh[j * 2]);
                        mma16816(acc[mi][nj], ah[mi], &bl[j * 2]);
                        mma16816(acc[mi][nj], al[mi], &bh[j * 2]);
                    }
            }
        }
        __syncthreads();
        stg = (stg + 1 >= 3) ? 0 : stg + 1;
    }

    const int gid = lane >> 2, tig = lane & 3;
#pragma unroll
    for (int mi = 0; mi < 2; mi++) {
#pragma unroll
        for (int hh = 0; hh < 2; hh++) {
            const int r = row0 + warp_m * 32 + mi * 16 + gid + hh * 8;
#pragma unroll
            for (int nj = 0; nj < 8; nj++) {
                const int c = col0 + warp_n * 64 + nj * 8 + tig * 2;
                float v0 = acc[mi][nj][hh * 2 + 0] * alpha;
                float v1 = acc[mi][nj][hh * 2 + 1] * alpha;
                const size_t o = coff + (size_t)r * ldc + c;
                if (EPI == 0) {
                    C[o] = v0 + bias[c];
                    C[o + 1] = v1 + bias[c + 1];
                } else {
                    C[o] = v0;
                    C[o + 1] = v1;
                }
            }
        }
    }
}

// ===================== host-side launch =====================
extern "C" void kernel_launch(void* const* d_in, const int* in_sizes, int n_in,
                              void* d_out, int out_size) {
    const float* hidden = (const float*)d_in[0];
    const float* cosp   = (const float*)d_in[1];
    const float* sinp   = (const float*)d_in[2];
    const float* qkv_w  = (const float*)d_in[3];
    const float* qkv_b  = (const float*)d_in[4];
    const float* proj_w = (const float*)d_in[5];
    const float* proj_b = (const float*)d_in[6];
    const float* ln1_g  = (const float*)d_in[7];
    const float* ln1_b  = (const float*)d_in[8];
    const float* ln2_g  = (const float*)d_in[9];
    const float* ln2_b  = (const float*)d_in[10];
    const float* fc1_w  = (const float*)d_in[11];
    const float* fc1_b  = (const float*)d_in[12];
    const float* fc2_w  = (const float*)d_in[13];
    const float* fc2_b  = (const float*)d_in[14];

    float* x = (float*)d_out;

    float *p_qkv, *p_part, *p_part1;
    bf16 *p_hh, *p_hl, *p_qh, *p_ql, *p_kh, *p_kl, *p_vth, *p_vtl;
    bf16 *p_ah, *p_al, *p_mh, *p_ml;
    bf16 *wqh, *wql, *wph, *wpl, *w1h, *w1l, *w2h, *w2l;
    cudaGetSymbolAddress((void**)&p_qkv, g_qkv);
    cudaGetSymbolAddress((void**)&p_part, g_part);
    cudaGetSymbolAddress((void**)&p_part1, g_part1);
    cudaGetSymbolAddress((void**)&p_hh,  g_hh);   cudaGetSymbolAddress((void**)&p_hl, g_hl);
    cudaGetSymbolAddress((void**)&p_qh,  g_qh);   cudaGetSymbolAddress((void**)&p_ql, g_ql);
    cudaGetSymbolAddress((void**)&p_kh,  g_kh);   cudaGetSymbolAddress((void**)&p_kl, g_kl);
    cudaGetSymbolAddress((void**)&p_vth, g_vth);  cudaGetSymbolAddress((void**)&p_vtl, g_vtl);
    cudaGetSymbolAddress((void**)&p_ah,  g_ah);   cudaGetSymbolAddress((void**)&p_al, g_al);
    cudaGetSymbolAddress((void**)&p_mh,  g_mh);   cudaGetSymbolAddress((void**)&p_ml, g_ml);
    cudaGetSymbolAddress((void**)&wqh, g_wqh);    cudaGetSymbolAddress((void**)&wql, g_wql);
    cudaGetSymbolAddress((void**)&wph, g_wph);    cudaGetSymbolAddress((void**)&wpl, g_wpl);
    cudaGetSymbolAddress((void**)&w1h, g_w1h);    cudaGetSymbolAddress((void**)&w1l, g_w1l);
    cudaGetSymbolAddress((void**)&w2h, g_w2h);    cudaGetSymbolAddress((void**)&w2l, g_w2l);

    float* pt[5] = {p_part, p_part + S_ * D_, p_part + 2 * (size_t)S_ * D_,
                    p_part + 3 * (size_t)S_ * D_, p_part + 4 * (size_t)S_ * D_};
    float* pt1[2] = {p_part1, p_part1 + (size_t)S_ * I_};

    cudaFuncSetAttribute((const void*)gemm_mma2<0>, cudaFuncAttributeMaxDynamicSharedMemorySize, GEMM2_SMEM);
    cudaFuncSetAttribute((const void*)gemm_mma2<5>, cudaFuncAttributeMaxDynamicSharedMemorySize, GEMM2_SMEM);
    cudaFuncSetAttribute((const void*)flash_kernel,  cudaFuncAttributeMaxDynamicSharedMemorySize, FLASH_SMEM);

    cudaMemcpyAsync(x, hidden, (size_t)S_ * D_ * sizeof(float), cudaMemcpyDeviceToDevice);

    for (int l = 0; l < 2; l++) {
        const float* qw = qkv_w + (size_t)l * D_ * NQKV_;
        const float* qb = qkv_b + (size_t)l * NQKV_;
        const float* pw = proj_w + (size_t)l * D_ * D_;
        const float* pb = proj_b + (size_t)l * D_;
        const float* g1 = ln1_g + (size_t)l * D_;
        const float* b1 = ln1_b + (size_t)l * D_;
        const float* g2 = ln2_g + (size_t)l * D_;
        const float* b2 = ln2_b + (size_t)l * D_;
        const float* f1w = fc1_w + (size_t)l * D_ * I_;
        const float* f1b = fc1_b + (size_t)l * I_;
        const float* f2w = fc2_w + (size_t)l * I_ * D_;
        const float* f2b = fc2_b + (size_t)l * D_;

        // LN1: layer 0 standalone (layer 1's LN1 is fused into layer 0's fc2 reduce)
        if (l == 0)
            ln_split_kernel<<<S_, 256>>>(x, g1, b1, p_hh, p_hl);

        // wsq, wsp before qkv so the ncu-captured launch (#4 global ≅ our #4) is the qkv GEMM
        wsplit_T_kernel<<<dim3(NQKV_ / 32, D_ / 32), dim3(32, 8)>>>(qw, wqh, wql, D_, NQKV_);
        wsplit_T_kernel<<<dim3(D_ / 32, D_ / 32), dim3(32, 8)>>>(pw, wph, wpl, D_, D_);

        // qkv = h @ W_qkv + b   (fp32 out)
        gemm_mma2<0><<<dim3(NQKV_ / 256, S_ / 128, 1), 512, GEMM2_SMEM>>>(
            p_hh, p_hl, wqh, wql, qb, p_qkv,
            D_, D_, D_, NQKV_, 0, 0, 0, 1.f);

        // RoPE + split + V^T (+zero pad)
        rope_split_kernel<<<(S_ * H_ * HDP_ + 255) / 256, 256>>>(
            p_qkv, cosp, sinp, p_qh, p_ql, p_kh, p_kl, p_vth, p_vtl);

        // fused flash attention -> attn out split in [S, D]
        flash_kernel<<<dim3(S_ / 128, H_), 256, FLASH_SMEM>>>(
            p_qh, p_ql, p_kh, p_kl, p_vth, p_vtl, p_ah, p_al);

        // proj: split-K=5 (K=1280 -> 256 each, 400 CTAs), then fused reduce+LN2
        gemm_mma2<5><<<dim3(D_ / 256, S_ / 128, 5), 512, GEMM2_SMEM>>>(
            p_ah, p_al, wph, wpl, nullptr, pt[0],
            D_ / 5, D_, D_, D_, D_ / 5, D_ / 5, (long long)S_ * D_, 1.f);
        reduce5_ln_kernel<<<S_, 256>>>(pt[0], pt[1], pt[2], pt[3], pt[4],
                                       pb, x, g2, b2, p_hh, p_hl);

        // fc1: split-K=2 (K=1280 -> 640 each, 640 CTAs), then reduce+bias+gelu+split
        wsplit_T_kernel<<<dim3(I_ / 32, D_ / 32), dim3(32, 8)>>>(f1w, w1h, w1l, D_, I_);
        gemm_mma2<5><<<dim3(I_ / 256, S_ / 128, 2), 512, GEMM2_SMEM>>>(
            p_hh, p_hl, w1h, w1l, nullptr, pt1[0],
            D_ / 2, D_, D_, I_, D_ / 2, D_ / 2, (long long)S_ * I_, 1.f);
        reduce2_gelu_kernel<<<(S_ * I_ + 255) / 256, 256>>>(pt1[0], pt1[1], f1b, p_mh, p_ml);

        // fc2: split-K=5 (K=5120 -> 1024 each, 400 CTAs)
        wsplit_T_kernel<<<dim3(D_ / 32, I_ / 32), dim3(32, 8)>>>(f2w, w2h, w2l, I_, D_);
        gemm_mma2<5><<<dim3(D_ / 256, S_ / 128, 5), 512, GEMM2_SMEM>>>(
            p_mh, p_ml, w2h, w2l, nullptr, pt[0],
            I_ / 5, I_, I_, D_, I_ / 5, I_ / 5, (long long)S_ * D_, 1.f);
        if (l == 0) {
            // fused: x += fc2 + bias, then LN1 of layer 1
            reduce5_ln_kernel<<<S_, 256>>>(pt[0], pt[1], pt[2], pt[3], pt[4],
                                           f2b, x, ln1_g + D_, ln1_b + D_, p_hh, p_hl);
        } else {
            reduce5_kernel<<<(S_ * D_ + 255) / 256, 256>>>(pt[0], pt[1], pt[2], pt[3], pt[4],
                                                           f2b, x);
        }
    }
}

// round 14
// speedup vs baseline: 1.4113x; 1.0100x over previous
#include <cuda_runtime.h>
#include <cuda_bf16.h>
#include <math.h>
#include <stdint.h>

// Problem constants
#define S_ 2048
#define D_ 1280
#define H_ 16
#define HD_ 80
#define HDP_ 96           // padded head dim (3 chunks of 32)
#define I_ 5120
#define NQKV_ 3840
#define EPS_ 1e-6f
#define SCALE_ 0.11180339887498949f  // 80^-0.5

typedef __nv_bfloat16 bf16;

// ===================== device scratch (no allocation allowed) =====================
__device__ float g_qkv[S_ * NQKV_];                  // qkv proj fp32
__device__ float g_part[5][S_ * D_];                 // split-K partials (52 MB)
__device__ float g_part1[2][S_ * I_];                // fc1 split-K partials (84 MB)
__device__ bf16  g_hh[S_ * D_],  g_hl[S_ * D_];      // LN out split
__device__ bf16  g_qh[H_ * S_ * HDP_], g_ql[H_ * S_ * HDP_];
__device__ bf16  g_kh[H_ * S_ * HDP_], g_kl[H_ * S_ * HDP_];
__device__ bf16  g_vth[H_ * HD_ * S_], g_vtl[H_ * HD_ * S_];   // V^T per head
__device__ bf16  g_ah[S_ * D_],  g_al[S_ * D_];      // attn out split
__device__ bf16  g_mh[S_ * I_],  g_ml[S_ * I_];      // mlp hidden split
__device__ bf16  g_wqh[NQKV_ * D_], g_wql[NQKV_ * D_];
__device__ bf16  g_wph[D_ * D_],    g_wpl[D_ * D_];
__device__ bf16  g_w1h[I_ * D_],    g_w1l[I_ * D_];
__device__ bf16  g_w2h[D_ * I_],    g_w2l[D_ * I_];

__device__ __forceinline__ void bsplit(float v, bf16& h, bf16& l) {
    h = __float2bfloat16(v);
    l = __float2bfloat16(v - __bfloat162float(h));
}

__device__ __forceinline__ uint32_t packbf(float a, float b) {
    __nv_bfloat162 t = __floats2bfloat162_rn(a, b);
    return *reinterpret_cast<uint32_t*>(&t);
}

__device__ __forceinline__ uint32_t smem_to_u32(const void* smem_ptr) {
    uint32_t addr;
    asm("{ .reg .u64 tmp; cvta.to.shared.u64 tmp, %1; cvt.u32.u64 %0, tmp; }"
        : "=r"(addr) : "l"(smem_ptr));
    return addr;
}

__device__ __forceinline__ void ldsm4(uint32_t (&r)[4], uint32_t addr) {
    asm volatile("ldmatrix.sync.aligned.m8n8.x4.shared.b16 {%0,%1,%2,%3}, [%4];"
                 : "=r"(r[0]), "=r"(r[1]), "=r"(r[2]), "=r"(r[3]) : "r"(addr));
}

__device__ __forceinline__ void mma16816(float (&d)[4], const uint32_t (&a)[4],
                                         const uint32_t* b) {
    asm volatile(
        "mma.sync.aligned.m16n8k16.row.col.f32.bf16.bf16.f32 "
        "{%0,%1,%2,%3}, {%4,%5,%6,%7}, {%8,%9}, {%0,%1,%2,%3};"
        : "+f"(d[0]), "+f"(d[1]), "+f"(d[2]), "+f"(d[3])
        : "r"(a[0]), "r"(a[1]), "r"(a[2]), "r"(a[3]), "r"(b[0]), "r"(b[1]));
}

__device__ __forceinline__ void cp16(uint32_t dst, const void* src) {
    asm volatile("cp.async.cg.shared.global [%0], [%1], 16;"
                 :: "r"(dst), "l"(src));
}

// ===================== LayerNorm -> bf16 split =====================
__global__ void ln_split_kernel(const float* __restrict__ x,
                                const float* __restrict__ g,
                                const float* __restrict__ b,
                                bf16* __restrict__ oh, bf16* __restrict__ ol) {
    const int row = blockIdx.x;
    const int t = threadIdx.x;
    __shared__ float srow[D_];
    __shared__ float red[256];

    float local = 0.f;
    for (int i = t; i < D_; i += 256) {
        float v = x[(size_t)row * D_ + i];
        srow[i] = v;
        local += v;
    }
    red[t] = local;
    __syncthreads();
    for (int s = 128; s > 0; s >>= 1) { if (t < s) red[t] += red[t + s]; __syncthreads(); }
    const float mean = red[0] * (1.0f / D_);
    __syncthreads();

    local = 0.f;
    for (int i = t; i < D_; i += 256) { float dv = srow[i] - mean; local += dv * dv; }
    red[t] = local;
    __syncthreads();
    for (int s = 128; s > 0; s >>= 1) { if (t < s) red[t] += red[t + s]; __syncthreads(); }
    const float inv = rsqrtf(red[0] * (1.0f / D_) + EPS_);

    for (int i = t; i < D_; i += 256) {
        float v = (srow[i] - mean) * inv * g[i] + b[i];
        bf16 h, l; bsplit(v, h, l);
        oh[(size_t)row * D_ + i] = h;
        ol[(size_t)row * D_ + i] = l;
    }
}

// ===================== split-K(5) reduce + residual + LayerNorm + split =====================
__global__ void reduce5_ln_kernel(const float* __restrict__ p0, const float* __restrict__ p1,
                                  const float* __restrict__ p2, const float* __restrict__ p3,
                                  const float* __restrict__ p4,
                                  const float* __restrict__ bias, float* __restrict__ x,
                                  const float* __restrict__ g, const float* __restrict__ b,
                                  bf16* __restrict__ oh, bf16* __restrict__ ol) {
    const int row = blockIdx.x;
    const int t = threadIdx.x;
    __shared__ float srow[D_];
    __shared__ float red[256];

    float local = 0.f;
    for (int i = t; i < D_; i += 256) {
        const size_t o = (size_t)row * D_ + i;
        float v = x[o] + ((p0[o] + p1[o]) + (p2[o] + p3[o]) + p4[o]) + bias[i];
        x[o] = v;
        srow[i] = v;
        local += v;
    }
    red[t] = local;
    __syncthreads();
    for (int s = 128; s > 0; s >>= 1) { if (t < s) red[t] += red[t + s]; __syncthreads(); }
    const float mean = red[0] * (1.0f / D_);
    __syncthreads();

    local = 0.f;
    for (int i = t; i < D_; i += 256) { float dv = srow[i] - mean; local += dv * dv; }
    red[t] = local;
    __syncthreads();
    for (int s = 128; s > 0; s >>= 1) { if (t < s) red[t] += red[t + s]; __syncthreads(); }
    const float inv = rsqrtf(red[0] * (1.0f / D_) + EPS_);

    for (int i = t; i < D_; i += 256) {
        float v = (srow[i] - mean) * inv * g[i] + b[i];
        bf16 h, l; bsplit(v, h, l);
        oh[(size_t)row * D_ + i] = h;
        ol[(size_t)row * D_ + i] = l;
    }
}

// plain split-K(5) reduce: x += sum + bias (final output)
__global__ void reduce5_kernel(const float* __restrict__ p0, const float* __restrict__ p1,
                               const float* __restrict__ p2, const float* __restrict__ p3,
                               const float* __restrict__ p4,
                               const float* __restrict__ bias, float* __restrict__ x) {
    int i = blockIdx.x * blockDim.x + threadIdx.x;
    if (i >= S_ * D_) return;
    const int c = i % D_;
    x[i] = x[i] + ((p0[i] + p1[i]) + (p2[i] + p3[i]) + p4[i]) + bias[c];
}

// split-K(2) reduce + bias + gelu + bf16 split (fc1 epilogue)
__global__ void reduce2_gelu_kernel(const float* __restrict__ p0, const float* __restrict__ p1,
                                    const float* __restrict__ bias,
                                    bf16* __restrict__ mh, bf16* __restrict__ ml) {
    int i = blockIdx.x * blockDim.x + threadIdx.x;
    if (i >= S_ * I_) return;
    const int c = i % I_;
    float v = p0[i] + p1[i] + bias[c];
    v = 0.5f * v * (1.0f + erff(v * 0.70710678118654752f));
    bf16 h, l; bsplit(v, h, l);
    mh[i] = h; ml[i] = l;
}

// ===================== weight transpose + split: w[K][N] -> Wt[N][K] =====================
__global__ void wsplit_T_kernel(const float* __restrict__ w,
                                bf16* __restrict__ oh, bf16* __restrict__ ol,
                                int K, int N) {
    __shared__ float tile[32][33];
    int k0 = blockIdx.y * 32, n0 = blockIdx.x * 32;
    int tx = threadIdx.x, ty = threadIdx.y;
#pragma unroll
    for (int j = 0; j < 4; j++)
        tile[ty + j * 8][tx] = w[(size_t)(k0 + ty + j * 8) * N + n0 + tx];
    __syncthreads();
#pragma unroll
    for (int j = 0; j < 4; j++) {
        int n = ty + j * 8;
        float v = tile[tx][n];
        bf16 h, l; bsplit(v, h, l);
        size_t o = (size_t)(n0 + n) * K + k0 + tx;
        oh[o] = h; ol[o] = l;
    }
}

// ===================== RoPE + head split + V transpose (incl. zero pad) =====================
__global__ void rope_split_kernel(const float* __restrict__ qkv,
                                  const float* __restrict__ cosp,
                                  const float* __restrict__ sinp,
                                  bf16* __restrict__ Qh, bf16* __restrict__ Ql,
                                  bf16* __restrict__ Kh, bf16* __restrict__ Kl,
                                  bf16* __restrict__ Vth, bf16* __restrict__ Vtl) {
    int i = blockIdx.x * blockDim.x + threadIdx.x;
    if (i >= S_ * H_ * HDP_) return;
    const int s = i / (H_ * HDP_);
    const int r = i % (H_ * HDP_);
    const int h = r / HDP_;
    const int d = r % HDP_;

    const size_t oq = ((size_t)h * S_ + s) * HDP_ + d;
    if (d >= HD_) {
        const bf16 z = __float2bfloat16(0.f);
        Qh[oq] = z; Ql[oq] = z; Kh[oq] = z; Kl[oq] = z;
        return;
    }

    const float c = cosp[s * HD_ + d];
    const float sn = sinp[s * HD_ + d];
    const size_t base = (size_t)s * NQKV_;

    const int d2 = (d < HD_ / 2) ? d + HD_ / 2 : d - HD_ / 2;
    const float sign = (d < HD_ / 2) ? -1.f : 1.f;

    const float q  = qkv[base + h * HD_ + d];
    const float qp = qkv[base + h * HD_ + d2];
    const float k  = qkv[base + D_ + h * HD_ + d];
    const float kp = qkv[base + D_ + h * HD_ + d2];
    const float v  = qkv[base + 2 * D_ + h * HD_ + d];

    const float rq = q * c + sign * qp * sn;
    const float rk = k * c + sign * kp * sn;

    bf16 hh, ll;
    bsplit(rq, hh, ll); Qh[oq] = hh; Ql[oq] = ll;
    bsplit(rk, hh, ll); Kh[oq] = hh; Kl[oq] = ll;
    const size_t ov = ((size_t)h * HD_ + d) * S_ + s;
    bsplit(v, hh, ll);  Vth[ov] = hh; Vtl[ov] = ll;
}

// ===================== fused flash attention =====================
#define FL_PK 208
#define FL_PV 272
#define FL_KT (128 * FL_PK)             // 26624
#define FL_VT (80 * FL_PV)              // 21760
#define FL_STG (2 * FL_KT + 2 * FL_VT)  // 96768
#define FLASH_SMEM (2 * FL_STG)         // 193536

__global__ void __launch_bounds__(256, 1)
flash_kernel(const bf16* __restrict__ Qh_, const bf16* __restrict__ Ql_,
             const bf16* __restrict__ Kh_, const bf16* __restrict__ Kl_,
             const bf16* __restrict__ Vth_, const bf16* __restrict__ Vtl_,
             bf16* __restrict__ Oh_, bf16* __restrict__ Ol_) {
    extern __shared__ __align__(16) char smem[];
    const uint32_t sbase = smem_to_u32(smem);
    const int tid = threadIdx.x;
    const int wid = tid >> 5;
    const int lane = tid & 31;
    const int h = blockIdx.y;
    const int q0 = blockIdx.x * 128;

    const bf16* Qhh = Qh_ + ((size_t)h * S_ + q0) * HDP_;
    const bf16* Qll = Ql_ + ((size_t)h * S_ + q0) * HDP_;
    const bf16* Khh = Kh_ + (size_t)h * S_ * HDP_;
    const bf16* Kll = Kl_ + (size_t)h * S_ * HDP_;
    const bf16* Vhh = Vth_ + (size_t)h * HD_ * S_;
    const bf16* Vll = Vtl_ + (size_t)h * HD_ * S_;

#pragma unroll
    for (int it = 0; it < 12; it++) {
        int e = it * 256 + tid;
        int split = e >= 1536;
        int idx = split ? e - 1536 : e;
        int row = idx / 12, c = idx % 12;
        const bf16* src = (split ? Qll : Qhh) + (size_t)row * HDP_ + c * 8;
        cp16(sbase + (uint32_t)split * FL_KT + (uint32_t)(row * FL_PK + c * 16), src);
    }
    asm volatile("cp.async.commit_group;" ::: "memory");
    asm volatile("cp.async.wait_group 0;" ::: "memory");
    __syncthreads();

    const uint32_t a_off = (uint32_t)((lane & 15) * FL_PK + (lane >> 4) * 16);
    uint32_t qfh[6][4], qfl[6][4];
#pragma unroll
    for (int ks = 0; ks < 6; ks++) {
        uint32_t ad = sbase + (uint32_t)(wid * 16 * FL_PK + ks * 32) + a_off;
        ldsm4(qfh[ks], ad);
        ldsm4(qfl[ks], ad + FL_KT);
    }
    __syncthreads();

    auto load_kv = [&](int t, int stg) {
        const int k0 = t * 128;
        const uint32_t db = sbase + (uint32_t)stg * FL_STG;
#pragma unroll
        for (int it = 0; it < 12; it++) {
            int e = it * 256 + tid;
            int split = e >= 1536;
            int idx = split ? e - 1536 : e;
            int row = idx / 12, c = idx % 12;
            const bf16* src = (split ? Kll : Khh) + (size_t)(k0 + row) * HDP_ + c * 8;
            cp16(db + (uint32_t)split * FL_KT + (uint32_t)(row * FL_PK + c * 16), src);
        }
#pragma unroll
        for (int it = 0; it < 10; it++) {
            int e = it * 256 + tid;
            int split = e >= 1280;
            int idx = split ? e - 1280 : e;
            int row = idx / 16, c = idx % 16;
            const bf16* src = (split ? Vll : Vhh) + (size_t)row * S_ + k0 + c * 8;
            cp16(db + 2 * FL_KT + (uint32_t)split * FL_VT + (uint32_t)(row * FL_PV + c * 16), src);
        }
    };

    const uint32_t bk_off = (uint32_t)((((lane & 7) | ((lane >> 4) << 3)) * FL_PK) +
                                       (((lane >> 3) & 1) * 16));
    const uint32_t bv_off = (uint32_t)((((lane & 7) | ((lane >> 4) << 3)) * FL_PV) +
                                       (((lane >> 3) & 1) * 16));

    float acc_o[10][4];
#pragma unroll
    for (int i = 0; i < 10; i++)
#pragma unroll
        for (int c = 0; c < 4; c++) acc_o[i][c] = 0.f;
    float m0 = -1e30f, m1 = -1e30f, sum0 = 0.f, sum1 = 0.f;
    const float SC2 = SCALE_ * 1.4426950408889634f;

    const int NT = S_ / 128;
    load_kv(0, 0);
    asm volatile("cp.async.commit_group;" ::: "memory");

    for (int t = 0; t < NT; t++) {
        const int buf = t & 1;
        if (t + 1 < NT) {
            load_kv(t + 1, buf ^ 1);
            asm volatile("cp.async.commit_group;" ::: "memory");
            asm volatile("cp.async.wait_group 1;" ::: "memory");
        } else {
            asm volatile("cp.async.wait_group 0;" ::: "memory");
        }
        __syncthreads();

        const uint32_t kb = sbase + (uint32_t)buf * FL_STG;
        const uint32_t vb = kb + 2 * FL_KT;

        float accs[16][4];
#pragma unroll
        for (int i = 0; i < 16; i++)
#pragma unroll
            for (int c = 0; c < 4; c++) accs[i][c] = 0.f;

        // ---- S = Q @ K^T with double-buffered K fragments ----
        {
            uint32_t kh[2][4], kl[2][4];
#define LDK(bufi, kss, nbb) do { \
                uint32_t kd = kb + (uint32_t)((nbb) * 16 * FL_PK + (kss) * 32) + bk_off; \
                ldsm4(kh[bufi], kd); \
                ldsm4(kl[bufi], kd + FL_KT); } while (0)
            LDK(0, 0, 0);
#pragma unroll
            for (int ks = 0; ks < 6; ks++) {
#pragma unroll
                for (int nb = 0; nb < 8; nb++) {
                    const int bb = (ks * 8 + nb) & 1;
                    if (nb < 7)      LDK(bb ^ 1, ks, nb + 1);
                    else if (ks < 5) LDK(bb ^ 1, ks + 1, 0);
#pragma unroll
                    for (int j = 0; j < 2; j++) {
                        mma16816(accs[nb * 2 + j], qfh[ks], &kh[bb][j * 2]);
                        mma16816(accs[nb * 2 + j], qfh[ks], &kl[bb][j * 2]);
                        mma16816(accs[nb * 2 + j], qfl[ks], &kh[bb][j * 2]);
                    }
                }
            }
#undef LDK
        }

        float tm0 = -1e30f, tm1 = -1e30f;
#pragma unroll
        for (int nj = 0; nj < 16; nj++) {
            tm0 = fmaxf(tm0, fmaxf(accs[nj][0], accs[nj][1]));
            tm1 = fmaxf(tm1, fmaxf(accs[nj][2], accs[nj][3]));
        }
        tm0 = fmaxf(tm0, __shfl_xor_sync(0xffffffff, tm0, 1));
        tm0 = fmaxf(tm0, __shfl_xor_sync(0xffffffff, tm0, 2));
        tm1 = fmaxf(tm1, __shfl_xor_sync(0xffffffff, tm1, 1));
        tm1 = fmaxf(tm1, __shfl_xor_sync(0xffffffff, tm1, 2));
        tm0 *= SC2; tm1 *= SC2;

        const float nm0 = fmaxf(m0, tm0), nm1 = fmaxf(m1, tm1);
        const float f0 = exp2f(m0 - nm0), f1 = exp2f(m1 - nm1);
        m0 = nm0; m1 = nm1;

        float rs0 = 0.f, rs1 = 0.f;
#pragma unroll
        for (int nj = 0; nj < 16; nj++) {
            accs[nj][0] = exp2f(fmaf(accs[nj][0], SC2, -m0));
            accs[nj][1] = exp2f(fmaf(accs[nj][1], SC2, -m0));
            accs[nj][2] = exp2f(fmaf(accs[nj][2], SC2, -m1));
            accs[nj][3] = exp2f(fmaf(accs[nj][3], SC2, -m1));
            rs0 += accs[nj][0] + accs[nj][1];
            rs1 += accs[nj][2] + accs[nj][3];
        }
        rs0 += __shfl_xor_sync(0xffffffff, rs0, 1);
        rs0 += __shfl_xor_sync(0xffffffff, rs0, 2);
        rs1 += __shfl_xor_sync(0xffffffff, rs1, 1);
        rs1 += __shfl_xor_sync(0xffffffff, rs1, 2);
        sum0 = sum0 * f0 + rs0;
        sum1 = sum1 * f1 + rs1;

#pragma unroll
        for (int i = 0; i < 10; i++) {
            acc_o[i][0] *= f0; acc_o[i][1] *= f0;
            acc_o[i][2] *= f1; acc_o[i][3] *= f1;
        }

#pragma unroll
        for (int kbk = 0; kbk < 8; kbk++) {
            uint32_t ah[4], al[4];
            {
                const float* p0 = accs[kbk * 2];
                const float* p1 = accs[kbk * 2 + 1];
                float r00 = p0[0] - __bfloat162float(__float2bfloat16(p0[0]));
                float r01 = p0[1] - __bfloat162float(__float2bfloat16(p0[1]));
                float r02 = p0[2] - __bfloat162float(__float2bfloat16(p0[2]));
                float r03 = p0[3] - __bfloat162float(__float2bfloat16(p0[3]));
                float r10 = p1[0] - __bfloat162float(__float2bfloat16(p1[0]));
                float r11 = p1[1] - __bfloat162float(__float2bfloat16(p1[1]));
                float r12 = p1[2] - __bfloat162float(__float2bfloat16(p1[2]));
                float r13 = p1[3] - __bfloat162float(__float2bfloat16(p1[3]));
                ah[0] = packbf(p0[0], p0[1]); ah[1] = packbf(p0[2], p0[3]);
                ah[2] = packbf(p1[0], p1[1]); ah[3] = packbf(p1[2], p1[3]);
                al[0] = packbf(r00, r01);     al[1] = packbf(r02, r03);
                al[2] = packbf(r10, r11);     al[3] = packbf(r12, r13);
            }
#pragma unroll
            for (int db = 0; db < 5; db++) {
                uint32_t vh[4], vl[4];
                uint32_t vd = vb + (uint32_t)(db * 16 * FL_PV + kbk * 32) + bv_off;
                ldsm4(vh, vd);
                ldsm4(vl, vd + FL_VT);
#pragma unroll
                for (int j = 0; j < 2; j++) {
                    mma16816(acc_o[db * 2 + j], ah, &vh[j * 2]);
                    mma16816(acc_o[db * 2 + j], ah, &vl[j * 2]);
                    mma16816(acc_o[db * 2 + j], al, &vh[j * 2]);
                }
            }
        }
        __syncthreads();
    }

    const int gid = lane >> 2, tig = lane & 3;
    const float inv0 = 1.0f / sum0, inv1 = 1.0f / sum1;
    const int r0 = q0 + wid * 16 + gid;
    const int r1 = r0 + 8;
#pragma unroll
    for (int db = 0; db < 10; db++) {
        const int col = h * HD_ + db * 8 + tig * 2;
        bf16 hh, ll;
        size_t o0 = (size_t)r0 * D_ + col;
        size_t o1 = (size_t)r1 * D_ + col;
        bsplit(acc_o[db][0] * inv0, hh, ll); Oh_[o0] = hh; Ol_[o0] = ll;
        bsplit(acc_o[db][1] * inv0, hh, ll); Oh_[o0 + 1] = hh; Ol_[o0 + 1] = ll;
        bsplit(acc_o[db][2] * inv1, hh, ll); Oh_[o1] = hh; Ol_[o1] = ll;
        bsplit(acc_o[db][3] * inv1, hh, ll); Oh_[o1 + 1] = hh; Ol_[o1 + 1] = ll;
    }
}

// ===================== 128x256 bf16x3 GEMM, 512 threads, 3-stage =====================
// C[M, N] = alpha * A[M,K] @ B[N,K]^T
// EPI: 0 = C=v+bias   5 = split-K partial store (z = K-slice via sA/sB elems, C slab via sC)
// Mainloop: A frags double-buffered across ks, B frags double-buffered across ni
// so every ldmatrix issues ahead of the MMAs that consume the previous fragments.
#define A_T 10240
#define B_T 20480
#define STAGE_B (2 * A_T + 2 * B_T)
#define GEMM2_SMEM (3 * STAGE_B)

template <int EPI>
__global__ void __launch_bounds__(512, 1)
gemm_mma2(const bf16* __restrict__ Agh, const bf16* __restrict__ Agl,
          const bf16* __restrict__ Bgh, const bf16* __restrict__ Bgl,
          const float* __restrict__ bias,
          float* __restrict__ C,
          int K, int lda, int ldb, int ldc,
          long long sA, long long sB, long long sC, float alpha) {
    extern __shared__ __align__(16) char smem[];
    const uint32_t sbase = smem_to_u32(smem);
    const int tid = threadIdx.x;
    const int wid = tid >> 5;
    const int lane = tid & 31;
    const int warp_m = wid & 3;
    const int warp_n = wid >> 2;
    const int bz = blockIdx.z;

    Agh += (size_t)bz * sA; Agl += (size_t)bz * sA;
    Bgh += (size_t)bz * sB; Bgl += (size_t)bz * sB;
    const size_t coff = (size_t)bz * sC;
    const int row0 = blockIdx.y * 128;
    const int col0 = blockIdx.x * 256;

    const uint32_t a_off = (uint32_t)(((lane & 15) * 40 + (lane >> 4) * 8) * 2);
    const uint32_t b_off = (uint32_t)(((((lane & 7) | ((lane >> 4) << 3)) * 40) +
                                      (((lane >> 3) & 1) * 8) ) * 2);

    auto load_chunk = [&](int kc, int stg) {
        const int k0 = kc << 5;
        const uint32_t dbase = sbase + (uint32_t)stg * STAGE_B;
#pragma unroll
        for (int it = 0; it < 2; it++) {
            int e = it * 512 + tid;
            int t = e >> 9;
            int idx = e & 511;
            int row = idx >> 2, c8 = idx & 3;
            const bf16* src = (t ? Agl : Agh) + (size_t)(row0 + row) * lda + k0 + c8 * 8;
            uint32_t dst = dbase + (uint32_t)t * A_T + (uint32_t)(row * 80 + c8 * 16);
            cp16(dst, src);
        }
#pragma unroll
        for (int it = 0; it < 4; it++) {
            int e = it * 512 + tid;
            int t = e >> 10;
            int idx = e & 1023;
            int row = idx >> 2, c8 = idx & 3;
            const bf16* src = (t ? Bgl : Bgh) + (size_t)(col0 + row) * ldb + k0 + c8 * 8;
            uint32_t dst = dbase + 2 * A_T + (uint32_t)t * B_T + (uint32_t)(row * 80 + c8 * 16);
            cp16(dst, src);
        }
    };

    float acc[2][8][4];
#pragma unroll
    for (int mi = 0; mi < 2; mi++)
#pragma unroll
        for (int nj = 0; nj < 8; nj++)
#pragma unroll
            for (int c = 0; c < 4; c++) acc[mi][nj][c] = 0.f;

    const int NC = K >> 5;
    load_chunk(0, 0);
    asm volatile("cp.async.commit_group;" ::: "memory");
    if (1 < NC) load_chunk(1, 1);
    asm volatile("cp.async.commit_group;" ::: "memory");

    int stg = 0;
    for (int kc = 0; kc < NC; kc++) {
        asm volatile("cp.async.wait_group 1;" ::: "memory");
        __syncthreads();
        if (kc + 2 < NC) load_chunk(kc + 2, (stg + 2 >= 3) ? stg - 1 : stg + 2);
        asm volatile("cp.async.commit_group;" ::: "memory");

        const uint32_t cbase = sbase + (uint32_t)stg * STAGE_B;

        // register double-buffered fragments
        uint32_t ah[2][2][4], al[2][2][4];   // [ks buf][mi]
        uint32_t bh[2][4], bl[2][4];         // [ni buf]
#define LDA(bufi, kss) do { \
        _Pragma("unroll") \
        for (int mi = 0; mi < 2; mi++) { \
            uint32_t ad = cbase + (uint32_t)((warp_m * 32 + mi * 16) * 80 + (kss) * 32) + a_off; \
            ldsm4(ah[bufi][mi], ad); \
            ldsm4(al[bufi][mi], ad + A_T); \
        } } while (0)
#define LDB(bufi, kss, nii) do { \
        uint32_t bd = cbase + 2 * A_T + \
                      (uint32_t)((warp_n * 64 + (nii) * 16) * 80 + (kss) * 32) + b_off; \
        ldsm4(bh[bufi], bd); \
        ldsm4(bl[bufi], bd + B_T); } while (0)

        LDA(0, 0);
        LDB(0, 0, 0);
#pragma unroll
        for (int ks = 0; ks < 2; ks++) {
#pragma unroll
            for (int ni = 0; ni < 4; ni++) {
                const int bb = (ks * 4 + ni) & 1;
                if (ni < 3)       LDB(bb ^ 1, ks, ni + 1);
                else if (ks == 0) { LDA(1, 1); LDB(bb ^ 1, 1, 0); }
#pragma unroll
                for (int mi = 0; mi < 2; mi++)
#pragma unroll
                    for (int j = 0; j < 2; j++) {
                        const int nj = ni * 2 + j;
                        mma16816(acc[mi][nj], ah[ks][mi], &bh[bb][j * 2]);
                        mma16816(acc[mi][nj], ah[ks][mi], &bl[bb][j * 2]);
                        mma16816(acc[mi][nj], al[ks][mi], &bh[bb][j * 2]);
                    }
            }
        }
#undef LDA
#undef LDB
        __syncthreads();
        stg = (stg + 1 >= 3) ? 0 : stg + 1;
    }

    const int gid = lane >> 2, tig = lane & 3;
#pragma unroll
    for (int mi = 0; mi < 2; mi++) {
#pragma unroll
        for (int hh = 0; hh < 2; hh++) {
            const int r = row0 + warp_m * 32 + mi * 16 + gid + hh * 8;
#pragma unroll
            for (int nj = 0; nj < 8; nj++) {
                const int c = col0 + warp_n * 64 + nj * 8 + tig * 2;
                float v0 = acc[mi][nj][hh * 2 + 0] * alpha;
                float v1 = acc[mi][nj][hh * 2 + 1] * alpha;
                const size_t o = coff + (size_t)r * ldc + c;
                if (EPI == 0) {
                    C[o] = v0 + bias[c];
                    C[o + 1] = v1 + bias[c + 1];
                } else {
                    C[o] = v0;
                    C[o + 1] = v1;
                }
            }
        }
    }
}

// ===================== host-side launch =====================
extern "C" void kernel_launch(void* const* d_in, const int* in_sizes, int n_in,
                              void* d_out, int out_size) {
    const float* hidden = (const float*)d_in[0];
    const float* cosp   = (const float*)d_in[1];
    const float* sinp   = (const float*)d_in[2];
    const float* qkv_w  = (const float*)d_in[3];
    const float* qkv_b  = (const float*)d_in[4];
    const float* proj_w = (const float*)d_in[5];
    const float* proj_b = (const float*)d_in[6];
    const float* ln1_g  = (const float*)d_in[7];
    const float* ln1_b  = (const float*)d_in[8];
    const float* ln2_g  = (const float*)d_in[9];
    const float* ln2_b  = (const float*)d_in[10];
    const float* fc1_w  = (const float*)d_in[11];
    const float* fc1_b  = (const float*)d_in[12];
    const float* fc2_w  = (const float*)d_in[13];
    const float* fc2_b  = (const float*)d_in[14];

    float* x = (float*)d_out;

    float *p_qkv, *p_part, *p_part1;
    bf16 *p_hh, *p_hl, *p_qh, *p_ql, *p_kh, *p_kl, *p_vth, *p_vtl;
    bf16 *p_ah, *p_al, *p_mh, *p_ml;
    bf16 *wqh, *wql, *wph, *wpl, *w1h, *w1l, *w2h, *w2l;
    cudaGetSymbolAddress((void**)&p_qkv, g_qkv);
    cudaGetSymbolAddress((void**)&p_part, g_part);
    cudaGetSymbolAddress((void**)&p_part1, g_part1);
    cudaGetSymbolAddress((void**)&p_hh,  g_hh);   cudaGetSymbolAddress((void**)&p_hl, g_hl);
    cudaGetSymbolAddress((void**)&p_qh,  g_qh);   cudaGetSymbolAddress((void**)&p_ql, g_ql);
    cudaGetSymbolAddress((void**)&p_kh,  g_kh);   cudaGetSymbolAddress((void**)&p_kl, g_kl);
    cudaGetSymbolAddress((void**)&p_vth, g_vth);  cudaGetSymbolAddress((void**)&p_vtl, g_vtl);
    cudaGetSymbolAddress((void**)&p_ah,  g_ah);   cudaGetSymbolAddress((void**)&p_al, g_al);
    cudaGetSymbolAddress((void**)&p_mh,  g_mh);   cudaGetSymbolAddress((void**)&p_ml, g_ml);
    cudaGetSymbolAddress((void**)&wqh, g_wqh);    cudaGetSymbolAddress((void**)&wql, g_wql);
    cudaGetSymbolAddress((void**)&wph, g_wph);    cudaGetSymbolAddress((void**)&wpl, g_wpl);
    cudaGetSymbolAddress((void**)&w1h, g_w1h);    cudaGetSymbolAddress((void**)&w1l, g_w1l);
    cudaGetSymbolAddress((void**)&w2h, g_w2h);    cudaGetSymbolAddress((void**)&w2l, g_w2l);

    float* pt[5] = {p_part, p_part + S_ * D_, p_part + 2 * (size_t)S_ * D_,
                    p_part + 3 * (size_t)S_ * D_, p_part + 4 * (size_t)S_ * D_};
    float* pt1[2] = {p_part1, p_part1 + (size_t)S_ * I_};

    cudaFuncSetAttribute((const void*)gemm_mma2<0>, cudaFuncAttributeMaxDynamicSharedMemorySize, GEMM2_SMEM);
    cudaFuncSetAttribute((const void*)gemm_mma2<5>, cudaFuncAttributeMaxDynamicSharedMemorySize, GEMM2_SMEM);
    cudaFuncSetAttribute((const void*)flash_kernel,  cudaFuncAttributeMaxDynamicSharedMemorySize, FLASH_SMEM);

    cudaMemcpyAsync(x, hidden, (size_t)S_ * D_ * sizeof(float), cudaMemcpyDeviceToDevice);

    for (int l = 0; l < 2; l++) {
        const float* qw = qkv_w + (size_t)l * D_ * NQKV_;
        const float* qb = qkv_b + (size_t)l * NQKV_;
        const float* pw = proj_w + (size_t)l * D_ * D_;
        const float* pb = proj_b + (size_t)l * D_;
        const float* g1 = ln1_g + (size_t)l * D_;
        const float* b1 = ln1_b + (size_t)l * D_;
        const float* g2 = ln2_g + (size_t)l * D_;
        const float* b2 = ln2_b + (size_t)l * D_;
        const float* f1w = fc1_w + (size_t)l * D_ * I_;
        const float* f1b = fc1_b + (size_t)l * I_;
        const float* f2w = fc2_w + (size_t)l * I_ * D_;
        const float* f2b = fc2_b + (size_t)l * D_;

        // LN1: layer 0 standalone (layer 1's LN1 is fused into layer 0's fc2 reduce)
        if (l == 0)
            ln_split_kernel<<<S_, 256>>>(x, g1, b1, p_hh, p_hl);

        // wsq, wsp before qkv so the ncu-captured launch (#4) is the qkv GEMM
        wsplit_T_kernel<<<dim3(NQKV_ / 32, D_ / 32), dim3(32, 8)>>>(qw, wqh, wql, D_, NQKV_);
        wsplit_T_kernel<<<dim3(D_ / 32, D_ / 32), dim3(32, 8)>>>(pw, wph, wpl, D_, D_);

        // qkv = h @ W_qkv + b   (fp32 out)
        gemm_mma2<0><<<dim3(NQKV_ / 256, S_ / 128, 1), 512, GEMM2_SMEM>>>(
            p_hh, p_hl, wqh, wql, qb, p_qkv,
            D_, D_, D_, NQKV_, 0, 0, 0, 1.f);

        // RoPE + split + V^T (+zero pad)
        rope_split_kernel<<<(S_ * H_ * HDP_ + 255) / 256, 256>>>(
            p_qkv, cosp, sinp, p_qh, p_ql, p_kh, p_kl, p_vth, p_vtl);

        // fused flash attention -> attn out split in [S, D]
        flash_kernel<<<dim3(S_ / 128, H_), 256, FLASH_SMEM>>>(
            p_qh, p_ql, p_kh, p_kl, p_vth, p_vtl, p_ah, p_al);

        // proj: split-K=5 (K=1280 -> 256 each, 400 CTAs), then fused reduce+LN2
        gemm_mma2<5><<<dim3(D_ / 256, S_ / 128, 5), 512, GEMM2_SMEM>>>(
            p_ah, p_al, wph, wpl, nullptr, pt[0],
            D_ / 5, D_, D_, D_, D_ / 5, D_ / 5, (long long)S_ * D_, 1.f);
        reduce5_ln_kernel<<<S_, 256>>>(pt[0], pt[1], pt[2], pt[3], pt[4],
                                       pb, x, g2, b2, p_hh, p_hl);

        // fc1: split-K=2 (K=1280 -> 640 each, 640 CTAs), then reduce+bias+gelu+split
        wsplit_T_kernel<<<dim3(I_ / 32, D_ / 32), dim3(32, 8)>>>(f1w, w1h, w1l, D_, I_);
        gemm_mma2<5><<<dim3(I_ / 256, S_ / 128, 2), 512, GEMM2_SMEM>>>(
            p_hh, p_hl, w1h, w1l, nullptr, pt1[0],
            D_ / 2, D_, D_, I_, D_ / 2, D_ / 2, (long long)S_ * I_, 1.f);
        reduce2_gelu_kernel<<<(S_ * I_ + 255) / 256, 256>>>(pt1[0], pt1[1], f1b, p_mh, p_ml);

        // fc2: split-K=5 (K=5120 -> 1024 each, 400 CTAs)
        wsplit_T_kernel<<<dim3(D_ / 32, I_ / 32), dim3(32, 8)>>>(f2w, w2h, w2l, I_, D_);
        gemm_mma2<5><<<dim3(D_ / 256, S_ / 128, 5), 512, GEMM2_SMEM>>>(
            p_mh, p_ml, w2h, w2l, nullptr, pt[0],
            I_ / 5, I_, I_, D_, I_ / 5, I_ / 5, (long long)S_ * D_, 1.f);
        if (l == 0) {
            // fused: x += fc2 + bias, then LN1 of layer 1
            reduce5_ln_kernel<<<S_, 256>>>(pt[0], pt[1], pt[2], pt[3], pt[4],
                                           f2b, x, ln1_g + D_, ln1_b + D_, p_hh, p_hl);
        } else {
            reduce5_kernel<<<(S_ * D_ + 255) / 256, 256>>>(pt[0], pt[1], pt[2], pt[3], pt[4],
                                                           f2b, x);
        }
    }
}

// round 15
// speedup vs baseline: 2.0998x; 1.4879x over previous
#include <cuda_runtime.h>
#include <cuda_fp16.h>
#include <math.h>
#include <stdint.h>

// Problem constants
#define S_ 2048
#define D_ 1280
#define H_ 16
#define HD_ 80
#define HDP_ 96           // padded head dim (3 chunks of 32)
#define I_ 5120
#define NQKV_ 3840
#define EPS_ 1e-6f
#define SCALE_ 0.11180339887498949f  // 80^-0.5

typedef __half fp16;

// ===================== device scratch (no allocation allowed) =====================
__device__ float g_qkv[S_ * NQKV_];                  // qkv proj fp32
__device__ float g_part[5][S_ * D_];                 // split-K partials
__device__ float g_part1[2][S_ * I_];                // fc1 split-K partials
__device__ fp16  g_hh[S_ * D_],  g_hl[S_ * D_];      // LN out split (A operand)
__device__ fp16  g_qh[H_ * S_ * HDP_], g_ql[H_ * S_ * HDP_];
__device__ fp16  g_k [H_ * S_ * HDP_];               // K single fp16
__device__ fp16  g_vt[H_ * HD_ * S_];                // V^T single fp16
__device__ fp16  g_ah[S_ * D_],  g_al[S_ * D_];      // attn out split
__device__ fp16  g_mh[S_ * I_],  g_ml[S_ * I_];      // mlp hidden split
__device__ fp16  g_wq[NQKV_ * D_];                   // weights single fp16 (rounded)
__device__ fp16  g_wp[D_ * D_];
__device__ fp16  g_w1[I_ * D_];
__device__ fp16  g_w2[D_ * I_];

__device__ __forceinline__ void fsplit(float v, fp16& h, fp16& l) {
    h = __float2half_rn(v);
    l = __float2half_rn(v - __half2float(h));
}

__device__ __forceinline__ uint32_t packh(float a, float b) {
    __half2 t = __floats2half2_rn(a, b);
    return *reinterpret_cast<uint32_t*>(&t);
}

__device__ __forceinline__ uint32_t smem_to_u32(const void* smem_ptr) {
    uint32_t addr;
    asm("{ .reg .u64 tmp; cvta.to.shared.u64 tmp, %1; cvt.u32.u64 %0, tmp; }"
        : "=r"(addr) : "l"(smem_ptr));
    return addr;
}

__device__ __forceinline__ void ldsm4(uint32_t (&r)[4], uint32_t addr) {
    asm volatile("ldmatrix.sync.aligned.m8n8.x4.shared.b16 {%0,%1,%2,%3}, [%4];"
                 : "=r"(r[0]), "=r"(r[1]), "=r"(r[2]), "=r"(r[3]) : "r"(addr));
}

__device__ __forceinline__ void mma16816(float (&d)[4], const uint32_t (&a)[4],
                                         const uint32_t* b) {
    asm volatile(
        "mma.sync.aligned.m16n8k16.row.col.f32.f16.f16.f32 "
        "{%0,%1,%2,%3}, {%4,%5,%6,%7}, {%8,%9}, {%0,%1,%2,%3};"
        : "+f"(d[0]), "+f"(d[1]), "+f"(d[2]), "+f"(d[3])
        : "r"(a[0]), "r"(a[1]), "r"(a[2]), "r"(a[3]), "r"(b[0]), "r"(b[1]));
}

__device__ __forceinline__ void cp16(uint32_t dst, const void* src) {
    asm volatile("cp.async.cg.shared.global [%0], [%1], 16;"
                 :: "r"(dst), "l"(src));
}

// ===================== LayerNorm -> fp16 split =====================
__global__ void ln_split_kernel(const float* __restrict__ x,
                                const float* __restrict__ g,
                                const float* __restrict__ b,
                                fp16* __restrict__ oh, fp16* __restrict__ ol) {
    const int row = blockIdx.x;
    const int t = threadIdx.x;
    __shared__ float srow[D_];
    __shared__ float red[256];

    float local = 0.f;
    for (int i = t; i < D_; i += 256) {
        float v = x[(size_t)row * D_ + i];
        srow[i] = v;
        local += v;
    }
    red[t] = local;
    __syncthreads();
    for (int s = 128; s > 0; s >>= 1) { if (t < s) red[t] += red[t + s]; __syncthreads(); }
    const float mean = red[0] * (1.0f / D_);
    __syncthreads();

    local = 0.f;
    for (int i = t; i < D_; i += 256) { float dv = srow[i] - mean; local += dv * dv; }
    red[t] = local;
    __syncthreads();
    for (int s = 128; s > 0; s >>= 1) { if (t < s) red[t] += red[t + s]; __syncthreads(); }
    const float inv = rsqrtf(red[0] * (1.0f / D_) + EPS_);

    for (int i = t; i < D_; i += 256) {
        float v = (srow[i] - mean) * inv * g[i] + b[i];
        fp16 h, l; fsplit(v, h, l);
        oh[(size_t)row * D_ + i] = h;
        ol[(size_t)row * D_ + i] = l;
    }
}

// ===================== split-K(5) reduce + residual + LayerNorm + split =====================
__global__ void reduce5_ln_kernel(const float* __restrict__ p0, const float* __restrict__ p1,
                                  const float* __restrict__ p2, const float* __restrict__ p3,
                                  const float* __restrict__ p4,
                                  const float* __restrict__ bias, float* __restrict__ x,
                                  const float* __restrict__ g, const float* __restrict__ b,
                                  fp16* __restrict__ oh, fp16* __restrict__ ol) {
    const int row = blockIdx.x;
    const int t = threadIdx.x;
    __shared__ float srow[D_];
    __shared__ float red[256];

    float local = 0.f;
    for (int i = t; i < D_; i += 256) {
        const size_t o = (size_t)row * D_ + i;
        float v = x[o] + ((p0[o] + p1[o]) + (p2[o] + p3[o]) + p4[o]) + bias[i];
        x[o] = v;
        srow[i] = v;
        local += v;
    }
    red[t] = local;
    __syncthreads();
    for (int s = 128; s > 0; s >>= 1) { if (t < s) red[t] += red[t + s]; __syncthreads(); }
    const float mean = red[0] * (1.0f / D_);
    __syncthreads();

    local = 0.f;
    for (int i = t; i < D_; i += 256) { float dv = srow[i] - mean; local += dv * dv; }
    red[t] = local;
    __syncthreads();
    for (int s = 128; s > 0; s >>= 1) { if (t < s) red[t] += red[t + s]; __syncthreads(); }
    const float inv = rsqrtf(red[0] * (1.0f / D_) + EPS_);

    for (int i = t; i < D_; i += 256) {
        float v = (srow[i] - mean) * inv * g[i] + b[i];
        fp16 h, l; fsplit(v, h, l);
        oh[(size_t)row * D_ + i] = h;
        ol[(size_t)row * D_ + i] = l;
    }
}

// plain split-K(5) reduce: x += sum + bias (final output)
__global__ void reduce5_kernel(const float* __restrict__ p0, const float* __restrict__ p1,
                               const float* __restrict__ p2, const float* __restrict__ p3,
                               const float* __restrict__ p4,
                               const float* __restrict__ bias, float* __restrict__ x) {
    int i = blockIdx.x * blockDim.x + threadIdx.x;
    if (i >= S_ * D_) return;
    const int c = i % D_;
    x[i] = x[i] + ((p0[i] + p1[i]) + (p2[i] + p3[i]) + p4[i]) + bias[c];
}

// split-K(2) reduce + bias + gelu + fp16 split (fc1 epilogue)
__global__ void reduce2_gelu_kernel(const float* __restrict__ p0, const float* __restrict__ p1,
                                    const float* __restrict__ bias,
                                    fp16* __restrict__ mh, fp16* __restrict__ ml) {
    int i = blockIdx.x * blockDim.x + threadIdx.x;
    if (i >= S_ * I_) return;
    const int c = i % I_;
    float v = p0[i] + p1[i] + bias[c];
    v = 0.5f * v * (1.0f + erff(v * 0.70710678118654752f));
    fp16 h, l; fsplit(v, h, l);
    mh[i] = h; ml[i] = l;
}

// ===================== weight transpose + round: w[K][N] -> Wt[N][K] fp16 =====================
__global__ void wsplit_T_kernel(const float* __restrict__ w,
                                fp16* __restrict__ o, int K, int N) {
    __shared__ float tile[32][33];
    int k0 = blockIdx.y * 32, n0 = blockIdx.x * 32;
    int tx = threadIdx.x, ty = threadIdx.y;
#pragma unroll
    for (int j = 0; j < 4; j++)
        tile[ty + j * 8][tx] = w[(size_t)(k0 + ty + j * 8) * N + n0 + tx];
    __syncthreads();
#pragma unroll
    for (int j = 0; j < 4; j++) {
        int n = ty + j * 8;
        o[(size_t)(n0 + n) * K + k0 + tx] = __float2half_rn(tile[tx][n]);
    }
}

// ===================== RoPE + head split + V transpose (incl. zero pad) =====================
__global__ void rope_split_kernel(const float* __restrict__ qkv,
                                  const float* __restrict__ cosp,
                                  const float* __restrict__ sinp,
                                  fp16* __restrict__ Qh, fp16* __restrict__ Ql,
                                  fp16* __restrict__ Kk, fp16* __restrict__ Vt) {
    int i = blockIdx.x * blockDim.x + threadIdx.x;
    if (i >= S_ * H_ * HDP_) return;
    const int s = i / (H_ * HDP_);
    const int r = i % (H_ * HDP_);
    const int h = r / HDP_;
    const int d = r % HDP_;

    const size_t oq = ((size_t)h * S_ + s) * HDP_ + d;
    if (d >= HD_) {
        const fp16 z = __float2half(0.f);
        Qh[oq] = z; Ql[oq] = z; Kk[oq] = z;
        return;
    }

    const float c = cosp[s * HD_ + d];
    const float sn = sinp[s * HD_ + d];
    const size_t base = (size_t)s * NQKV_;

    const int d2 = (d < HD_ / 2) ? d + HD_ / 2 : d - HD_ / 2;
    const float sign = (d < HD_ / 2) ? -1.f : 1.f;

    const float q  = qkv[base + h * HD_ + d];
    const float qp = qkv[base + h * HD_ + d2];
    const float k  = qkv[base + D_ + h * HD_ + d];
    const float kp = qkv[base + D_ + h * HD_ + d2];
    const float v  = qkv[base + 2 * D_ + h * HD_ + d];

    const float rq = q * c + sign * qp * sn;
    const float rk = k * c + sign * kp * sn;

    fp16 hh, ll;
    fsplit(rq, hh, ll); Qh[oq] = hh; Ql[oq] = ll;
    Kk[oq] = __float2half_rn(rk);
    Vt[((size_t)h * HD_ + d) * S_ + s] = __float2half_rn(v);
}

// ===================== fused flash attention (fp16: Q split, K/V/P single) ==========
#define FL_PK 208
#define FL_PV 272
#define FL_KT (128 * FL_PK)             // 26624
#define FL_VT (80 * FL_PV)              // 21760
#define FL_STG (FL_KT + FL_VT)          // 48384
#define FLASH_SMEM (2 * FL_STG)         // 96768

__global__ void __launch_bounds__(256, 1)
flash_kernel(const fp16* __restrict__ Qh_, const fp16* __restrict__ Ql_,
             const fp16* __restrict__ K_, const fp16* __restrict__ Vt_,
             fp16* __restrict__ Oh_, fp16* __restrict__ Ol_) {
    extern __shared__ __align__(16) char smem[];
    const uint32_t sbase = smem_to_u32(smem);
    const int tid = threadIdx.x;
    const int wid = tid >> 5;
    const int lane = tid & 31;
    const int h = blockIdx.y;
    const int q0 = blockIdx.x * 128;

    const fp16* Qhh = Qh_ + ((size_t)h * S_ + q0) * HDP_;
    const fp16* Qll = Ql_ + ((size_t)h * S_ + q0) * HDP_;
    const fp16* Kg  = K_  + (size_t)h * S_ * HDP_;
    const fp16* Vg  = Vt_ + (size_t)h * HD_ * S_;

    // stage Qh into stage-0 K slot, Ql into stage-1 K slot
#pragma unroll
    for (int it = 0; it < 12; it++) {
        int e = it * 256 + tid;              // 3072 = 2 splits * 128 rows * 12 chunks
        int split = e >= 1536;
        int idx = split ? e - 1536 : e;
        int row = idx / 12, c = idx % 12;
        const fp16* src = (split ? Qll : Qhh) + (size_t)row * HDP_ + c * 8;
        cp16(sbase + (uint32_t)split * FL_STG + (uint32_t)(row * FL_PK + c * 16), src);
    }
    asm volatile("cp.async.commit_group;" ::: "memory");
    asm volatile("cp.async.wait_group 0;" ::: "memory");
    __syncthreads();

    const uint32_t a_off = (uint32_t)((lane & 15) * FL_PK + (lane >> 4) * 16);
    uint32_t qfh[6][4], qfl[6][4];
#pragma unroll
    for (int ks = 0; ks < 6; ks++) {
        uint32_t ad = sbase + (uint32_t)(wid * 16 * FL_PK + ks * 32) + a_off;
        ldsm4(qfh[ks], ad);
        ldsm4(qfl[ks], ad + FL_STG);
    }
    __syncthreads();

    auto load_kv = [&](int t, int stg) {
        const int k0 = t * 128;
        const uint32_t db = sbase + (uint32_t)stg * FL_STG;
#pragma unroll
        for (int it = 0; it < 6; it++) {     // K: 128 rows * 12 chunks = 1536
            int idx = it * 256 + tid;
            int row = idx / 12, c = idx % 12;
            const fp16* src = Kg + (size_t)(k0 + row) * HDP_ + c * 8;
            cp16(db + (uint32_t)(row * FL_PK + c * 16), src);
        }
#pragma unroll
        for (int it = 0; it < 5; it++) {     // V: 80 rows * 16 chunks = 1280
            int idx = it * 256 + tid;
            int row = idx / 16, c = idx % 16;
            const fp16* src = Vg + (size_t)row * S_ + k0 + c * 8;
            cp16(db + FL_KT + (uint32_t)(row * FL_PV + c * 16), src);
        }
    };

    const uint32_t bk_off = (uint32_t)((((lane & 7) | ((lane >> 4) << 3)) * FL_PK) +
                                       (((lane >> 3) & 1) * 16));
    const uint32_t bv_off = (uint32_t)((((lane & 7) | ((lane >> 4) << 3)) * FL_PV) +
                                       (((lane >> 3) & 1) * 16));

    float acc_o[10][4];
#pragma unroll
    for (int i = 0; i < 10; i++)
#pragma unroll
        for (int c = 0; c < 4; c++) acc_o[i][c] = 0.f;
    float m0 = -1e30f, m1 = -1e30f, sum0 = 0.f, sum1 = 0.f;
    const float SC2 = SCALE_ * 1.4426950408889634f;

    const int NT = S_ / 128;
    load_kv(0, 0);
    asm volatile("cp.async.commit_group;" ::: "memory");

    for (int t = 0; t < NT; t++) {
        const int buf = t & 1;
        if (t + 1 < NT) {
            load_kv(t + 1, buf ^ 1);
            asm volatile("cp.async.commit_group;" ::: "memory");
            asm volatile("cp.async.wait_group 1;" ::: "memory");
        } else {
            asm volatile("cp.async.wait_group 0;" ::: "memory");
        }
        __syncthreads();

        const uint32_t kb = sbase + (uint32_t)buf * FL_STG;
        const uint32_t vb = kb + FL_KT;

        float accs[16][4];
#pragma unroll
        for (int i = 0; i < 16; i++)
#pragma unroll
            for (int c = 0; c < 4; c++) accs[i][c] = 0.f;

        // ---- S = Q @ K^T (Q split 2-term, K single) ----
        {
            uint32_t kh[2][4];
#define LDK(bufi, kss, nbb) \
            ldsm4(kh[bufi], kb + (uint32_t)((nbb) * 16 * FL_PK + (kss) * 32) + bk_off)
            LDK(0, 0, 0);
#pragma unroll
            for (int ks = 0; ks < 6; ks++) {
#pragma unroll
                for (int nb = 0; nb < 8; nb++) {
                    const int bb = (ks * 8 + nb) & 1;
                    if (nb < 7)      LDK(bb ^ 1, ks, nb + 1);
                    else if (ks < 5) LDK(bb ^ 1, ks + 1, 0);
#pragma unroll
                    for (int j = 0; j < 2; j++) {
                        mma16816(accs[nb * 2 + j], qfh[ks], &kh[bb][j * 2]);
                        mma16816(accs[nb * 2 + j], qfl[ks], &kh[bb][j * 2]);
                    }
                }
            }
#undef LDK
        }

        float tm0 = -1e30f, tm1 = -1e30f;
#pragma unroll
        for (int nj = 0; nj < 16; nj++) {
            tm0 = fmaxf(tm0, fmaxf(accs[nj][0], accs[nj][1]));
            tm1 = fmaxf(tm1, fmaxf(accs[nj][2], accs[nj][3]));
        }
        tm0 = fmaxf(tm0, __shfl_xor_sync(0xffffffff, tm0, 1));
        tm0 = fmaxf(tm0, __shfl_xor_sync(0xffffffff, tm0, 2));
        tm1 = fmaxf(tm1, __shfl_xor_sync(0xffffffff, tm1, 1));
        tm1 = fmaxf(tm1, __shfl_xor_sync(0xffffffff, tm1, 2));
        tm0 *= SC2; tm1 *= SC2;

        const float nm0 = fmaxf(m0, tm0), nm1 = fmaxf(m1, tm1);
        const float f0 = exp2f(m0 - nm0), f1 = exp2f(m1 - nm1);
        m0 = nm0; m1 = nm1;

        float rs0 = 0.f, rs1 = 0.f;
#pragma unroll
        for (int nj = 0; nj < 16; nj++) {
            accs[nj][0] = exp2f(fmaf(accs[nj][0], SC2, -m0));
            accs[nj][1] = exp2f(fmaf(accs[nj][1], SC2, -m0));
            accs[nj][2] = exp2f(fmaf(accs[nj][2], SC2, -m1));
            accs[nj][3] = exp2f(fmaf(accs[nj][3], SC2, -m1));
            rs0 += accs[nj][0] + accs[nj][1];
            rs1 += accs[nj][2] + accs[nj][3];
        }
        rs0 += __shfl_xor_sync(0xffffffff, rs0, 1);
        rs0 += __shfl_xor_sync(0xffffffff, rs0, 2);
        rs1 += __shfl_xor_sync(0xffffffff, rs1, 1);
        rs1 += __shfl_xor_sync(0xffffffff, rs1, 2);
        sum0 = sum0 * f0 + rs0;
        sum1 = sum1 * f1 + rs1;

#pragma unroll
        for (int i = 0; i < 10; i++) {
            acc_o[i][0] *= f0; acc_o[i][1] *= f0;
            acc_o[i][2] *= f1; acc_o[i][3] *= f1;
        }

        // ---- O += P @ V (P single fp16, V single) ----
#pragma unroll
        for (int kbk = 0; kbk < 8; kbk++) {
            uint32_t ah[4];
            {
                const float* p0 = accs[kbk * 2];
                const float* p1 = accs[kbk * 2 + 1];
                ah[0] = packh(p0[0], p0[1]); ah[1] = packh(p0[2], p0[3]);
                ah[2] = packh(p1[0], p1[1]); ah[3] = packh(p1[2], p1[3]);
            }
#pragma unroll
            for (int db = 0; db < 5; db++) {
                uint32_t vh[4];
                ldsm4(vh, vb + (uint32_t)(db * 16 * FL_PV + kbk * 32) + bv_off);
#pragma unroll
                for (int j = 0; j < 2; j++)
                    mma16816(acc_o[db * 2 + j], ah, &vh[j * 2]);
            }
        }
        __syncthreads();
    }

    const int gid = lane >> 2, tig = lane & 3;
    const float inv0 = 1.0f / sum0, inv1 = 1.0f / sum1;
    const int r0 = q0 + wid * 16 + gid;
    const int r1 = r0 + 8;
#pragma unroll
    for (int db = 0; db < 10; db++) {
        const int col = h * HD_ + db * 8 + tig * 2;
        fp16 hh, ll;
        size_t o0 = (size_t)r0 * D_ + col;
        size_t o1 = (size_t)r1 * D_ + col;
        fsplit(acc_o[db][0] * inv0, hh, ll); Oh_[o0] = hh; Ol_[o0] = ll;
        fsplit(acc_o[db][1] * inv0, hh, ll); Oh_[o0 + 1] = hh; Ol_[o0 + 1] = ll;
        fsplit(acc_o[db][2] * inv1, hh, ll); Oh_[o1] = hh; Ol_[o1] = ll;
        fsplit(acc_o[db][3] * inv1, hh, ll); Oh_[o1 + 1] = hh; Ol_[o1 + 1] = ll;
    }
}

// ===================== 128x256 fp16 2-term GEMM, 512 threads, 4-stage =====================
// C[M, N] = alpha * (Ah+Al)[M,K] @ B[N,K]^T   (A split fp16, B single fp16)
// EPI: 0 = C=v+bias   5 = split-K partial store
#define A_T 10240
#define B_T 20480
#define STAGE_B (2 * A_T + B_T)        // 40960
#define GEMM2_SMEM (4 * STAGE_B)       // 163840

template <int EPI>
__global__ void __launch_bounds__(512, 1)
gemm_mma2(const fp16* __restrict__ Agh, const fp16* __restrict__ Agl,
          const fp16* __restrict__ Bg,
          const float* __restrict__ bias,
          float* __restrict__ C,
          int K, int lda, int ldb, int ldc,
          long long sA, long long sB, long long sC, float alpha) {
    extern __shared__ __align__(16) char smem[];
    const uint32_t sbase = smem_to_u32(smem);
    const int tid = threadIdx.x;
    const int wid = tid >> 5;
    const int lane = tid & 31;
    const int warp_m = wid & 3;
    const int warp_n = wid >> 2;
    const int bz = blockIdx.z;

    Agh += (size_t)bz * sA; Agl += (size_t)bz * sA;
    Bg  += (size_t)bz * sB;
    const size_t coff = (size_t)bz * sC;
    const int row0 = blockIdx.y * 128;
    const int col0 = blockIdx.x * 256;

    const uint32_t a_off = (uint32_t)(((lane & 15) * 40 + (lane >> 4) * 8) * 2);
    const uint32_t b_off = (uint32_t)(((((lane & 7) | ((lane >> 4) << 3)) * 40) +
                                      (((lane >> 3) & 1) * 8) ) * 2);

    auto load_chunk = [&](int kc, int stg) {
        const int k0 = kc << 5;
        const uint32_t dbase = sbase + (uint32_t)stg * STAGE_B;
#pragma unroll
        for (int it = 0; it < 2; it++) {     // Ah, Al: 2 * 512 cp16
            int e = it * 512 + tid;
            int t = e >> 9;
            int idx = e & 511;
            int row = idx >> 2, c8 = idx & 3;
            const fp16* src = (t ? Agl : Agh) + (size_t)(row0 + row) * lda + k0 + c8 * 8;
            cp16(dbase + (uint32_t)t * A_T + (uint32_t)(row * 80 + c8 * 16), src);
        }
#pragma unroll
        for (int it = 0; it < 2; it++) {     // B: 1024 cp16
            int idx = it * 512 + tid;
            int row = idx >> 2, c8 = idx & 3;
            const fp16* src = Bg + (size_t)(col0 + row) * ldb + k0 + c8 * 8;
            cp16(dbase + 2 * A_T + (uint32_t)(row * 80 + c8 * 16), src);
        }
    };

    float acc[2][8][4];
#pragma unroll
    for (int mi = 0; mi < 2; mi++)
#pragma unroll
        for (int nj = 0; nj < 8; nj++)
#pragma unroll
            for (int c = 0; c < 4; c++) acc[mi][nj][c] = 0.f;

    const int NC = K >> 5;
#pragma unroll
    for (int i = 0; i < 3; i++) {
        if (i < NC) load_chunk(i, i);
        asm volatile("cp.async.commit_group;" ::: "memory");
    }

    for (int kc = 0; kc < NC; kc++) {
        asm volatile("cp.async.wait_group 2;" ::: "memory");
        __syncthreads();
        if (kc + 3 < NC) load_chunk(kc + 3, (kc + 3) & 3);
        asm volatile("cp.async.commit_group;" ::: "memory");

        const uint32_t cbase = sbase + (uint32_t)(kc & 3) * STAGE_B;

        uint32_t ah[2][2][4], al[2][2][4];   // [ks buf][mi]
        uint32_t bh[2][4];                   // [ni buf]
#define LDA(bufi, kss) do { \
        _Pragma("unroll") \
        for (int mi = 0; mi < 2; mi++) { \
            uint32_t ad = cbase + (uint32_t)((warp_m * 32 + mi * 16) * 80 + (kss) * 32) + a_off; \
            ldsm4(ah[bufi][mi], ad); \
            ldsm4(al[bufi][mi], ad + A_T); \
        } } while (0)
#define LDB(bufi, kss, nii) \
        ldsm4(bh[bufi], cbase + 2 * A_T + \
              (uint32_t)((warp_n * 64 + (nii) * 16) * 80 + (kss) * 32) + b_off)

        LDA(0, 0);
        LDB(0, 0, 0);
#pragma unroll
        for (int ks = 0; ks < 2; ks++) {
#pragma unroll
            for (int ni = 0; ni < 4; ni++) {
                const int bb = (ks * 4 + ni) & 1;
                if (ni < 3)       LDB(bb ^ 1, ks, ni + 1);
                else if (ks == 0) { LDA(1, 1); LDB(bb ^ 1, 1, 0); }
#pragma unroll
                for (int mi = 0; mi < 2; mi++)
#pragma unroll
                    for (int j = 0; j < 2; j++) {
                        const int nj = ni * 2 + j;
                        mma16816(acc[mi][nj], ah[ks][mi], &bh[bb][j * 2]);
                        mma16816(acc[mi][nj], al[ks][mi], &bh[bb][j * 2]);
                    }
            }
        }
#undef LDA
#undef LDB
        __syncthreads();
    }

    const int gid = lane >> 2, tig = lane & 3;
#pragma unroll
    for (int mi = 0; mi < 2; mi++) {
#pragma unroll
        for (int hh = 0; hh < 2; hh++) {
            const int r = row0 + warp_m * 32 + mi * 16 + gid + hh * 8;
#pragma unroll
            for (int nj = 0; nj < 8; nj++) {
                const int c = col0 + warp_n * 64 + nj * 8 + tig * 2;
                float v0 = acc[mi][nj][hh * 2 + 0] * alpha;
                float v1 = acc[mi][nj][hh * 2 + 1] * alpha;
                const size_t o = coff + (size_t)r * ldc + c;
                if (EPI == 0) {
                    C[o] = v0 + bias[c];
                    C[o + 1] = v1 + bias[c + 1];
                } else {
                    C[o] = v0;
                    C[o + 1] = v1;
                }
            }
        }
    }
}

// ===================== host-side launch =====================
extern "C" void kernel_launch(void* const* d_in, const int* in_sizes, int n_in,
                              void* d_out, int out_size) {
    const float* hidden = (const float*)d_in[0];
    const float* cosp   = (const float*)d_in[1];
    const float* sinp   = (const float*)d_in[2];
    const float* qkv_w  = (const float*)d_in[3];
    const float* qkv_b  = (const float*)d_in[4];
    const float* proj_w = (const float*)d_in[5];
    const float* proj_b = (const float*)d_in[6];
    const float* ln1_g  = (const float*)d_in[7];
    const float* ln1_b  = (const float*)d_in[8];
    const float* ln2_g  = (const float*)d_in[9];
    const float* ln2_b  = (const float*)d_in[10];
    const float* fc1_w  = (const float*)d_in[11];
    const float* fc1_b  = (const float*)d_in[12];
    const float* fc2_w  = (const float*)d_in[13];
    const float* fc2_b  = (const float*)d_in[14];

    float* x = (float*)d_out;

    float *p_qkv, *p_part, *p_part1;
    fp16 *p_hh, *p_hl, *p_qh, *p_ql, *p_k, *p_vt;
    fp16 *p_ah, *p_al, *p_mh, *p_ml;
    fp16 *wq, *wp, *w1, *w2;
    cudaGetSymbolAddress((void**)&p_qkv, g_qkv);
    cudaGetSymbolAddress((void**)&p_part, g_part);
    cudaGetSymbolAddress((void**)&p_part1, g_part1);
    cudaGetSymbolAddress((void**)&p_hh,  g_hh);   cudaGetSymbolAddress((void**)&p_hl, g_hl);
    cudaGetSymbolAddress((void**)&p_qh,  g_qh);   cudaGetSymbolAddress((void**)&p_ql, g_ql);
    cudaGetSymbolAddress((void**)&p_k,   g_k);    cudaGetSymbolAddress((void**)&p_vt, g_vt);
    cudaGetSymbolAddress((void**)&p_ah,  g_ah);   cudaGetSymbolAddress((void**)&p_al, g_al);
    cudaGetSymbolAddress((void**)&p_mh,  g_mh);   cudaGetSymbolAddress((void**)&p_ml, g_ml);
    cudaGetSymbolAddress((void**)&wq, g_wq);
    cudaGetSymbolAddress((void**)&wp, g_wp);
    cudaGetSymbolAddress((void**)&w1, g_w1);
    cudaGetSymbolAddress((void**)&w2, g_w2);

    float* pt[5] = {p_part, p_part + S_ * D_, p_part + 2 * (size_t)S_ * D_,
                    p_part + 3 * (size_t)S_ * D_, p_part + 4 * (size_t)S_ * D_};
    float* pt1[2] = {p_part1, p_part1 + (size_t)S_ * I_};

    cudaFuncSetAttribute((const void*)gemm_mma2<0>, cudaFuncAttributeMaxDynamicSharedMemorySize, GEMM2_SMEM);
    cudaFuncSetAttribute((const void*)gemm_mma2<5>, cudaFuncAttributeMaxDynamicSharedMemorySize, GEMM2_SMEM);
    cudaFuncSetAttribute((const void*)flash_kernel,  cudaFuncAttributeMaxDynamicSharedMemorySize, FLASH_SMEM);

    cudaMemcpyAsync(x, hidden, (size_t)S_ * D_ * sizeof(float), cudaMemcpyDeviceToDevice);

    for (int l = 0; l < 2; l++) {
        const float* qw = qkv_w + (size_t)l * D_ * NQKV_;
        const float* qb = qkv_b + (size_t)l * NQKV_;
        const float* pw = proj_w + (size_t)l * D_ * D_;
        const float* pb = proj_b + (size_t)l * D_;
        const float* g1 = ln1_g + (size_t)l * D_;
        const float* b1 = ln1_b + (size_t)l * D_;
        const float* g2 = ln2_g + (size_t)l * D_;
        const float* b2 = ln2_b + (size_t)l * D_;
        const float* f1w = fc1_w + (size_t)l * D_ * I_;
        const float* f1b = fc1_b + (size_t)l * I_;
        const float* f2w = fc2_w + (size_t)l * I_ * D_;
        const float* f2b = fc2_b + (size_t)l * D_;

        // LN1: layer 0 standalone (layer 1's LN1 fused into layer 0's fc2 reduce)
        if (l == 0)
            ln_split_kernel<<<S_, 256>>>(x, g1, b1, p_hh, p_hl);

        // weight prep before qkv (keeps ncu slot #4 on the qkv GEMM)
        wsplit_T_kernel<<<dim3(NQKV_ / 32, D_ / 32), dim3(32, 8)>>>(qw, wq, D_, NQKV_);
        wsplit_T_kernel<<<dim3(D_ / 32, D_ / 32), dim3(32, 8)>>>(pw, wp, D_, D_);

        // qkv = h @ W_qkv + b   (fp32 out)
        gemm_mma2<0><<<dim3(NQKV_ / 256, S_ / 128, 1), 512, GEMM2_SMEM>>>(
            p_hh, p_hl, wq, qb, p_qkv,
            D_, D_, D_, NQKV_, 0, 0, 0, 1.f);

        // RoPE + split/round + V^T (+zero pad)
        rope_split_kernel<<<(S_ * H_ * HDP_ + 255) / 256, 256>>>(
            p_qkv, cosp, sinp, p_qh, p_ql, p_k, p_vt);

        // fused flash attention -> attn out split in [S, D]
        flash_kernel<<<dim3(S_ / 128, H_), 256, FLASH_SMEM>>>(
            p_qh, p_ql, p_k, p_vt, p_ah, p_al);

        // proj: split-K=5 (400 CTAs), then fused reduce+LN2
        gemm_mma2<5><<<dim3(D_ / 256, S_ / 128, 5), 512, GEMM2_SMEM>>>(
            p_ah, p_al, wp, nullptr, pt[0],
            D_ / 5, D_, D_, D_, D_ / 5, D_ / 5, (long long)S_ * D_, 1.f);
        reduce5_ln_kernel<<<S_, 256>>>(pt[0], pt[1], pt[2], pt[3], pt[4],
                                       pb, x, g2, b2, p_hh, p_hl);

        // fc1: split-K=2 (640 CTAs), then reduce+bias+gelu+split
        wsplit_T_kernel<<<dim3(I_ / 32, D_ / 32), dim3(32, 8)>>>(f1w, w1, D_, I_);
        gemm_mma2<5><<<dim3(I_ / 256, S_ / 128, 2), 512, GEMM2_SMEM>>>(
            p_hh, p_hl, w1, nullptr, pt1[0],
            D_ / 2, D_, D_, I_, D_ / 2, D_ / 2, (long long)S_ * I_, 1.f);
        reduce2_gelu_kernel<<<(S_ * I_ + 255) / 256, 256>>>(pt1[0], pt1[1], f1b, p_mh, p_ml);

        // fc2: split-K=5 (400 CTAs)
        wsplit_T_kernel<<<dim3(D_ / 32, I_ / 32), dim3(32, 8)>>>(f2w, w2, I_, D_);
        gemm_mma2<5><<<dim3(D_ / 256, S_ / 128, 5), 512, GEMM2_SMEM>>>(
            p_mh, p_ml, w2, nullptr, pt[0],
            I_ / 5, I_, I_, D_, I_ / 5, I_ / 5, (long long)S_ * D_, 1.f);
        if (l == 0) {
            reduce5_ln_kernel<<<S_, 256>>>(pt[0], pt[1], pt[2], pt[3], pt[4],
                                           f2b, x, ln1_g + D_, ln1_b + D_, p_hh, p_hl);
        } else {
            reduce5_kernel<<<(S_ * D_ + 255) / 256, 256>>>(pt[0], pt[1], pt[2], pt[3], pt[4],
                                                           f2b, x);
        }
    }
}

// round 16
// speedup vs baseline: 2.8793x; 1.3712x over previous
#include <cuda_runtime.h>
#include <cuda_fp16.h>
#include <math.h>
#include <stdint.h>

// Problem constants
#define S_ 2048
#define D_ 1280
#define H_ 16
#define HD_ 80
#define HDP_ 96           // padded head dim (3 chunks of 32)
#define I_ 5120
#define NQKV_ 3840
#define EPS_ 1e-6f
#define SCALE_ 0.11180339887498949f  // 80^-0.5

typedef __half fp16;

// ===================== device scratch (no allocation allowed) =====================
__device__ float g_qkv[S_ * NQKV_];                  // qkv proj fp32
__device__ float g_part[5][S_ * D_];                 // split-K partials
__device__ float g_part1[2][S_ * I_];                // fc1 split-K partials
__device__ fp16  g_h[S_ * D_];                       // LN out (single fp16)
__device__ fp16  g_qh[H_ * S_ * HDP_], g_ql[H_ * S_ * HDP_];  // Q split (flash)
__device__ fp16  g_k [H_ * S_ * HDP_];               // K single fp16
__device__ fp16  g_vt[H_ * HD_ * S_];                // V^T single fp16
__device__ fp16  g_a[S_ * D_];                       // attn out single
__device__ fp16  g_m[S_ * I_];                       // mlp hidden single
__device__ fp16  g_wq[NQKV_ * D_];                   // weights fp16 (transposed)
__device__ fp16  g_wp[D_ * D_];
__device__ fp16  g_w1[I_ * D_];
__device__ fp16  g_w2[D_ * I_];

__device__ __forceinline__ void fsplit(float v, fp16& h, fp16& l) {
    h = __float2half_rn(v);
    l = __float2half_rn(v - __half2float(h));
}

__device__ __forceinline__ uint32_t packh(float a, float b) {
    __half2 t = __floats2half2_rn(a, b);
    return *reinterpret_cast<uint32_t*>(&t);
}

__device__ __forceinline__ uint32_t smem_to_u32(const void* smem_ptr) {
    uint32_t addr;
    asm("{ .reg .u64 tmp; cvta.to.shared.u64 tmp, %1; cvt.u32.u64 %0, tmp; }"
        : "=r"(addr) : "l"(smem_ptr));
    return addr;
}

__device__ __forceinline__ void ldsm4(uint32_t (&r)[4], uint32_t addr) {
    asm volatile("ldmatrix.sync.aligned.m8n8.x4.shared.b16 {%0,%1,%2,%3}, [%4];"
                 : "=r"(r[0]), "=r"(r[1]), "=r"(r[2]), "=r"(r[3]) : "r"(addr));
}

__device__ __forceinline__ void mma16816(float (&d)[4], const uint32_t (&a)[4],
                                         const uint32_t* b) {
    asm volatile(
        "mma.sync.aligned.m16n8k16.row.col.f32.f16.f16.f32 "
        "{%0,%1,%2,%3}, {%4,%5,%6,%7}, {%8,%9}, {%0,%1,%2,%3};"
        : "+f"(d[0]), "+f"(d[1]), "+f"(d[2]), "+f"(d[3])
        : "r"(a[0]), "r"(a[1]), "r"(a[2]), "r"(a[3]), "r"(b[0]), "r"(b[1]));
}

__device__ __forceinline__ void cp16(uint32_t dst, const void* src) {
    asm volatile("cp.async.cg.shared.global [%0], [%1], 16;"
                 :: "r"(dst), "l"(src));
}

// ===================== LayerNorm -> fp16 (single) =====================
__global__ void ln_kernel(const float* __restrict__ x,
                          const float* __restrict__ g,
                          const float* __restrict__ b,
                          fp16* __restrict__ oh) {
    const int row = blockIdx.x;
    const int t = threadIdx.x;
    __shared__ float srow[D_];
    __shared__ float red[256];

    float local = 0.f;
    for (int i = t; i < D_; i += 256) {
        float v = x[(size_t)row * D_ + i];
        srow[i] = v;
        local += v;
    }
    red[t] = local;
    __syncthreads();
    for (int s = 128; s > 0; s >>= 1) { if (t < s) red[t] += red[t + s]; __syncthreads(); }
    const float mean = red[0] * (1.0f / D_);
    __syncthreads();

    local = 0.f;
    for (int i = t; i < D_; i += 256) { float dv = srow[i] - mean; local += dv * dv; }
    red[t] = local;
    __syncthreads();
    for (int s = 128; s > 0; s >>= 1) { if (t < s) red[t] += red[t + s]; __syncthreads(); }
    const float inv = rsqrtf(red[0] * (1.0f / D_) + EPS_);

    for (int i = t; i < D_; i += 256) {
        float v = (srow[i] - mean) * inv * g[i] + b[i];
        oh[(size_t)row * D_ + i] = __float2half_rn(v);
    }
}

// ===================== split-K(5) reduce + residual + LayerNorm =====================
__global__ void reduce5_ln_kernel(const float* __restrict__ p0, const float* __restrict__ p1,
                                  const float* __restrict__ p2, const float* __restrict__ p3,
                                  const float* __restrict__ p4,
                                  const float* __restrict__ bias, float* __restrict__ x,
                                  const float* __restrict__ g, const float* __restrict__ b,
                                  fp16* __restrict__ oh) {
    const int row = blockIdx.x;
    const int t = threadIdx.x;
    __shared__ float srow[D_];
    __shared__ float red[256];

    float local = 0.f;
    for (int i = t; i < D_; i += 256) {
        const size_t o = (size_t)row * D_ + i;
        float v = x[o] + ((p0[o] + p1[o]) + (p2[o] + p3[o]) + p4[o]) + bias[i];
        x[o] = v;
        srow[i] = v;
        local += v;
    }
    red[t] = local;
    __syncthreads();
    for (int s = 128; s > 0; s >>= 1) { if (t < s) red[t] += red[t + s]; __syncthreads(); }
    const float mean = red[0] * (1.0f / D_);
    __syncthreads();

    local = 0.f;
    for (int i = t; i < D_; i += 256) { float dv = srow[i] - mean; local += dv * dv; }
    red[t] = local;
    __syncthreads();
    for (int s = 128; s > 0; s >>= 1) { if (t < s) red[t] += red[t + s]; __syncthreads(); }
    const float inv = rsqrtf(red[0] * (1.0f / D_) + EPS_);

    for (int i = t; i < D_; i += 256) {
        float v = (srow[i] - mean) * inv * g[i] + b[i];
        oh[(size_t)row * D_ + i] = __float2half_rn(v);
    }
}

// plain split-K(5) reduce: x += sum + bias (final output)
__global__ void reduce5_kernel(const float* __restrict__ p0, const float* __restrict__ p1,
                               const float* __restrict__ p2, const float* __restrict__ p3,
                               const float* __restrict__ p4,
                               const float* __restrict__ bias, float* __restrict__ x) {
    int i = blockIdx.x * blockDim.x + threadIdx.x;
    if (i >= S_ * D_) return;
    const int c = i % D_;
    x[i] = x[i] + ((p0[i] + p1[i]) + (p2[i] + p3[i]) + p4[i]) + bias[c];
}

// split-K(2) reduce + bias + gelu + fp16 round (fc1 epilogue)
__global__ void reduce2_gelu_kernel(const float* __restrict__ p0, const float* __restrict__ p1,
                                    const float* __restrict__ bias,
                                    fp16* __restrict__ mh) {
    int i = blockIdx.x * blockDim.x + threadIdx.x;
    if (i >= S_ * I_) return;
    const int c = i % I_;
    float v = p0[i] + p1[i] + bias[c];
    v = 0.5f * v * (1.0f + erff(v * 0.70710678118654752f));
    mh[i] = __float2half_rn(v);
}

// ===================== weight transpose + round: w[K][N] -> Wt[N][K] fp16 ===========
__global__ void wsplit_T_kernel(const float* __restrict__ w,
                                fp16* __restrict__ o, int K, int N) {
    __shared__ float tile[32][33];
    int k0 = blockIdx.y * 32, n0 = blockIdx.x * 32;
    int tx = threadIdx.x, ty = threadIdx.y;
#pragma unroll
    for (int j = 0; j < 4; j++)
        tile[ty + j * 8][tx] = w[(size_t)(k0 + ty + j * 8) * N + n0 + tx];
    __syncthreads();
#pragma unroll
    for (int j = 0; j < 4; j++) {
        int n = ty + j * 8;
        o[(size_t)(n0 + n) * K + k0 + tx] = __float2half_rn(tile[tx][n]);
    }
}

// ===================== RoPE + head split + V transpose (incl. zero pad) =============
__global__ void rope_split_kernel(const float* __restrict__ qkv,
                                  const float* __restrict__ cosp,
                                  const float* __restrict__ sinp,
                                  fp16* __restrict__ Qh, fp16* __restrict__ Ql,
                                  fp16* __restrict__ Kk, fp16* __restrict__ Vt) {
    int i = blockIdx.x * blockDim.x + threadIdx.x;
    if (i >= S_ * H_ * HDP_) return;
    const int s = i / (H_ * HDP_);
    const int r = i % (H_ * HDP_);
    const int h = r / HDP_;
    const int d = r % HDP_;

    const size_t oq = ((size_t)h * S_ + s) * HDP_ + d;
    if (d >= HD_) {
        const fp16 z = __float2half(0.f);
        Qh[oq] = z; Ql[oq] = z; Kk[oq] = z;
        return;
    }

    const float c = cosp[s * HD_ + d];
    const float sn = sinp[s * HD_ + d];
    const size_t base = (size_t)s * NQKV_;

    const int d2 = (d < HD_ / 2) ? d + HD_ / 2 : d - HD_ / 2;
    const float sign = (d < HD_ / 2) ? -1.f : 1.f;

    const float q  = qkv[base + h * HD_ + d];
    const float qp = qkv[base + h * HD_ + d2];
    const float k  = qkv[base + D_ + h * HD_ + d];
    const float kp = qkv[base + D_ + h * HD_ + d2];
    const float v  = qkv[base + 2 * D_ + h * HD_ + d];

    const float rq = q * c + sign * qp * sn;
    const float rk = k * c + sign * kp * sn;

    fp16 hh, ll;
    fsplit(rq, hh, ll); Qh[oq] = hh; Ql[oq] = ll;
    Kk[oq] = __float2half_rn(rk);
    Vt[((size_t)h * HD_ + d) * S_ + s] = __float2half_rn(v);
}

// ===================== fused flash attention (Q split 2-term, K/V/P single) =========
#define FL_PK 208
#define FL_PV 272
#define FL_KT (128 * FL_PK)             // 26624
#define FL_VT (80 * FL_PV)              // 21760
#define FL_STG (FL_KT + FL_VT)          // 48384
#define FLASH_SMEM (2 * FL_STG)         // 96768

__global__ void __launch_bounds__(256, 1)
flash_kernel(const fp16* __restrict__ Qh_, const fp16* __restrict__ Ql_,
             const fp16* __restrict__ K_, const fp16* __restrict__ Vt_,
             fp16* __restrict__ O_) {
    extern __shared__ __align__(16) char smem[];
    const uint32_t sbase = smem_to_u32(smem);
    const int tid = threadIdx.x;
    const int wid = tid >> 5;
    const int lane = tid & 31;
    const int h = blockIdx.y;
    const int q0 = blockIdx.x * 128;

    const fp16* Qhh = Qh_ + ((size_t)h * S_ + q0) * HDP_;
    const fp16* Qll = Ql_ + ((size_t)h * S_ + q0) * HDP_;
    const fp16* Kg  = K_  + (size_t)h * S_ * HDP_;
    const fp16* Vg  = Vt_ + (size_t)h * HD_ * S_;

#pragma unroll
    for (int it = 0; it < 12; it++) {
        int e = it * 256 + tid;
        int split = e >= 1536;
        int idx = split ? e - 1536 : e;
        int row = idx / 12, c = idx % 12;
        const fp16* src = (split ? Qll : Qhh) + (size_t)row * HDP_ + c * 8;
        cp16(sbase + (uint32_t)split * FL_STG + (uint32_t)(row * FL_PK + c * 16), src);
    }
    asm volatile("cp.async.commit_group;" ::: "memory");
    asm volatile("cp.async.wait_group 0;" ::: "memory");
    __syncthreads();

    const uint32_t a_off = (uint32_t)((lane & 15) * FL_PK + (lane >> 4) * 16);
    uint32_t qfh[6][4], qfl[6][4];
#pragma unroll
    for (int ks = 0; ks < 6; ks++) {
        uint32_t ad = sbase + (uint32_t)(wid * 16 * FL_PK + ks * 32) + a_off;
        ldsm4(qfh[ks], ad);
        ldsm4(qfl[ks], ad + FL_STG);
    }
    __syncthreads();

    auto load_kv = [&](int t, int stg) {
        const int k0 = t * 128;
        const uint32_t db = sbase + (uint32_t)stg * FL_STG;
#pragma unroll
        for (int it = 0; it < 6; it++) {
            int idx = it * 256 + tid;
            int row = idx / 12, c = idx % 12;
            const fp16* src = Kg + (size_t)(k0 + row) * HDP_ + c * 8;
            cp16(db + (uint32_t)(row * FL_PK + c * 16), src);
        }
#pragma unroll
        for (int it = 0; it < 5; it++) {
            int idx = it * 256 + tid;
            int row = idx / 16, c = idx % 16;
            const fp16* src = Vg + (size_t)row * S_ + k0 + c * 8;
            cp16(db + FL_KT + (uint32_t)(row * FL_PV + c * 16), src);
        }
    };

    const uint32_t bk_off = (uint32_t)((((lane & 7) | ((lane >> 4) << 3)) * FL_PK) +
                                       (((lane >> 3) & 1) * 16));
    const uint32_t bv_off = (uint32_t)((((lane & 7) | ((lane >> 4) << 3)) * FL_PV) +
                                       (((lane >> 3) & 1) * 16));

    float acc_o[10][4];
#pragma unroll
    for (int i = 0; i < 10; i++)
#pragma unroll
        for (int c = 0; c < 4; c++) acc_o[i][c] = 0.f;
    float m0 = -1e30f, m1 = -1e30f, sum0 = 0.f, sum1 = 0.f;
    const float SC2 = SCALE_ * 1.4426950408889634f;

    const int NT = S_ / 128;
    load_kv(0, 0);
    asm volatile("cp.async.commit_group;" ::: "memory");

    for (int t = 0; t < NT; t++) {
        const int buf = t & 1;
        if (t + 1 < NT) {
            load_kv(t + 1, buf ^ 1);
            asm volatile("cp.async.commit_group;" ::: "memory");
            asm volatile("cp.async.wait_group 1;" ::: "memory");
        } else {
            asm volatile("cp.async.wait_group 0;" ::: "memory");
        }
        __syncthreads();

        const uint32_t kb = sbase + (uint32_t)buf * FL_STG;
        const uint32_t vb = kb + FL_KT;

        float accs[16][4];
#pragma unroll
        for (int i = 0; i < 16; i++)
#pragma unroll
            for (int c = 0; c < 4; c++) accs[i][c] = 0.f;

        {
            uint32_t kh[2][4];
#define LDK(bufi, kss, nbb) \
            ldsm4(kh[bufi], kb + (uint32_t)((nbb) * 16 * FL_PK + (kss) * 32) + bk_off)
            LDK(0, 0, 0);
#pragma unroll
            for (int ks = 0; ks < 6; ks++) {
#pragma unroll
                for (int nb = 0; nb < 8; nb++) {
                    const int bb = (ks * 8 + nb) & 1;
                    if (nb < 7)      LDK(bb ^ 1, ks, nb + 1);
                    else if (ks < 5) LDK(bb ^ 1, ks + 1, 0);
#pragma unroll
                    for (int j = 0; j < 2; j++) {
                        mma16816(accs[nb * 2 + j], qfh[ks], &kh[bb][j * 2]);
                        mma16816(accs[nb * 2 + j], qfl[ks], &kh[bb][j * 2]);
                    }
                }
            }
#undef LDK
        }

        float tm0 = -1e30f, tm1 = -1e30f;
#pragma unroll
        for (int nj = 0; nj < 16; nj++) {
            tm0 = fmaxf(tm0, fmaxf(accs[nj][0], accs[nj][1]));
            tm1 = fmaxf(tm1, fmaxf(accs[nj][2], accs[nj][3]));
        }
        tm0 = fmaxf(tm0, __shfl_xor_sync(0xffffffff, tm0, 1));
        tm0 = fmaxf(tm0, __shfl_xor_sync(0xffffffff, tm0, 2));
        tm1 = fmaxf(tm1, __shfl_xor_sync(0xffffffff, tm1, 1));
        tm1 = fmaxf(tm1, __shfl_xor_sync(0xffffffff, tm1, 2));
        tm0 *= SC2; tm1 *= SC2;

        const float nm0 = fmaxf(m0, tm0), nm1 = fmaxf(m1, tm1);
        const float f0 = exp2f(m0 - nm0), f1 = exp2f(m1 - nm1);
        m0 = nm0; m1 = nm1;

        float rs0 = 0.f, rs1 = 0.f;
#pragma unroll
        for (int nj = 0; nj < 16; nj++) {
            accs[nj][0] = exp2f(fmaf(accs[nj][0], SC2, -m0));
            accs[nj][1] = exp2f(fmaf(accs[nj][1], SC2, -m0));
            accs[nj][2] = exp2f(fmaf(accs[nj][2], SC2, -m1));
            accs[nj][3] = exp2f(fmaf(accs[nj][3], SC2, -m1));
            rs0 += accs[nj][0] + accs[nj][1];
            rs1 += accs[nj][2] + accs[nj][3];
        }
        rs0 += __shfl_xor_sync(0xffffffff, rs0, 1);
        rs0 += __shfl_xor_sync(0xffffffff, rs0, 2);
        rs1 += __shfl_xor_sync(0xffffffff, rs1, 1);
        rs1 += __shfl_xor_sync(0xffffffff, rs1, 2);
        sum0 = sum0 * f0 + rs0;
        sum1 = sum1 * f1 + rs1;

#pragma unroll
        for (int i = 0; i < 10; i++) {
            acc_o[i][0] *= f0; acc_o[i][1] *= f0;
            acc_o[i][2] *= f1; acc_o[i][3] *= f1;
        }

#pragma unroll
        for (int kbk = 0; kbk < 8; kbk++) {
            uint32_t ah[4];
            {
                const float* p0 = accs[kbk * 2];
                const float* p1 = accs[kbk * 2 + 1];
                ah[0] = packh(p0[0], p0[1]); ah[1] = packh(p0[2], p0[3]);
                ah[2] = packh(p1[0], p1[1]); ah[3] = packh(p1[2], p1[3]);
            }
#pragma unroll
            for (int db = 0; db < 5; db++) {
                uint32_t vh[4];
                ldsm4(vh, vb + (uint32_t)(db * 16 * FL_PV + kbk * 32) + bv_off);
#pragma unroll
                for (int j = 0; j < 2; j++)
                    mma16816(acc_o[db * 2 + j], ah, &vh[j * 2]);
            }
        }
        __syncthreads();
    }

    const int gid = lane >> 2, tig = lane & 3;
    const float inv0 = 1.0f / sum0, inv1 = 1.0f / sum1;
    const int r0 = q0 + wid * 16 + gid;
    const int r1 = r0 + 8;
#pragma unroll
    for (int db = 0; db < 10; db++) {
        const int col = h * HD_ + db * 8 + tig * 2;
        size_t o0 = (size_t)r0 * D_ + col;
        size_t o1 = (size_t)r1 * D_ + col;
        O_[o0]     = __float2half_rn(acc_o[db][0] * inv0);
        O_[o0 + 1] = __float2half_rn(acc_o[db][1] * inv0);
        O_[o1]     = __float2half_rn(acc_o[db][2] * inv1);
        O_[o1 + 1] = __float2half_rn(acc_o[db][3] * inv1);
    }
}

// ===================== 128x256 fp16 1-term GEMM, 512 threads, BK=64, 3-stage ========
// C[M, N] = alpha * A[M,K] @ B[N,K]^T   (A, B single fp16)
// EPI: 0 = C=v+bias   5 = split-K partial store
#define PITCH 144                       // 64 elems * 2B + 16B pad (9x16B, coprime 8)
#define A_T64 (128 * PITCH)             // 18432
#define B_T64 (256 * PITCH)             // 36864
#define STAGE64 (A_T64 + B_T64)         // 55296
#define GEMM2_SMEM (3 * STAGE64)        // 165888

template <int EPI>
__global__ void __launch_bounds__(512, 1)
gemm_mma2(const fp16* __restrict__ Ag, const fp16* __restrict__ Bg,
          const float* __restrict__ bias,
          float* __restrict__ C,
          int K, int lda, int ldb, int ldc,
          long long sA, long long sB, long long sC, float alpha) {
    extern __shared__ __align__(16) char smem[];
    const uint32_t sbase = smem_to_u32(smem);
    const int tid = threadIdx.x;
    const int wid = tid >> 5;
    const int lane = tid & 31;
    const int warp_m = wid & 3;
    const int warp_n = wid >> 2;
    const int bz = blockIdx.z;

    Ag += (size_t)bz * sA;
    Bg += (size_t)bz * sB;
    const size_t coff = (size_t)bz * sC;
    const int row0 = blockIdx.y * 128;
    const int col0 = blockIdx.x * 256;

    const uint32_t a_off = (uint32_t)((lane & 15) * PITCH + (lane >> 4) * 16);
    const uint32_t b_off = (uint32_t)((((lane & 7) | ((lane >> 4) << 3)) * PITCH) +
                                      (((lane >> 3) & 1) * 16));

    auto load_chunk = [&](int kc, int stg) {
        const int k0 = kc << 6;
        const uint32_t dbase = sbase + (uint32_t)stg * STAGE64;
#pragma unroll
        for (int it = 0; it < 2; it++) {     // A: 128 rows * 8 chunks = 1024
            int idx = it * 512 + tid;
            int row = idx >> 3, c8 = idx & 7;
            const fp16* src = Ag + (size_t)(row0 + row) * lda + k0 + c8 * 8;
            cp16(dbase + (uint32_t)(row * PITCH + c8 * 16), src);
        }
#pragma unroll
        for (int it = 0; it < 4; it++) {     // B: 256 rows * 8 chunks = 2048
            int idx = it * 512 + tid;
            int row = idx >> 3, c8 = idx & 7;
            const fp16* src = Bg + (size_t)(col0 + row) * ldb + k0 + c8 * 8;
            cp16(dbase + A_T64 + (uint32_t)(row * PITCH + c8 * 16), src);
        }
    };

    float acc[2][8][4];
#pragma unroll
    for (int mi = 0; mi < 2; mi++)
#pragma unroll
        for (int nj = 0; nj < 8; nj++)
#pragma unroll
            for (int c = 0; c < 4; c++) acc[mi][nj][c] = 0.f;

    const int NC = K >> 6;
    load_chunk(0, 0);
    asm volatile("cp.async.commit_group;" ::: "memory");
    if (1 < NC) load_chunk(1, 1);
    asm volatile("cp.async.commit_group;" ::: "memory");

    int stg = 0;
    for (int kc = 0; kc < NC; kc++) {
        asm volatile("cp.async.wait_group 1;" ::: "memory");
        __syncthreads();
        if (kc + 2 < NC) load_chunk(kc + 2, (stg + 2 >= 3) ? stg - 1 : stg + 2);
        asm volatile("cp.async.commit_group;" ::: "memory");

        const uint32_t cbase = sbase + (uint32_t)stg * STAGE64;

        uint32_t ah[2][2][4];                // [ks buf][mi]
        uint32_t bh[2][4];                   // [ni buf]
#define LDA(bufi, kss) do { \
        _Pragma("unroll") \
        for (int mi = 0; mi < 2; mi++) { \
            ldsm4(ah[bufi][mi], cbase + \
                  (uint32_t)((warp_m * 32 + mi * 16) * PITCH + (kss) * 32) + a_off); \
        } } while (0)
#define LDB(bufi, kss, nii) \
        ldsm4(bh[bufi], cbase + A_T64 + \
              (uint32_t)((warp_n * 64 + (nii) * 16) * PITCH + (kss) * 32) + b_off)

        LDA(0, 0);
        LDB(0, 0, 0);
#pragma unroll
        for (int ks = 0; ks < 4; ks++) {
#pragma unroll
            for (int ni = 0; ni < 4; ni++) {
                const int bb = (ks * 4 + ni) & 1;
                if (ni < 3)       LDB(bb ^ 1, ks, ni + 1);
                else if (ks < 3)  { LDA((ks + 1) & 1, ks + 1); LDB(bb ^ 1, ks + 1, 0); }
#pragma unroll
                for (int mi = 0; mi < 2; mi++)
#pragma unroll
                    for (int j = 0; j < 2; j++)
                        mma16816(acc[mi][ni * 2 + j], ah[ks & 1][mi], &bh[bb][j * 2]);
            }
        }
#undef LDA
#undef LDB
        __syncthreads();
        stg = (stg + 1 >= 3) ? 0 : stg + 1;
    }

    const int gid = lane >> 2, tig = lane & 3;
#pragma unroll
    for (int mi = 0; mi < 2; mi++) {
#pragma unroll
        for (int hh = 0; hh < 2; hh++) {
            const int r = row0 + warp_m * 32 + mi * 16 + gid + hh * 8;
#pragma unroll
            for (int nj = 0; nj < 8; nj++) {
                const int c = col0 + warp_n * 64 + nj * 8 + tig * 2;
                float v0 = acc[mi][nj][hh * 2 + 0] * alpha;
                float v1 = acc[mi][nj][hh * 2 + 1] * alpha;
                const size_t o = coff + (size_t)r * ldc + c;
                if (EPI == 0) {
                    C[o] = v0 + bias[c];
                    C[o + 1] = v1 + bias[c + 1];
                } else {
                    C[o] = v0;
                    C[o + 1] = v1;
                }
            }
        }
    }
}

// ===================== host-side launch =====================
extern "C" void kernel_launch(void* const* d_in, const int* in_sizes, int n_in,
                              void* d_out, int out_size) {
    const float* hidden = (const float*)d_in[0];
    const float* cosp   = (const float*)d_in[1];
    const float* sinp   = (const float*)d_in[2];
    const float* qkv_w  = (const float*)d_in[3];
    const float* qkv_b  = (const float*)d_in[4];
    const float* proj_w = (const float*)d_in[5];
    const float* proj_b = (const float*)d_in[6];
    const float* ln1_g  = (const float*)d_in[7];
    const float* ln1_b  = (const float*)d_in[8];
    const float* ln2_g  = (const float*)d_in[9];
    const float* ln2_b  = (const float*)d_in[10];
    const float* fc1_w  = (const float*)d_in[11];
    const float* fc1_b  = (const float*)d_in[12];
    const float* fc2_w  = (const float*)d_in[13];
    const float* fc2_b  = (const float*)d_in[14];

    float* x = (float*)d_out;

    float *p_qkv, *p_part, *p_part1;
    fp16 *p_h, *p_qh, *p_ql, *p_k, *p_vt, *p_a, *p_m;
    fp16 *wq, *wp, *w1, *w2;
    cudaGetSymbolAddress((void**)&p_qkv, g_qkv);
    cudaGetSymbolAddress((void**)&p_part, g_part);
    cudaGetSymbolAddress((void**)&p_part1, g_part1);
    cudaGetSymbolAddress((void**)&p_h,  g_h);
    cudaGetSymbolAddress((void**)&p_qh, g_qh);   cudaGetSymbolAddress((void**)&p_ql, g_ql);
    cudaGetSymbolAddress((void**)&p_k,  g_k);    cudaGetSymbolAddress((void**)&p_vt, g_vt);
    cudaGetSymbolAddress((void**)&p_a,  g_a);    cudaGetSymbolAddress((void**)&p_m,  g_m);
    cudaGetSymbolAddress((void**)&wq, g_wq);
    cudaGetSymbolAddress((void**)&wp, g_wp);
    cudaGetSymbolAddress((void**)&w1, g_w1);
    cudaGetSymbolAddress((void**)&w2, g_w2);

    float* pt[5] = {p_part, p_part + S_ * D_, p_part + 2 * (size_t)S_ * D_,
                    p_part + 3 * (size_t)S_ * D_, p_part + 4 * (size_t)S_ * D_};
    float* pt1[2] = {p_part1, p_part1 + (size_t)S_ * I_};

    cudaFuncSetAttribute((const void*)gemm_mma2<0>, cudaFuncAttributeMaxDynamicSharedMemorySize, GEMM2_SMEM);
    cudaFuncSetAttribute((const void*)gemm_mma2<5>, cudaFuncAttributeMaxDynamicSharedMemorySize, GEMM2_SMEM);
    cudaFuncSetAttribute((const void*)flash_kernel,  cudaFuncAttributeMaxDynamicSharedMemorySize, FLASH_SMEM);

    cudaMemcpyAsync(x, hidden, (size_t)S_ * D_ * sizeof(float), cudaMemcpyDeviceToDevice);

    for (int l = 0; l < 2; l++) {
        const float* qw = qkv_w + (size_t)l * D_ * NQKV_;
        const float* qb = qkv_b + (size_t)l * NQKV_;
        const float* pw = proj_w + (size_t)l * D_ * D_;
        const float* pb = proj_b + (size_t)l * D_;
        const float* g1 = ln1_g + (size_t)l * D_;
        const float* b1 = ln1_b + (size_t)l * D_;
        const float* g2 = ln2_g + (size_t)l * D_;
        const float* b2 = ln2_b + (size_t)l * D_;
        const float* f1w = fc1_w + (size_t)l * D_ * I_;
        const float* f1b = fc1_b + (size_t)l * I_;
        const float* f2w = fc2_w + (size_t)l * I_ * D_;
        const float* f2b = fc2_b + (size_t)l * D_;

        if (l == 0)
            ln_kernel<<<S_, 256>>>(x, g1, b1, p_h);

        // weight prep before qkv (keeps ncu slot #4 on the qkv GEMM)
        wsplit_T_kernel<<<dim3(NQKV_ / 32, D_ / 32), dim3(32, 8)>>>(qw, wq, D_, NQKV_);
        wsplit_T_kernel<<<dim3(D_ / 32, D_ / 32), dim3(32, 8)>>>(pw, wp, D_, D_);

        // qkv = h @ W_qkv + b   (fp32 out)
        gemm_mma2<0><<<dim3(NQKV_ / 256, S_ / 128, 1), 512, GEMM2_SMEM>>>(
            p_h, wq, qb, p_qkv,
            D_, D_, D_, NQKV_, 0, 0, 0, 1.f);

        // RoPE + split/round + V^T (+zero pad)
        rope_split_kernel<<<(S_ * H_ * HDP_ + 255) / 256, 256>>>(
            p_qkv, cosp, sinp, p_qh, p_ql, p_k, p_vt);

        // fused flash attention -> attn out fp16 in [S, D]
        flash_kernel<<<dim3(S_ / 128, H_), 256, FLASH_SMEM>>>(
            p_qh, p_ql, p_k, p_vt, p_a);

        // proj: split-K=5 (K slices 256 = 4 chunks, 400 CTAs), fused reduce+LN2
        gemm_mma2<5><<<dim3(D_ / 256, S_ / 128, 5), 512, GEMM2_SMEM>>>(
            p_a, wp, nullptr, pt[0],
            D_ / 5, D_, D_, D_, D_ / 5, D_ / 5, (long long)S_ * D_, 1.f);
        reduce5_ln_kernel<<<S_, 256>>>(pt[0], pt[1], pt[2], pt[3], pt[4],
                                       pb, x, g2, b2, p_h);

        // fc1: split-K=2 (slices 640 = 10 chunks, 640 CTAs), reduce+bias+gelu
        wsplit_T_kernel<<<dim3(I_ / 32, D_ / 32), dim3(32, 8)>>>(f1w, w1, D_, I_);
        gemm_mma2<5><<<dim3(I_ / 256, S_ / 128, 2), 512, GEMM2_SMEM>>>(
            p_h, w1, nullptr, pt1[0],
            D_ / 2, D_, D_, I_, D_ / 2, D_ / 2, (long long)S_ * I_, 1.f);
        reduce2_gelu_kernel<<<(S_ * I_ + 255) / 256, 256>>>(pt1[0], pt1[1], f1b, p_m);

        // fc2: split-K=5 (slices 1024 = 16 chunks, 400 CTAs)
        wsplit_T_kernel<<<dim3(D_ / 32, I_ / 32), dim3(32, 8)>>>(f2w, w2, I_, D_);
        gemm_mma2<5><<<dim3(D_ / 256, S_ / 128, 5), 512, GEMM2_SMEM>>>(
            p_m, w2, nullptr, pt[0],
            I_ / 5, I_, I_, D_, I_ / 5, I_ / 5, (long long)S_ * D_, 1.f);
        if (l == 0) {
            reduce5_ln_kernel<<<S_, 256>>>(pt[0], pt[1], pt[2], pt[3], pt[4],
                                           f2b, x, ln1_g + D_, ln1_b + D_, p_h);
        } else {
            reduce5_kernel<<<(S_ * D_ + 255) / 256, 256>>>(pt[0], pt[1], pt[2], pt[3], pt[4],
                                                           f2b, x);
        }
    }
}

// round 17
// speedup vs baseline: 3.0497x; 1.0592x over previous
#include <cuda_runtime.h>
#include <cuda_fp16.h>
#include <math.h>
#include <stdint.h>

// Problem constants
#define S_ 2048
#define D_ 1280
#define H_ 16
#define HD_ 80
#define HDP_ 96           // padded head dim (3 chunks of 32)
#define I_ 5120
#define NQKV_ 3840
#define EPS_ 1e-6f
#define SCALE_ 0.11180339887498949f  // 80^-0.5

typedef __half fp16;

// ===================== device scratch (no allocation allowed) =====================
__device__ float g_qkv[S_ * NQKV_];                  // qkv proj fp32
__device__ float g_part[2][S_ * D_];                 // split-K partials
__device__ fp16  g_h[S_ * D_];                       // LN out (single fp16)
__device__ fp16  g_qh[H_ * S_ * HDP_], g_ql[H_ * S_ * HDP_];  // Q split (flash)
__device__ fp16  g_k [H_ * S_ * HDP_];               // K single fp16
__device__ fp16  g_vt[H_ * HD_ * S_];                // V^T single fp16
__device__ fp16  g_a[S_ * D_];                       // attn out single
__device__ fp16  g_m[S_ * I_];                       // mlp hidden single
__device__ fp16  g_wq[NQKV_ * D_];                   // weights fp16 (transposed)
__device__ fp16  g_wp[D_ * D_];
__device__ fp16  g_w1[I_ * D_];
__device__ fp16  g_w2[D_ * I_];

__device__ __forceinline__ void fsplit(float v, fp16& h, fp16& l) {
    h = __float2half_rn(v);
    l = __float2half_rn(v - __half2float(h));
}

__device__ __forceinline__ uint32_t packh(float a, float b) {
    __half2 t = __floats2half2_rn(a, b);
    return *reinterpret_cast<uint32_t*>(&t);
}

__device__ __forceinline__ uint32_t smem_to_u32(const void* smem_ptr) {
    uint32_t addr;
    asm("{ .reg .u64 tmp; cvta.to.shared.u64 tmp, %1; cvt.u32.u64 %0, tmp; }"
        : "=r"(addr) : "l"(smem_ptr));
    return addr;
}

__device__ __forceinline__ void ldsm4(uint32_t (&r)[4], uint32_t addr) {
    asm volatile("ldmatrix.sync.aligned.m8n8.x4.shared.b16 {%0,%1,%2,%3}, [%4];"
                 : "=r"(r[0]), "=r"(r[1]), "=r"(r[2]), "=r"(r[3]) : "r"(addr));
}

__device__ __forceinline__ void mma16816(float (&d)[4], const uint32_t (&a)[4],
                                         const uint32_t* b) {
    asm volatile(
        "mma.sync.aligned.m16n8k16.row.col.f32.f16.f16.f32 "
        "{%0,%1,%2,%3}, {%4,%5,%6,%7}, {%8,%9}, {%0,%1,%2,%3};"
        : "+f"(d[0]), "+f"(d[1]), "+f"(d[2]), "+f"(d[3])
        : "r"(a[0]), "r"(a[1]), "r"(a[2]), "r"(a[3]), "r"(b[0]), "r"(b[1]));
}

__device__ __forceinline__ void cp16(uint32_t dst, const void* src) {
    asm volatile("cp.async.cg.shared.global [%0], [%1], 16;"
                 :: "r"(dst), "l"(src));
}

// ===================== LayerNorm -> fp16 (single) =====================
__global__ void ln_kernel(const float* __restrict__ x,
                          const float* __restrict__ g,
                          const float* __restrict__ b,
                          fp16* __restrict__ oh) {
    const int row = blockIdx.x;
    const int t = threadIdx.x;
    __shared__ float srow[D_];
    __shared__ float red[256];

    float local = 0.f;
    for (int i = t; i < D_; i += 256) {
        float v = x[(size_t)row * D_ + i];
        srow[i] = v;
        local += v;
    }
    red[t] = local;
    __syncthreads();
    for (int s = 128; s > 0; s >>= 1) { if (t < s) red[t] += red[t + s]; __syncthreads(); }
    const float mean = red[0] * (1.0f / D_);
    __syncthreads();

    local = 0.f;
    for (int i = t; i < D_; i += 256) { float dv = srow[i] - mean; local += dv * dv; }
    red[t] = local;
    __syncthreads();
    for (int s = 128; s > 0; s >>= 1) { if (t < s) red[t] += red[t + s]; __syncthreads(); }
    const float inv = rsqrtf(red[0] * (1.0f / D_) + EPS_);

    for (int i = t; i < D_; i += 256) {
        float v = (srow[i] - mean) * inv * g[i] + b[i];
        oh[(size_t)row * D_ + i] = __float2half_rn(v);
    }
}

// ===================== split-K(2) reduce + residual + LayerNorm =====================
__global__ void reduce2_ln_kernel(const float* __restrict__ p0, const float* __restrict__ p1,
                                  const float* __restrict__ bias, float* __restrict__ x,
                                  const float* __restrict__ g, const float* __restrict__ b,
                                  fp16* __restrict__ oh) {
    const int row = blockIdx.x;
    const int t = threadIdx.x;
    __shared__ float srow[D_];
    __shared__ float red[256];

    float local = 0.f;
    for (int i = t; i < D_; i += 256) {
        const size_t o = (size_t)row * D_ + i;
        float v = x[o] + (p0[o] + p1[o]) + bias[i];
        x[o] = v;
        srow[i] = v;
        local += v;
    }
    red[t] = local;
    __syncthreads();
    for (int s = 128; s > 0; s >>= 1) { if (t < s) red[t] += red[t + s]; __syncthreads(); }
    const float mean = red[0] * (1.0f / D_);
    __syncthreads();

    local = 0.f;
    for (int i = t; i < D_; i += 256) { float dv = srow[i] - mean; local += dv * dv; }
    red[t] = local;
    __syncthreads();
    for (int s = 128; s > 0; s >>= 1) { if (t < s) red[t] += red[t + s]; __syncthreads(); }
    const float inv = rsqrtf(red[0] * (1.0f / D_) + EPS_);

    for (int i = t; i < D_; i += 256) {
        float v = (srow[i] - mean) * inv * g[i] + b[i];
        oh[(size_t)row * D_ + i] = __float2half_rn(v);
    }
}

// plain split-K(2) reduce: x += p0+p1 + bias (final output)
__global__ void reduce2_kernel(const float* __restrict__ p0, const float* __restrict__ p1,
                               const float* __restrict__ bias, float* __restrict__ x) {
    int i = blockIdx.x * blockDim.x + threadIdx.x;
    if (i >= S_ * D_) return;
    const int c = i % D_;
    x[i] = x[i] + (p0[i] + p1[i]) + bias[c];
}

// ===================== weight transpose + round: w[K][N] -> Wt[N][K] fp16 ===========
__global__ void wsplit_T_kernel(const float* __restrict__ w,
                                fp16* __restrict__ o, int K, int N) {
    __shared__ float tile[32][33];
    int k0 = blockIdx.y * 32, n0 = blockIdx.x * 32;
    int tx = threadIdx.x, ty = threadIdx.y;
#pragma unroll
    for (int j = 0; j < 4; j++)
        tile[ty + j * 8][tx] = w[(size_t)(k0 + ty + j * 8) * N + n0 + tx];
    __syncthreads();
#pragma unroll
    for (int j = 0; j < 4; j++) {
        int n = ty + j * 8;
        o[(size_t)(n0 + n) * K + k0 + tx] = __float2half_rn(tile[tx][n]);
    }
}

// ===================== RoPE + head split + V transpose (incl. zero pad) =============
__global__ void rope_split_kernel(const float* __restrict__ qkv,
                                  const float* __restrict__ cosp,
                                  const float* __restrict__ sinp,
                                  fp16* __restrict__ Qh, fp16* __restrict__ Ql,
                                  fp16* __restrict__ Kk, fp16* __restrict__ Vt) {
    int i = blockIdx.x * blockDim.x + threadIdx.x;
    if (i >= S_ * H_ * HDP_) return;
    const int s = i / (H_ * HDP_);
    const int r = i % (H_ * HDP_);
    const int h = r / HDP_;
    const int d = r % HDP_;

    const size_t oq = ((size_t)h * S_ + s) * HDP_ + d;
    if (d >= HD_) {
        const fp16 z = __float2half(0.f);
        Qh[oq] = z; Ql[oq] = z; Kk[oq] = z;
        return;
    }

    const float c = cosp[s * HD_ + d];
    const float sn = sinp[s * HD_ + d];
    const size_t base = (size_t)s * NQKV_;

    const int d2 = (d < HD_ / 2) ? d + HD_ / 2 : d - HD_ / 2;
    const float sign = (d < HD_ / 2) ? -1.f : 1.f;

    const float q  = qkv[base + h * HD_ + d];
    const float qp = qkv[base + h * HD_ + d2];
    const float k  = qkv[base + D_ + h * HD_ + d];
    const float kp = qkv[base + D_ + h * HD_ + d2];
    const float v  = qkv[base + 2 * D_ + h * HD_ + d];

    const float rq = q * c + sign * qp * sn;
    const float rk = k * c + sign * kp * sn;

    fp16 hh, ll;
    fsplit(rq, hh, ll); Qh[oq] = hh; Ql[oq] = ll;
    Kk[oq] = __float2half_rn(rk);
    Vt[((size_t)h * HD_ + d) * S_ + s] = __float2half_rn(v);
}

// ===================== fused flash attention (Q split 2-term, K/V/P single) =========
#define FL_PK 208
#define FL_PV 272
#define FL_KT (128 * FL_PK)             // 26624
#define FL_VT (80 * FL_PV)              // 21760
#define FL_STG (FL_KT + FL_VT)          // 48384
#define FLASH_SMEM (2 * FL_STG)         // 96768

__global__ void __launch_bounds__(256, 1)
flash_kernel(const fp16* __restrict__ Qh_, const fp16* __restrict__ Ql_,
             const fp16* __restrict__ K_, const fp16* __restrict__ Vt_,
             fp16* __restrict__ O_) {
    extern __shared__ __align__(16) char smem[];
    const uint32_t sbase = smem_to_u32(smem);
    const int tid = threadIdx.x;
    const int wid = tid >> 5;
    const int lane = tid & 31;
    const int h = blockIdx.y;
    const int q0 = blockIdx.x * 128;

    const fp16* Qhh = Qh_ + ((size_t)h * S_ + q0) * HDP_;
    const fp16* Qll = Ql_ + ((size_t)h * S_ + q0) * HDP_;
    const fp16* Kg  = K_  + (size_t)h * S_ * HDP_;
    const fp16* Vg  = Vt_ + (size_t)h * HD_ * S_;

#pragma unroll
    for (int it = 0; it < 12; it++) {
        int e = it * 256 + tid;
        int split = e >= 1536;
        int idx = split ? e - 1536 : e;
        int row = idx / 12, c = idx % 12;
        const fp16* src = (split ? Qll : Qhh) + (size_t)row * HDP_ + c * 8;
        cp16(sbase + (uint32_t)split * FL_STG + (uint32_t)(row * FL_PK + c * 16), src);
    }
    asm volatile("cp.async.commit_group;" ::: "memory");
    asm volatile("cp.async.wait_group 0;" ::: "memory");
    __syncthreads();

    const uint32_t a_off = (uint32_t)((lane & 15) * FL_PK + (lane >> 4) * 16);
    uint32_t qfh[6][4], qfl[6][4];
#pragma unroll
    for (int ks = 0; ks < 6; ks++) {
        uint32_t ad = sbase + (uint32_t)(wid * 16 * FL_PK + ks * 32) + a_off;
        ldsm4(qfh[ks], ad);
        ldsm4(qfl[ks], ad + FL_STG);
    }
    __syncthreads();

    auto load_kv = [&](int t, int stg) {
        const int k0 = t * 128;
        const uint32_t db = sbase + (uint32_t)stg * FL_STG;
#pragma unroll
        for (int it = 0; it < 6; it++) {
            int idx = it * 256 + tid;
            int row = idx / 12, c = idx % 12;
            const fp16* src = Kg + (size_t)(k0 + row) * HDP_ + c * 8;
            cp16(db + (uint32_t)(row * FL_PK + c * 16), src);
        }
#pragma unroll
        for (int it = 0; it < 5; it++) {
            int idx = it * 256 + tid;
            int row = idx / 16, c = idx % 16;
            const fp16* src = Vg + (size_t)row * S_ + k0 + c * 8;
            cp16(db + FL_KT + (uint32_t)(row * FL_PV + c * 16), src);
        }
    };

    const uint32_t bk_off = (uint32_t)((((lane & 7) | ((lane >> 4) << 3)) * FL_PK) +
                                       (((lane >> 3) & 1) * 16));
    const uint32_t bv_off = (uint32_t)((((lane & 7) | ((lane >> 4) << 3)) * FL_PV) +
                                       (((lane >> 3) & 1) * 16));

    float acc_o[10][4];
#pragma unroll
    for (int i = 0; i < 10; i++)
#pragma unroll
        for (int c = 0; c < 4; c++) acc_o[i][c] = 0.f;
    float m0 = -1e30f, m1 = -1e30f, sum0 = 0.f, sum1 = 0.f;
    const float SC2 = SCALE_ * 1.4426950408889634f;

    const int NT = S_ / 128;
    load_kv(0, 0);
    asm volatile("cp.async.commit_group;" ::: "memory");

    for (int t = 0; t < NT; t++) {
        const int buf = t & 1;
        if (t + 1 < NT) {
            load_kv(t + 1, buf ^ 1);
            asm volatile("cp.async.commit_group;" ::: "memory");
            asm volatile("cp.async.wait_group 1;" ::: "memory");
        } else {
            asm volatile("cp.async.wait_group 0;" ::: "memory");
        }
        __syncthreads();

        const uint32_t kb = sbase + (uint32_t)buf * FL_STG;
        const uint32_t vb = kb + FL_KT;

        float accs[16][4];
#pragma unroll
        for (int i = 0; i < 16; i++)
#pragma unroll
            for (int c = 0; c < 4; c++) accs[i][c] = 0.f;

        {
            uint32_t kh[2][4];
#define LDK(bufi, kss, nbb) \
            ldsm4(kh[bufi], kb + (uint32_t)((nbb) * 16 * FL_PK + (kss) * 32) + bk_off)
            LDK(0, 0, 0);
#pragma unroll
            for (int ks = 0; ks < 6; ks++) {
#pragma unroll
                for (int nb = 0; nb < 8; nb++) {
                    const int bb = (ks * 8 + nb) & 1;
                    if (nb < 7)      LDK(bb ^ 1, ks, nb + 1);
                    else if (ks < 5) LDK(bb ^ 1, ks + 1, 0);
#pragma unroll
                    for (int j = 0; j < 2; j++) {
                        mma16816(accs[nb * 2 + j], qfh[ks], &kh[bb][j * 2]);
                        mma16816(accs[nb * 2 + j], qfl[ks], &kh[bb][j * 2]);
                    }
                }
            }
#undef LDK
        }

        float tm0 = -1e30f, tm1 = -1e30f;
#pragma unroll
        for (int nj = 0; nj < 16; nj++) {
            tm0 = fmaxf(tm0, fmaxf(accs[nj][0], accs[nj][1]));
            tm1 = fmaxf(tm1, fmaxf(accs[nj][2], accs[nj][3]));
        }
        tm0 = fmaxf(tm0, __shfl_xor_sync(0xffffffff, tm0, 1));
        tm0 = fmaxf(tm0, __shfl_xor_sync(0xffffffff, tm0, 2));
        tm1 = fmaxf(tm1, __shfl_xor_sync(0xffffffff, tm1, 1));
        tm1 = fmaxf(tm1, __shfl_xor_sync(0xffffffff, tm1, 2));
        tm0 *= SC2; tm1 *= SC2;

        const float nm0 = fmaxf(m0, tm0), nm1 = fmaxf(m1, tm1);
        const float f0 = exp2f(m0 - nm0), f1 = exp2f(m1 - nm1);
        m0 = nm0; m1 = nm1;

        float rs0 = 0.f, rs1 = 0.f;
#pragma unroll
        for (int nj = 0; nj < 16; nj++) {
            accs[nj][0] = exp2f(fmaf(accs[nj][0], SC2, -m0));
            accs[nj][1] = exp2f(fmaf(accs[nj][1], SC2, -m0));
            accs[nj][2] = exp2f(fmaf(accs[nj][2], SC2, -m1));
            accs[nj][3] = exp2f(fmaf(accs[nj][3], SC2, -m1));
            rs0 += accs[nj][0] + accs[nj][1];
            rs1 += accs[nj][2] + accs[nj][3];
        }
        rs0 += __shfl_xor_sync(0xffffffff, rs0, 1);
        rs0 += __shfl_xor_sync(0xffffffff, rs0, 2);
        rs1 += __shfl_xor_sync(0xffffffff, rs1, 1);
        rs1 += __shfl_xor_sync(0xffffffff, rs1, 2);
        sum0 = sum0 * f0 + rs0;
        sum1 = sum1 * f1 + rs1;

#pragma unroll
        for (int i = 0; i < 10; i++) {
            acc_o[i][0] *= f0; acc_o[i][1] *= f0;
            acc_o[i][2] *= f1; acc_o[i][3] *= f1;
        }

#pragma unroll
        for (int kbk = 0; kbk < 8; kbk++) {
            uint32_t ah[4];
            {
                const float* p0 = accs[kbk * 2];
                const float* p1 = accs[kbk * 2 + 1];
                ah[0] = packh(p0[0], p0[1]); ah[1] = packh(p0[2], p0[3]);
                ah[2] = packh(p1[0], p1[1]); ah[3] = packh(p1[2], p1[3]);
            }
#pragma unroll
            for (int db = 0; db < 5; db++) {
                uint32_t vh[4];
                ldsm4(vh, vb + (uint32_t)(db * 16 * FL_PV + kbk * 32) + bv_off);
#pragma unroll
                for (int j = 0; j < 2; j++)
                    mma16816(acc_o[db * 2 + j], ah, &vh[j * 2]);
            }
        }
        __syncthreads();
    }

    const int gid = lane >> 2, tig = lane & 3;
    const float inv0 = 1.0f / sum0, inv1 = 1.0f / sum1;
    const int r0 = q0 + wid * 16 + gid;
    const int r1 = r0 + 8;
#pragma unroll
    for (int db = 0; db < 10; db++) {
        const int col = h * HD_ + db * 8 + tig * 2;
        size_t o0 = (size_t)r0 * D_ + col;
        size_t o1 = (size_t)r1 * D_ + col;
        O_[o0]     = __float2half_rn(acc_o[db][0] * inv0);
        O_[o0 + 1] = __float2half_rn(acc_o[db][1] * inv0);
        O_[o1]     = __float2half_rn(acc_o[db][2] * inv1);
        O_[o1 + 1] = __float2half_rn(acc_o[db][3] * inv1);
    }
}

// ===================== 128x128 fp16 GEMM, 256 threads, BK=64, 3-stage, 2 CTA/SM ====
// C[M, N] = alpha * A[M,K] @ B[N,K]^T
// EPI: 0 = C=v+bias (fp32)   4 = gelu(v+bias) -> fp16 Ch   5 = partial store fp32
#define PITCH 144                       // 64 elems * 2B + 16B pad
#define T128 (128 * PITCH)              // 18432
#define STAGE1 (2 * T128)               // 36864 (A + B)
#define GEMM_SMEM (3 * STAGE1)          // 110592

template <int EPI>
__global__ void __launch_bounds__(256, 2)
gemm_mma(const fp16* __restrict__ Ag, const fp16* __restrict__ Bg,
         const float* __restrict__ bias,
         float* __restrict__ C, fp16* __restrict__ Ch,
         int K, int lda, int ldb, int ldc,
         long long sA, long long sB, long long sC, float alpha) {
    extern __shared__ __align__(16) char smem[];
    const uint32_t sbase = smem_to_u32(smem);
    const int tid = threadIdx.x;
    const int wid = tid >> 5;
    const int lane = tid & 31;
    const int warp_m = wid & 3;    // 4 x 32 rows
    const int warp_n = wid >> 2;   // 2 x 64 cols
    const int bz = blockIdx.z;

    Ag += (size_t)bz * sA;
    Bg += (size_t)bz * sB;
    const size_t coff = (size_t)bz * sC;
    const int row0 = blockIdx.y * 128;
    const int col0 = blockIdx.x * 128;

    const uint32_t a_off = (uint32_t)((lane & 15) * PITCH + (lane >> 4) * 16);
    const uint32_t b_off = (uint32_t)((((lane & 7) | ((lane >> 4) << 3)) * PITCH) +
                                      (((lane >> 3) & 1) * 16));

    auto load_chunk = [&](int kc, int stg) {
        const int k0 = kc << 6;
        const uint32_t dbase = sbase + (uint32_t)stg * STAGE1;
#pragma unroll
        for (int it = 0; it < 4; it++) {     // A: 128 rows * 8 chunks = 1024
            int idx = it * 256 + tid;
            int row = idx >> 3, c8 = idx & 7;
            const fp16* src = Ag + (size_t)(row0 + row) * lda + k0 + c8 * 8;
            cp16(dbase + (uint32_t)(row * PITCH + c8 * 16), src);
        }
#pragma unroll
        for (int it = 0; it < 4; it++) {     // B: 128 rows * 8 chunks = 1024
            int idx = it * 256 + tid;
            int row = idx >> 3, c8 = idx & 7;
            const fp16* src = Bg + (size_t)(col0 + row) * ldb + k0 + c8 * 8;
            cp16(dbase + T128 + (uint32_t)(row * PITCH + c8 * 16), src);
        }
    };

    float acc[2][8][4];
#pragma unroll
    for (int mi = 0; mi < 2; mi++)
#pragma unroll
        for (int nj = 0; nj < 8; nj++)
#pragma unroll
            for (int c = 0; c < 4; c++) acc[mi][nj][c] = 0.f;

    const int NC = K >> 6;
    load_chunk(0, 0);
    asm volatile("cp.async.commit_group;" ::: "memory");
    if (1 < NC) load_chunk(1, 1);
    asm volatile("cp.async.commit_group;" ::: "memory");

    int stg = 0;
    for (int kc = 0; kc < NC; kc++) {
        asm volatile("cp.async.wait_group 1;" ::: "memory");
        __syncthreads();
        if (kc + 2 < NC) load_chunk(kc + 2, (stg + 2 >= 3) ? stg - 1 : stg + 2);
        asm volatile("cp.async.commit_group;" ::: "memory");

        const uint32_t cbase = sbase + (uint32_t)stg * STAGE1;

        uint32_t ah[2][2][4];                // [ks buf][mi]
        uint32_t bh[2][4];                   // [ni buf]
#define LDA(bufi, kss) do { \
        _Pragma("unroll") \
        for (int mi = 0; mi < 2; mi++) { \
            ldsm4(ah[bufi][mi], cbase + \
                  (uint32_t)((warp_m * 32 + mi * 16) * PITCH + (kss) * 32) + a_off); \
        } } while (0)
#define LDB(bufi, kss, nii) \
        ldsm4(bh[bufi], cbase + T128 + \
              (uint32_t)((warp_n * 64 + (nii) * 16) * PITCH + (kss) * 32) + b_off)

        LDA(0, 0);
        LDB(0, 0, 0);
#pragma unroll
        for (int ks = 0; ks < 4; ks++) {
#pragma unroll
            for (int ni = 0; ni < 4; ni++) {
                const int bb = (ks * 4 + ni) & 1;
                if (ni < 3)       LDB(bb ^ 1, ks, ni + 1);
                else if (ks < 3)  { LDA((ks + 1) & 1, ks + 1); LDB(bb ^ 1, ks + 1, 0); }
#pragma unroll
                for (int mi = 0; mi < 2; mi++)
#pragma unroll
                    for (int j = 0; j < 2; j++)
                        mma16816(acc[mi][ni * 2 + j], ah[ks & 1][mi], &bh[bb][j * 2]);
            }
        }
#undef LDA
#undef LDB
        __syncthreads();
        stg = (stg + 1 >= 3) ? 0 : stg + 1;
    }

    const int gid = lane >> 2, tig = lane & 3;
#pragma unroll
    for (int mi = 0; mi < 2; mi++) {
#pragma unroll
        for (int hh = 0; hh < 2; hh++) {
            const int r = row0 + warp_m * 32 + mi * 16 + gid + hh * 8;
#pragma unroll
            for (int nj = 0; nj < 8; nj++) {
                const int c = col0 + warp_n * 64 + nj * 8 + tig * 2;
                float v0 = acc[mi][nj][hh * 2 + 0] * alpha;
                float v1 = acc[mi][nj][hh * 2 + 1] * alpha;
                const size_t o = coff + (size_t)r * ldc + c;
                if (EPI == 0) {
                    C[o] = v0 + bias[c];
                    C[o + 1] = v1 + bias[c + 1];
                } else if (EPI == 4) {
                    float g0 = v0 + bias[c], g1 = v1 + bias[c + 1];
                    g0 = 0.5f * g0 * (1.0f + erff(g0 * 0.70710678118654752f));
                    g1 = 0.5f * g1 * (1.0f + erff(g1 * 0.70710678118654752f));
                    Ch[o] = __float2half_rn(g0);
                    Ch[o + 1] = __float2half_rn(g1);
                } else {
                    C[o] = v0;
                    C[o + 1] = v1;
                }
            }
        }
    }
}

// ===================== host-side launch =====================
extern "C" void kernel_launch(void* const* d_in, const int* in_sizes, int n_in,
                              void* d_out, int out_size) {
    const float* hidden = (const float*)d_in[0];
    const float* cosp   = (const float*)d_in[1];
    const float* sinp   = (const float*)d_in[2];
    const float* qkv_w  = (const float*)d_in[3];
    const float* qkv_b  = (const float*)d_in[4];
    const float* proj_w = (const float*)d_in[5];
    const float* proj_b = (const float*)d_in[6];
    const float* ln1_g  = (const float*)d_in[7];
    const float* ln1_b  = (const float*)d_in[8];
    const float* ln2_g  = (const float*)d_in[9];
    const float* ln2_b  = (const float*)d_in[10];
    const float* fc1_w  = (const float*)d_in[11];
    const float* fc1_b  = (const float*)d_in[12];
    const float* fc2_w  = (const float*)d_in[13];
    const float* fc2_b  = (const float*)d_in[14];

    float* x = (float*)d_out;

    float *p_qkv, *p_part;
    fp16 *p_h, *p_qh, *p_ql, *p_k, *p_vt, *p_a, *p_m;
    fp16 *wq, *wp, *w1, *w2;
    cudaGetSymbolAddress((void**)&p_qkv, g_qkv);
    cudaGetSymbolAddress((void**)&p_part, g_part);
    cudaGetSymbolAddress((void**)&p_h,  g_h);
    cudaGetSymbolAddress((void**)&p_qh, g_qh);   cudaGetSymbolAddress((void**)&p_ql, g_ql);
    cudaGetSymbolAddress((void**)&p_k,  g_k);    cudaGetSymbolAddress((void**)&p_vt, g_vt);
    cudaGetSymbolAddress((void**)&p_a,  g_a);    cudaGetSymbolAddress((void**)&p_m,  g_m);
    cudaGetSymbolAddress((void**)&wq, g_wq);
    cudaGetSymbolAddress((void**)&wp, g_wp);
    cudaGetSymbolAddress((void**)&w1, g_w1);
    cudaGetSymbolAddress((void**)&w2, g_w2);

    float* pt[2] = {p_part, p_part + (size_t)S_ * D_};

    cudaFuncSetAttribute((const void*)gemm_mma<0>, cudaFuncAttributeMaxDynamicSharedMemorySize, GEMM_SMEM);
    cudaFuncSetAttribute((const void*)gemm_mma<4>, cudaFuncAttributeMaxDynamicSharedMemorySize, GEMM_SMEM);
    cudaFuncSetAttribute((const void*)gemm_mma<5>, cudaFuncAttributeMaxDynamicSharedMemorySize, GEMM_SMEM);
    cudaFuncSetAttribute((const void*)flash_kernel, cudaFuncAttributeMaxDynamicSharedMemorySize, FLASH_SMEM);

    cudaMemcpyAsync(x, hidden, (size_t)S_ * D_ * sizeof(float), cudaMemcpyDeviceToDevice);

    for (int l = 0; l < 2; l++) {
        const float* qw = qkv_w + (size_t)l * D_ * NQKV_;
        const float* qb = qkv_b + (size_t)l * NQKV_;
        const float* pw = proj_w + (size_t)l * D_ * D_;
        const float* pb = proj_b + (size_t)l * D_;
        const float* g1 = ln1_g + (size_t)l * D_;
        const float* b1 = ln1_b + (size_t)l * D_;
        const float* g2 = ln2_g + (size_t)l * D_;
        const float* b2 = ln2_b + (size_t)l * D_;
        const float* f1w = fc1_w + (size_t)l * D_ * I_;
        const float* f1b = fc1_b + (size_t)l * I_;
        const float* f2w = fc2_w + (size_t)l * I_ * D_;
        const float* f2b = fc2_b + (size_t)l * D_;

        if (l == 0)
            ln_kernel<<<S_, 256>>>(x, g1, b1, p_h);

        // weight prep before qkv (keeps ncu slot #4 on the qkv GEMM)
        wsplit_T_kernel<<<dim3(NQKV_ / 32, D_ / 32), dim3(32, 8)>>>(qw, wq, D_, NQKV_);
        wsplit_T_kernel<<<dim3(D_ / 32, D_ / 32), dim3(32, 8)>>>(pw, wp, D_, D_);

        // qkv = h @ W_qkv + b  (fp32 out), 480 CTAs @ 2/SM
        gemm_mma<0><<<dim3(NQKV_ / 128, S_ / 128, 1), 256, GEMM_SMEM>>>(
            p_h, wq, qb, p_qkv, nullptr,
            D_, D_, D_, NQKV_, 0, 0, 0, 1.f);

        // RoPE + split/round + V^T (+zero pad)
        rope_split_kernel<<<(S_ * H_ * HDP_ + 255) / 256, 256>>>(
            p_qkv, cosp, sinp, p_qh, p_ql, p_k, p_vt);

        // fused flash attention -> attn out fp16 in [S, D]
        flash_kernel<<<dim3(S_ / 128, H_), 256, FLASH_SMEM>>>(
            p_qh, p_ql, p_k, p_vt, p_a);

        // proj: split-K=2 (K=640 each, 320 CTAs), fused reduce+LN2
        gemm_mma<5><<<dim3(D_ / 128, S_ / 128, 2), 256, GEMM_SMEM>>>(
            p_a, wp, nullptr, pt[0], nullptr,
            D_ / 2, D_, D_, D_, D_ / 2, D_ / 2, (long long)S_ * D_, 1.f);
        reduce2_ln_kernel<<<S_, 256>>>(pt[0], pt[1], pb, x, g2, b2, p_h);

        // fc1: no split (640 CTAs), bias+gelu fused in epilogue -> fp16 p_m
        wsplit_T_kernel<<<dim3(I_ / 32, D_ / 32), dim3(32, 8)>>>(f1w, w1, D_, I_);
        gemm_mma<4><<<dim3(I_ / 128, S_ / 128, 1), 256, GEMM_SMEM>>>(
            p_h, w1, f1b, nullptr, p_m,
            D_, D_, D_, I_, 0, 0, 0, 1.f);

        // fc2: split-K=2 (K=2560 each, 320 CTAs)
        wsplit_T_kernel<<<dim3(D_ / 32, I_ / 32), dim3(32, 8)>>>(f2w, w2, I_, D_);
        gemm_mma<5><<<dim3(D_ / 128, S_ / 128, 2), 256, GEMM_SMEM>>>(
            p_m, w2, nullptr, pt[0], nullptr,
            I_ / 2, I_, I_, D_, I_ / 2, I_ / 2, (long long)S_ * D_, 1.f);
        if (l == 0) {
            reduce2_ln_kernel<<<S_, 256>>>(pt[0], pt[1], f2b, x,
                                           ln1_g + D_, ln1_b + D_, p_h);
        } else {
            reduce2_kernel<<<(S_ * D_ + 255) / 256, 256>>>(pt[0], pt[1], f2b, x);
        }
    }
}